// round 12
// baseline (speedup 1.0000x reference)
#include <cuda_runtime.h>
#include <cuda_bf16.h>
#include <math.h>
#include <stdint.h>

// nGPT block: B=8, T=1024, C=1024, H=16, D=64
#define BT   8192
#define CDIM 1024

// ---- scratch carve (float units) ----
#define OFF_INV  0
#define OFF_V    4096                         // bf16 v [token][dim]
#define OFF_T1   (OFF_V   + BT*CDIM)          // bf16 t1 [token][dim]
#define OFF_H2   (OFF_T1  + BT*CDIM)
#define OFF_HB   (OFF_H2  + BT*CDIM)
#define OFF_YB   (OFF_HB  + BT*CDIM/2)
#define OFF_H2B  (OFF_YB  + BT*CDIM/2)
#define OFF_XB   (OFF_H2B + BT*CDIM/2)        // 8192x4096 bf16
#define OFF_WQB  (OFF_XB  + BT*4*CDIM/2)      // Wq,Wk,Wv,Wo bf16 contiguous
#define OFF_WFCB (OFF_WQB + 4*CDIM*CDIM/2)    // permuted Wfc bf16
#define OFF_WPJB (OFF_WFCB + 8*CDIM*CDIM/2)
#define OFF_QBF  (OFF_WPJB + 4*CDIM*CDIM/2)   // bf16 q [token][dim]
#define OFF_KBF  (OFF_QBF + BT*CDIM/2)        // bf16 k
#define OFF_VT   (OFF_KBF + BT*CDIM/2)        // bf16 V^T [dim][token]
#define BUF_TOTAL (OFF_VT + BT*CDIM/2)

__device__ float g_buf[BUF_TOTAL];

__device__ __forceinline__ uint32_t cvt2bf(float lo, float hi) {
    uint32_t r;
    asm("cvt.rn.bf16x2.f32 %0, %1, %2;" : "=r"(r) : "f"(hi), "f"(lo));
    return r;
}

// ---------------------------------------------------------------------------
// inverse column norms of W [C,C] row-major: inv[k] = 1/||W[:,k]||
// ---------------------------------------------------------------------------
__global__ void colnorm_kernel(const float* __restrict__ Wq, const float* __restrict__ Wk,
                               const float* __restrict__ Wv, const float* __restrict__ Wo,
                               float* __restrict__ inv)
{
    int m = blockIdx.y;
    const float* W = (m == 0) ? Wq : (m == 1) ? Wk : (m == 2) ? Wv : Wo;
    int tx = threadIdx.x & 31;
    int ty = threadIdx.x >> 5;
    int col = blockIdx.x * 32 + tx;
    float s = 0.f;
    for (int i = ty; i < CDIM; i += 8) {
        float w = W[i * CDIM + col];
        s += w * w;
    }
    __shared__ float sm[8][32];
    sm[ty][tx] = s;
    __syncthreads();
    if (ty == 0) {
        float tot = 0.f;
        #pragma unroll
        for (int r = 0; r < 8; r++) tot += sm[r][tx];
        inv[m * CDIM + col] = rsqrtf(tot);
    }
}

// ---------------------------------------------------------------------------
// Weight conversion with folded column norms (4 matrices)
// ---------------------------------------------------------------------------
__global__ void wconv4_kernel(const float* __restrict__ Wq, const float* __restrict__ Wk,
                              const float* __restrict__ Wv, const float* __restrict__ Wo,
                              const float* __restrict__ inv, uint32_t* __restrict__ dst)
{
    int m = blockIdx.y;
    const float* W = (m == 0) ? Wq : (m == 1) ? Wk : (m == 2) ? Wv : Wo;
    int idx = blockIdx.x * 256 + threadIdx.x;
    float4 w = ((const float4*)W)[idx];
    float4 s = ((const float4*)(inv + m * CDIM))[idx & 255];
    uint32_t* d = dst + (size_t)m * (CDIM * CDIM / 2) + idx * 2;
    d[0] = cvt2bf(w.x * s.x, w.y * s.y);
    d[1] = cvt2bf(w.z * s.z, w.w * s.w);
}

__global__ void conv_kernel(const float* __restrict__ src, uint32_t* __restrict__ dst)
{
    int idx = blockIdx.x * 256 + threadIdx.x;
    float4 v = ((const float4*)src)[idx];
    dst[idx * 2 + 0] = cvt2bf(v.x, v.y);
    dst[idx * 2 + 1] = cvt2bf(v.z, v.w);
}

// ---------------------------------------------------------------------------
// Wfc conversion with row permutation for fused SwiGLU
// ---------------------------------------------------------------------------
__global__ void wfc_perm_kernel(const float* __restrict__ Wfc, uint32_t* __restrict__ dst)
{
    int idx = blockIdx.x * 256 + threadIdx.x;
    int r = idx >> 8, c4 = idx & 255;
    int b = r >> 4, w = r & 15;
    int src_r = (w < 8) ? (b * 8 + w) : (4096 + b * 8 + (w - 8));
    float4 v = ((const float4*)Wfc)[(size_t)src_r * 256 + c4];
    dst[(size_t)idx * 2 + 0] = cvt2bf(v.x, v.y);
    dst[(size_t)idx * 2 + 1] = cvt2bf(v.z, v.w);
}

// ---------------------------------------------------------------------------
// bf16 mma.sync GEMM NT (R9/R11 winning shape): 128x128x64, 3-stage cp.async,
// 4 warps, warp tile 64x64, 128 threads, 2 CTAs/SM.
// MODE 1: bf16 out. MODE 2: fused qkv + qk per-head norm. MODE 3: fused SwiGLU.
// ---------------------------------------------------------------------------
#define STAGES 3
#define GEMM_SMEM (STAGES * 32768)

template <int MODE>
__global__ void __launch_bounds__(128, 2) gemm_kernel(
    const __nv_bfloat16* __restrict__ A, const __nv_bfloat16* __restrict__ B,
    void* __restrict__ C0, void* __restrict__ C1, void* __restrict__ C2,
    const float* __restrict__ scl,
    int M, int N, int K)
{
    extern __shared__ char smc[];
    const int tid = threadIdx.x, lane = tid & 31, warp = tid >> 5;
    const int wm = warp & 1, wn = warp >> 1;
    const int crow = blockIdx.y * 128, ccol = blockIdx.x * 128;
    const uint32_t sbase = (uint32_t)__cvta_generic_to_shared(smc);

    const __nv_bfloat16* Ag = A + (size_t)crow * K;
    const __nv_bfloat16* Bg = B + (size_t)ccol * K;

    auto issue = [&](int t, int buf) {
        const uint32_t abase = sbase + buf * 32768;
        const uint32_t bbase = abase + 16384;
        const int k0 = t * 64;
        #pragma unroll
        for (int i = 0; i < 8; i++) {
            int idx = tid + i * 128;
            int row = idx >> 3, c = idx & 7;
            uint32_t sw = (uint32_t)(row * 128 + ((c ^ (row & 7)) << 4));
            asm volatile("cp.async.cg.shared.global [%0], [%1], 16;"
                         :: "r"(abase + sw), "l"((const void*)(Ag + (size_t)row * K + k0 + c * 8)));
            asm volatile("cp.async.cg.shared.global [%0], [%1], 16;"
                         :: "r"(bbase + sw), "l"((const void*)(Bg + (size_t)row * K + k0 + c * 8)));
        }
    };

    float acc[4][8][4];
    #pragma unroll
    for (int i = 0; i < 4; i++)
        #pragma unroll
        for (int j = 0; j < 8; j++)
            #pragma unroll
            for (int e = 0; e < 4; e++) acc[i][j][e] = 0.f;

    const int nt = K / 64;

    issue(0, 0); asm volatile("cp.async.commit_group;");
    issue(1, 1); asm volatile("cp.async.commit_group;");

    const int arow0 = wm * 64 + (lane & 15);
    const int akb   = lane >> 4;
    const int asw   = lane & 7;
    const int brow0 = wn * 64 + (lane & 7) + ((lane >> 4) << 3);
    const int bkb   = (lane >> 3) & 1;

    for (int t = 0; t < nt; t++) {
        asm volatile("cp.async.wait_group 1;");
        __syncthreads();

        if (t + 2 < nt) {
            issue(t + 2, (t + 2) % STAGES);
        }
        asm volatile("cp.async.commit_group;");

        const int buf = t % STAGES;
        const uint32_t abase = sbase + buf * 32768;
        const uint32_t bbase = abase + 16384;

        #pragma unroll
        for (int ks = 0; ks < 4; ks++) {
            uint32_t a[4][4], br[4][4];
            const int ach = 2 * ks + akb;
            const int bch = 2 * ks + bkb;
            #pragma unroll
            for (int mi = 0; mi < 4; mi++) {
                uint32_t ad = abase + (uint32_t)(arow0 + mi * 16) * 128 +
                              (uint32_t)((ach ^ asw) << 4);
                asm volatile("ldmatrix.sync.aligned.m8n8.x4.shared.b16 {%0,%1,%2,%3}, [%4];"
                             : "=r"(a[mi][0]), "=r"(a[mi][1]), "=r"(a[mi][2]), "=r"(a[mi][3])
                             : "r"(ad));
            }
            #pragma unroll
            for (int nj2 = 0; nj2 < 4; nj2++) {
                uint32_t bd = bbase + (uint32_t)(brow0 + nj2 * 16) * 128 +
                              (uint32_t)((bch ^ asw) << 4);
                asm volatile("ldmatrix.sync.aligned.m8n8.x4.shared.b16 {%0,%1,%2,%3}, [%4];"
                             : "=r"(br[nj2][0]), "=r"(br[nj2][1]), "=r"(br[nj2][2]), "=r"(br[nj2][3])
                             : "r"(bd));
            }
            #pragma unroll
            for (int mi = 0; mi < 4; mi++)
                #pragma unroll
                for (int nj = 0; nj < 8; nj++) {
                    uint32_t b0 = br[nj >> 1][(nj & 1) * 2];
                    uint32_t b1 = br[nj >> 1][(nj & 1) * 2 + 1];
                    asm volatile(
                        "mma.sync.aligned.m16n8k16.row.col.f32.bf16.bf16.f32 "
                        "{%0,%1,%2,%3}, {%4,%5,%6,%7}, {%8,%9}, {%0,%1,%2,%3};"
                        : "+f"(acc[mi][nj][0]), "+f"(acc[mi][nj][1]),
                          "+f"(acc[mi][nj][2]), "+f"(acc[mi][nj][3])
                        : "r"(a[mi][0]), "r"(a[mi][1]), "r"(a[mi][2]), "r"(a[mi][3]),
                          "r"(b0), "r"(b1));
                }
        }
        __syncthreads();
    }

    // ---- epilogue ----
    if (MODE == 3) {
        const int xc0 = blockIdx.x * 64;
        __nv_bfloat16* Xb = (__nv_bfloat16*)C0;
        #pragma unroll
        for (int p = 0; p < 4; p++) {
            const int cb = xc0 + (wn * 4 + p) * 8 + 2 * (lane & 3);
            const float su0 = scl[cb] * 32.f,        su1 = scl[cb + 1] * 32.f;
            const float sg0 = scl[4096 + cb] * 32.f, sg1 = scl[4096 + cb + 1] * 32.f;
            #pragma unroll
            for (int mi = 0; mi < 4; mi++) {
                const int r0 = crow + wm * 64 + mi * 16 + (lane >> 2);
                float g, x0, x1;
                g = acc[mi][2 * p + 1][0] * sg0; x0 = (acc[mi][2 * p][0] * su0) * g / (1.f + __expf(-g));
                g = acc[mi][2 * p + 1][1] * sg1; x1 = (acc[mi][2 * p][1] * su1) * g / (1.f + __expf(-g));
                *(uint32_t*)&Xb[(size_t)r0 * 4096 + cb] = cvt2bf(x0, x1);
                g = acc[mi][2 * p + 1][2] * sg0; x0 = (acc[mi][2 * p][2] * su0) * g / (1.f + __expf(-g));
                g = acc[mi][2 * p + 1][3] * sg1; x1 = (acc[mi][2 * p][3] * su1) * g / (1.f + __expf(-g));
                *(uint32_t*)&Xb[(size_t)(r0 + 8) * 4096 + cb] = cvt2bf(x0, x1);
            }
        }
    } else if (MODE == 2) {
        const int which = ccol >> 10;        // 0=q,1=k,2=v
        const int cl = ccol & 1023;
        if (which == 2) {
            __nv_bfloat16* Cb = (__nv_bfloat16*)C2;
            #pragma unroll
            for (int mi = 0; mi < 4; mi++) {
                const int r0 = crow + wm * 64 + mi * 16 + (lane >> 2);
                #pragma unroll
                for (int nj = 0; nj < 8; nj++) {
                    const int c0 = cl + wn * 64 + nj * 8 + 2 * (lane & 3);
                    *(uint32_t*)&Cb[(size_t)r0 * 1024 + c0] =
                        cvt2bf(acc[mi][nj][0], acc[mi][nj][1]);
                    *(uint32_t*)&Cb[(size_t)(r0 + 8) * 1024 + c0] =
                        cvt2bf(acc[mi][nj][2], acc[mi][nj][3]);
                }
            }
        } else {
            __nv_bfloat16* Cb = which ? (__nv_bfloat16*)C1 : (__nv_bfloat16*)C0;
            const float extra = which ? 32.f : 256.f;
            float sc0[8], sc1[8];
            #pragma unroll
            for (int nj = 0; nj < 8; nj++) {
                const int c0 = cl + wn * 64 + nj * 8 + 2 * (lane & 3);
                sc0[nj] = scl[c0] * extra;
                sc1[nj] = scl[c0 + 1] * extra;
            }
            #pragma unroll
            for (int mi = 0; mi < 4; mi++) {
                const int r0 = crow + wm * 64 + mi * 16 + (lane >> 2);
                float ss0 = 0.f, ss1 = 0.f;
                #pragma unroll
                for (int nj = 0; nj < 8; nj++) {
                    ss0 += acc[mi][nj][0] * acc[mi][nj][0] + acc[mi][nj][1] * acc[mi][nj][1];
                    ss1 += acc[mi][nj][2] * acc[mi][nj][2] + acc[mi][nj][3] * acc[mi][nj][3];
                }
                ss0 += __shfl_xor_sync(0xffffffffu, ss0, 1);
                ss0 += __shfl_xor_sync(0xffffffffu, ss0, 2);
                ss1 += __shfl_xor_sync(0xffffffffu, ss1, 1);
                ss1 += __shfl_xor_sync(0xffffffffu, ss1, 2);
                const float rn0 = rsqrtf(ss0), rn1 = rsqrtf(ss1);
                #pragma unroll
                for (int nj = 0; nj < 8; nj++) {
                    const int c0 = cl + wn * 64 + nj * 8 + 2 * (lane & 3);
                    *(uint32_t*)&Cb[(size_t)r0 * 1024 + c0] =
                        cvt2bf(acc[mi][nj][0] * rn0 * sc0[nj], acc[mi][nj][1] * rn0 * sc1[nj]);
                    *(uint32_t*)&Cb[(size_t)(r0 + 8) * 1024 + c0] =
                        cvt2bf(acc[mi][nj][2] * rn1 * sc0[nj], acc[mi][nj][3] * rn1 * sc1[nj]);
                }
            }
        }
    } else {
        __nv_bfloat16* Cb = (__nv_bfloat16*)C0;
        #pragma unroll
        for (int mi = 0; mi < 4; mi++) {
            const int r0 = crow + wm * 64 + mi * 16 + (lane >> 2);
            #pragma unroll
            for (int nj = 0; nj < 8; nj++) {
                const int c0 = ccol + wn * 64 + nj * 8 + 2 * (lane & 3);
                *(uint32_t*)&Cb[(size_t)r0 * N + c0] =
                    cvt2bf(acc[mi][nj][0], acc[mi][nj][1]);
                *(uint32_t*)&Cb[(size_t)(r0 + 8) * N + c0] =
                    cvt2bf(acc[mi][nj][2], acc[mi][nj][3]);
            }
        }
    }
}

// ---------------------------------------------------------------------------
// V transpose: vB bf16 [8192][1024] -> Vt bf16 [1024][8192]
// ---------------------------------------------------------------------------
__global__ void vtrans_kernel(const __nv_bfloat16* __restrict__ vB,
                              __nv_bfloat16* __restrict__ Vt)
{
    __shared__ __nv_bfloat16 tile[64][72];
    int tid = threadIdx.x;
    int t0 = blockIdx.x * 64, d0 = blockIdx.y * 64;
    #pragma unroll
    for (int i = 0; i < 2; i++) {
        int idx = tid + i * 256;
        int row = idx >> 3, c = idx & 7;
        uint4 v = *(const uint4*)&vB[(size_t)(t0 + row) * CDIM + d0 + c * 8];
        __nv_bfloat16 tmp[8];
        *(uint4*)tmp = v;
        #pragma unroll
        for (int j = 0; j < 8; j++) tile[c * 8 + j][row] = tmp[j];
    }
    __syncthreads();
    #pragma unroll
    for (int i = 0; i < 2; i++) {
        int idx = tid + i * 256;
        int d = idx >> 3, c = idx & 7;
        *(uint4*)&Vt[(size_t)(d0 + d) * BT + t0 + c * 8] = *(uint4*)&tile[d][c * 8];
    }
}

// ---------------------------------------------------------------------------
// Tensor-core flash attention (non-causal), D=64.
// CTA: 256 q rows x one (b,h); 8 warps, each warp owns rows
// {qt*128 + warp*16 .. +16} for qt=0,1. grid (4, 128), 256 threads.
// smem: Q 32KB + 3 stages x (K 16KB + Vt 16KB) = 128KB.
// ---------------------------------------------------------------------------
#define ATT_SMEM (32768 + 3 * 32768)

__global__ void __launch_bounds__(256, 1) attn_tc_kernel(
    const __nv_bfloat16* __restrict__ q, const __nv_bfloat16* __restrict__ k,
    const __nv_bfloat16* __restrict__ vt, __nv_bfloat16* __restrict__ y)
{
    extern __shared__ char smc[];
    const int tid = threadIdx.x, lane = tid & 31, warp = tid >> 5;
    const int bh = blockIdx.y, b = bh >> 4, cb = (bh & 15) * 64;
    const int tq0 = b * 1024 + blockIdx.x * 256;
    const uint32_t sb = (uint32_t)__cvta_generic_to_shared(smc);
    const uint32_t qs = sb;
    const uint32_t kvs = sb + 32768;

    // ---- Q tile: 256 rows x 128B = 32KB ----
    #pragma unroll
    for (int i = 0; i < 8; i++) {
        int idx = tid + i * 256;
        int row = idx >> 3, c = idx & 7;
        uint32_t sw = (uint32_t)(row * 128 + ((c ^ (row & 7)) << 4));
        asm volatile("cp.async.cg.shared.global [%0], [%1], 16;"
                     :: "r"(qs + sw), "l"((const void*)(q + (size_t)(tq0 + row) * CDIM + cb + c * 8)));
    }
    asm volatile("cp.async.commit_group;");

    auto issueKV = [&](int kt, int buf) {
        const int tk0 = b * 1024 + kt * 128;
        const uint32_t kb_ = kvs + buf * 32768;
        const uint32_t vb_ = kb_ + 16384;
        #pragma unroll
        for (int i = 0; i < 4; i++) {
            int idx = tid + i * 256;
            int row = idx >> 3, c = idx & 7;
            uint32_t sw = (uint32_t)(row * 128 + ((c ^ (row & 7)) << 4));
            asm volatile("cp.async.cg.shared.global [%0], [%1], 16;"
                         :: "r"(kb_ + sw), "l"((const void*)(k + (size_t)(tk0 + row) * CDIM + cb + c * 8)));
            asm volatile("cp.async.cg.shared.global [%0], [%1], 16;"
                         :: "r"(vb_ + sw),
                            "l"((const void*)(vt + (size_t)(cb + (row & 63)) * BT + tk0 + (row >> 6) * 64 + c * 8)));
        }
    };

    issueKV(0, 0); asm volatile("cp.async.commit_group;");
    issueKV(1, 1); asm volatile("cp.async.commit_group;");

    asm volatile("cp.async.wait_group 2;");
    __syncthreads();

    const int akb  = lane >> 4;
    const int lsw  = lane & 7;
    uint32_t aq[2][4][4];
    #pragma unroll
    for (int qt = 0; qt < 2; qt++) {
        const int arow = qt * 128 + warp * 16 + (lane & 15);
        #pragma unroll
        for (int ks = 0; ks < 4; ks++) {
            uint32_t ad = qs + (uint32_t)arow * 128 + (uint32_t)(((2 * ks + akb) ^ lsw) << 4);
            asm volatile("ldmatrix.sync.aligned.m8n8.x4.shared.b16 {%0,%1,%2,%3}, [%4];"
                         : "=r"(aq[qt][ks][0]), "=r"(aq[qt][ks][1]),
                           "=r"(aq[qt][ks][2]), "=r"(aq[qt][ks][3])
                         : "r"(ad));
        }
    }

    float acc_o[2][8][4];
    float m0[2], m1[2], l0[2], l1[2];
    #pragma unroll
    for (int qt = 0; qt < 2; qt++) {
        m0[qt] = -1e30f; m1[qt] = -1e30f; l0[qt] = 0.f; l1[qt] = 0.f;
        #pragma unroll
        for (int j = 0; j < 8; j++)
            #pragma unroll
            for (int e = 0; e < 4; e++) acc_o[qt][j][e] = 0.f;
    }

    const int brow = (lane & 7) + ((lane >> 4) << 3);
    const int bkb  = (lane >> 3) & 1;

    for (int kt = 0; kt < 8; kt++) {
        asm volatile("cp.async.wait_group 1;");
        __syncthreads();

        const uint32_t kb_ = kvs + (kt % 3) * 32768;
        const uint32_t vb_ = kb_ + 16384;

        #pragma unroll
        for (int qt = 0; qt < 2; qt++) {
            float s[16][4];
            #pragma unroll
            for (int j = 0; j < 16; j++)
                #pragma unroll
                for (int e = 0; e < 4; e++) s[j][e] = 0.f;

            #pragma unroll
            for (int ks = 0; ks < 4; ks++) {
                const int bch = 2 * ks + bkb;
                #pragma unroll
                for (int nj2 = 0; nj2 < 8; nj2++) {
                    uint32_t bk[4];
                    uint32_t bd = kb_ + (uint32_t)(brow + nj2 * 16) * 128 +
                                  (uint32_t)((bch ^ lsw) << 4);
                    asm volatile("ldmatrix.sync.aligned.m8n8.x4.shared.b16 {%0,%1,%2,%3}, [%4];"
                                 : "=r"(bk[0]), "=r"(bk[1]), "=r"(bk[2]), "=r"(bk[3]) : "r"(bd));
                    asm volatile(
                        "mma.sync.aligned.m16n8k16.row.col.f32.bf16.bf16.f32 "
                        "{%0,%1,%2,%3}, {%4,%5,%6,%7}, {%8,%9}, {%0,%1,%2,%3};"
                        : "+f"(s[2 * nj2][0]), "+f"(s[2 * nj2][1]),
                          "+f"(s[2 * nj2][2]), "+f"(s[2 * nj2][3])
                        : "r"(aq[qt][ks][0]), "r"(aq[qt][ks][1]),
                          "r"(aq[qt][ks][2]), "r"(aq[qt][ks][3]),
                          "r"(bk[0]), "r"(bk[1]));
                    asm volatile(
                        "mma.sync.aligned.m16n8k16.row.col.f32.bf16.bf16.f32 "
                        "{%0,%1,%2,%3}, {%4,%5,%6,%7}, {%8,%9}, {%0,%1,%2,%3};"
                        : "+f"(s[2 * nj2 + 1][0]), "+f"(s[2 * nj2 + 1][1]),
                          "+f"(s[2 * nj2 + 1][2]), "+f"(s[2 * nj2 + 1][3])
                        : "r"(aq[qt][ks][0]), "r"(aq[qt][ks][1]),
                          "r"(aq[qt][ks][2]), "r"(aq[qt][ks][3]),
                          "r"(bk[2]), "r"(bk[3]));
                }
            }

            float rm0 = -1e30f, rm1 = -1e30f;
            #pragma unroll
            for (int j = 0; j < 16; j++) {
                rm0 = fmaxf(rm0, fmaxf(s[j][0], s[j][1]));
                rm1 = fmaxf(rm1, fmaxf(s[j][2], s[j][3]));
            }
            rm0 = fmaxf(rm0, __shfl_xor_sync(0xffffffffu, rm0, 1));
            rm0 = fmaxf(rm0, __shfl_xor_sync(0xffffffffu, rm0, 2));
            rm1 = fmaxf(rm1, __shfl_xor_sync(0xffffffffu, rm1, 1));
            rm1 = fmaxf(rm1, __shfl_xor_sync(0xffffffffu, rm1, 2));
            float nm0 = fmaxf(m0[qt], rm0), nm1 = fmaxf(m1[qt], rm1);
            float co0 = __expf(m0[qt] - nm0), co1 = __expf(m1[qt] - nm1);
            float ls0 = 0.f, ls1 = 0.f;
            #pragma unroll
            for (int j = 0; j < 16; j++) {
                s[j][0] = __expf(s[j][0] - nm0); ls0 += s[j][0];
                s[j][1] = __expf(s[j][1] - nm0); ls0 += s[j][1];
                s[j][2] = __expf(s[j][2] - nm1); ls1 += s[j][2];
                s[j][3] = __expf(s[j][3] - nm1); ls1 += s[j][3];
            }
            ls0 += __shfl_xor_sync(0xffffffffu, ls0, 1);
            ls0 += __shfl_xor_sync(0xffffffffu, ls0, 2);
            ls1 += __shfl_xor_sync(0xffffffffu, ls1, 1);
            ls1 += __shfl_xor_sync(0xffffffffu, ls1, 2);
            l0[qt] = l0[qt] * co0 + ls0; l1[qt] = l1[qt] * co1 + ls1;
            m0[qt] = nm0; m1[qt] = nm1;
            #pragma unroll
            for (int j = 0; j < 8; j++) {
                acc_o[qt][j][0] *= co0; acc_o[qt][j][1] *= co0;
                acc_o[qt][j][2] *= co1; acc_o[qt][j][3] *= co1;
            }

            #pragma unroll
            for (int kp = 0; kp < 8; kp++) {
                uint32_t ap[4];
                ap[0] = cvt2bf(s[2 * kp][0],     s[2 * kp][1]);
                ap[1] = cvt2bf(s[2 * kp][2],     s[2 * kp][3]);
                ap[2] = cvt2bf(s[2 * kp + 1][0], s[2 * kp + 1][1]);
                ap[3] = cvt2bf(s[2 * kp + 1][2], s[2 * kp + 1][3]);
                const uint32_t vbase = vb_ + (uint32_t)((kp >> 2) * 8192);
                const int ach = 2 * (kp & 3) + bkb;
                #pragma unroll
                for (int dj2 = 0; dj2 < 4; dj2++) {
                    uint32_t bv[4];
                    uint32_t bd = vbase + (uint32_t)(brow + dj2 * 16) * 128 +
                                  (uint32_t)((ach ^ lsw) << 4);
                    asm volatile("ldmatrix.sync.aligned.m8n8.x4.shared.b16 {%0,%1,%2,%3}, [%4];"
                                 : "=r"(bv[0]), "=r"(bv[1]), "=r"(bv[2]), "=r"(bv[3]) : "r"(bd));
                    asm volatile(
                        "mma.sync.aligned.m16n8k16.row.col.f32.bf16.bf16.f32 "
                        "{%0,%1,%2,%3}, {%4,%5,%6,%7}, {%8,%9}, {%0,%1,%2,%3};"
                        : "+f"(acc_o[qt][2 * dj2][0]), "+f"(acc_o[qt][2 * dj2][1]),
                          "+f"(acc_o[qt][2 * dj2][2]), "+f"(acc_o[qt][2 * dj2][3])
                        : "r"(ap[0]), "r"(ap[1]), "r"(ap[2]), "r"(ap[3]),
                          "r"(bv[0]), "r"(bv[1]));
                    asm volatile(
                        "mma.sync.aligned.m16n8k16.row.col.f32.bf16.bf16.f32 "
                        "{%0,%1,%2,%3}, {%4,%5,%6,%7}, {%8,%9}, {%0,%1,%2,%3};"
                        : "+f"(acc_o[qt][2 * dj2 + 1][0]), "+f"(acc_o[qt][2 * dj2 + 1][1]),
                          "+f"(acc_o[qt][2 * dj2 + 1][2]), "+f"(acc_o[qt][2 * dj2 + 1][3])
                        : "r"(ap[0]), "r"(ap[1]), "r"(ap[2]), "r"(ap[3]),
                          "r"(bv[2]), "r"(bv[3]));
                }
            }
        }

        if (kt + 2 < 8) issueKV(kt + 2, (kt + 2) % 3);
        asm volatile("cp.async.commit_group;");
    }

    // ---- epilogue (both q sub-tiles) ----
    #pragma unroll
    for (int qt = 0; qt < 2; qt++) {
        const float li0 = 1.f / l0[qt], li1 = 1.f / l1[qt];
        const int r0 = tq0 + qt * 128 + warp * 16 + (lane >> 2);
        #pragma unroll
        for (int dj = 0; dj < 8; dj++) {
            const int c0 = cb + dj * 8 + 2 * (lane & 3);
            *(uint32_t*)&y[(size_t)r0 * CDIM + c0] =
                cvt2bf(acc_o[qt][dj][0] * li0, acc_o[qt][dj][1] * li0);
            *(uint32_t*)&y[(size_t)(r0 + 8) * CDIM + c0] =
                cvt2bf(acc_o[qt][dj][2] * li1, acc_o[qt][dj][3] * li1);
        }
    }
}

// ---------------------------------------------------------------------------
// out = justnorm( justnorm(h) + |alpha*1.6| * (justnorm(hb) - justnorm(h)) )
// hb is bf16 (lr-damped branch).
// ---------------------------------------------------------------------------
__global__ void residual_kernel(const float* __restrict__ hin,
                                const __nv_bfloat162* __restrict__ hb,
                                const float* __restrict__ alpha, float* __restrict__ out,
                                uint32_t* __restrict__ outb)
{
    int t = blockIdx.x, tid = threadIdx.x;
    float4 a = ((const float4*)hin)[(size_t)t * 256 + tid];
    __nv_bfloat162 b0 = hb[((size_t)t * 256 + tid) * 2];
    __nv_bfloat162 b1 = hb[((size_t)t * 256 + tid) * 2 + 1];
    float4 b = make_float4(__bfloat162float(b0.x), __bfloat162float(b0.y),
                           __bfloat162float(b1.x), __bfloat162float(b1.y));
    float s1 = a.x * a.x + a.y * a.y + a.z * a.z + a.w * a.w;
    float s2 = b.x * b.x + b.y * b.y + b.z * b.z + b.w * b.w;
    #pragma unroll
    for (int off = 16; off >= 1; off >>= 1) {
        s1 += __shfl_xor_sync(0xffffffffu, s1, off);
        s2 += __shfl_xor_sync(0xffffffffu, s2, off);
    }
    __shared__ float red1[8], red2[8];
    int w = tid >> 5, lane = tid & 31;
    if (lane == 0) { red1[w] = s1; red2[w] = s2; }
    __syncthreads();
    float t1 = 0.f, t2 = 0.f;
    #pragma unroll
    for (int i = 0; i < 8; i++) { t1 += red1[i]; t2 += red2[i]; }
    float r1 = rsqrtf(t1), r2 = rsqrtf(t2);

    float4 al = ((const float4*)alpha)[tid];
    float4 u;
    u.x = a.x * r1 + fabsf(al.x * 1.6f) * (b.x * r2 - a.x * r1);
    u.y = a.y * r1 + fabsf(al.y * 1.6f) * (b.y * r2 - a.y * r1);
    u.z = a.z * r1 + fabsf(al.z * 1.6f) * (b.z * r2 - a.z * r1);
    u.w = a.w * r1 + fabsf(al.w * 1.6f) * (b.w * r2 - a.w * r1);

    float s3 = u.x * u.x + u.y * u.y + u.z * u.z + u.w * u.w;
    #pragma unroll
    for (int off = 16; off >= 1; off >>= 1) s3 += __shfl_xor_sync(0xffffffffu, s3, off);
    __syncthreads();
    if (lane == 0) red1[w] = s3;
    __syncthreads();
    float t3 = 0.f;
    #pragma unroll
    for (int i = 0; i < 8; i++) t3 += red1[i];
    float r3 = rsqrtf(t3);
    float4 o = make_float4(u.x * r3, u.y * r3, u.z * r3, u.w * r3);
    ((float4*)out)[(size_t)t * 256 + tid] = o;
    if (outb) {
        outb[((size_t)t * 256 + tid) * 2 + 0] = cvt2bf(o.x, o.y);
        outb[((size_t)t * 256 + tid) * 2 + 1] = cvt2bf(o.z, o.w);
    }
}

// ---------------------------------------------------------------------------
extern "C" void kernel_launch(void* const* d_in, const int* in_sizes, int n_in,
                              void* d_out, int out_size)
{
    (void)in_sizes; (void)n_in; (void)out_size;
    const float* h     = (const float*)d_in[0];
    const float* Wq    = (const float*)d_in[1];
    const float* Wk    = (const float*)d_in[2];
    const float* Wv    = (const float*)d_in[3];
    const float* Wo    = (const float*)d_in[4];
    const float* Wfc   = (const float*)d_in[5];
    const float* Wproj = (const float*)d_in[6];
    const float* sqk   = (const float*)d_in[7];
    const float* suv   = (const float*)d_in[8];
    const float* a_att = (const float*)d_in[9];
    const float* a_mlp = (const float*)d_in[10];
    float* out = (float*)d_out;

    float* buf = nullptr;
    cudaGetSymbolAddress((void**)&buf, g_buf);
    float* inv = buf + OFF_INV;
    float* h2  = buf + OFF_H2;
    __nv_bfloat16* vBf  = (__nv_bfloat16*)(buf + OFF_V);
    __nv_bfloat16* t1B  = (__nv_bfloat16*)(buf + OFF_T1);
    __nv_bfloat16* hB   = (__nv_bfloat16*)(buf + OFF_HB);
    __nv_bfloat16* yB   = (__nv_bfloat16*)(buf + OFF_YB);
    __nv_bfloat16* h2B  = (__nv_bfloat16*)(buf + OFF_H2B);
    __nv_bfloat16* xB   = (__nv_bfloat16*)(buf + OFF_XB);
    __nv_bfloat16* WqB  = (__nv_bfloat16*)(buf + OFF_WQB);   // q,k,v contiguous
    __nv_bfloat16* WoB  = WqB + 3 * CDIM * CDIM;
    __nv_bfloat16* WfcP = (__nv_bfloat16*)(buf + OFF_WFCB);  // permuted
    __nv_bfloat16* WpjB = (__nv_bfloat16*)(buf + OFF_WPJB);
    __nv_bfloat16* qBf  = (__nv_bfloat16*)(buf + OFF_QBF);
    __nv_bfloat16* kBf  = (__nv_bfloat16*)(buf + OFF_KBF);
    __nv_bfloat16* VtG  = (__nv_bfloat16*)(buf + OFF_VT);

    cudaFuncSetAttribute(attn_tc_kernel, cudaFuncAttributeMaxDynamicSharedMemorySize, ATT_SMEM);
    cudaFuncSetAttribute(gemm_kernel<1>, cudaFuncAttributeMaxDynamicSharedMemorySize, GEMM_SMEM);
    cudaFuncSetAttribute(gemm_kernel<2>, cudaFuncAttributeMaxDynamicSharedMemorySize, GEMM_SMEM);
    cudaFuncSetAttribute(gemm_kernel<3>, cudaFuncAttributeMaxDynamicSharedMemorySize, GEMM_SMEM);

    // weight norms + conversions
    colnorm_kernel<<<dim3(32, 4), 256>>>(Wq, Wk, Wv, Wo, inv);
    wconv4_kernel<<<dim3(1024, 4), 256>>>(Wq, Wk, Wv, Wo, inv, (uint32_t*)WqB);
    wfc_perm_kernel<<<8 * CDIM * CDIM / 1024, 256>>>(Wfc, (uint32_t*)WfcP);
    conv_kernel<<<4 * CDIM * CDIM / 1024, 256>>>(Wproj, (uint32_t*)WpjB);
    conv_kernel<<<BT * CDIM / 1024, 256>>>(h, (uint32_t*)hB);

    // fused qkv projection + qk per-head norm: all bf16 outputs
    gemm_kernel<2><<<dim3(24, BT / 128), 128, GEMM_SMEM>>>(hB, WqB, qBf, kBf, vBf, sqk, BT, 3 * CDIM, CDIM);

    vtrans_kernel<<<dim3(BT / 64, CDIM / 64), 256>>>(vBf, VtG);

    attn_tc_kernel<<<dim3(4, 128), 256, ATT_SMEM>>>(qBf, kBf, VtG, yB);

    // o projection -> bf16 t1B
    gemm_kernel<1><<<dim3(8, BT / 128), 128, GEMM_SMEM>>>(yB, WoB, t1B, nullptr, nullptr, nullptr, BT, CDIM, CDIM);

    residual_kernel<<<BT, 256>>>(h, (const __nv_bfloat162*)t1B, a_att, h2, (uint32_t*)h2B);

    // MLP: fc + SwiGLU fused -> x bf16; proj -> bf16 t1B
    gemm_kernel<3><<<dim3(64, BT / 128), 128, GEMM_SMEM>>>(h2B, WfcP, xB, nullptr, nullptr, suv, BT, 8 * CDIM, CDIM);
    gemm_kernel<1><<<dim3(8, BT / 128), 128, GEMM_SMEM>>>(xB, WpjB, t1B, nullptr, nullptr, nullptr, BT, CDIM, 4 * CDIM);

    residual_kernel<<<BT, 256>>>(h2, (const __nv_bfloat162*)t1B, a_mlp, out, nullptr);
}

// round 13
// speedup vs baseline: 1.0169x; 1.0169x over previous
#include <cuda_runtime.h>
#include <cuda_bf16.h>
#include <math.h>
#include <stdint.h>

// nGPT block: B=8, T=1024, C=1024, H=16, D=64
#define BT   8192
#define CDIM 1024

// ---- scratch carve (float units) ----
#define OFF_INV  0
#define OFF_V    4096                         // bf16 v [token][dim]
#define OFF_T1   (OFF_V   + BT*CDIM)          // bf16 t1 [token][dim]
#define OFF_H2   (OFF_T1  + BT*CDIM)
#define OFF_HB   (OFF_H2  + BT*CDIM)
#define OFF_YB   (OFF_HB  + BT*CDIM/2)
#define OFF_H2B  (OFF_YB  + BT*CDIM/2)
#define OFF_XB   (OFF_H2B + BT*CDIM/2)        // 8192x4096 bf16
#define OFF_WQB  (OFF_XB  + BT*4*CDIM/2)      // Wq,Wk,Wv,Wo bf16 contiguous
#define OFF_WFCB (OFF_WQB + 4*CDIM*CDIM/2)    // permuted Wfc bf16
#define OFF_WPJB (OFF_WFCB + 8*CDIM*CDIM/2)
#define OFF_QBF  (OFF_WPJB + 4*CDIM*CDIM/2)   // bf16 q [token][dim]
#define OFF_KBF  (OFF_QBF + BT*CDIM/2)        // bf16 k
#define OFF_VT   (OFF_KBF + BT*CDIM/2)        // bf16 V^T [dim][token]
#define BUF_TOTAL (OFF_VT + BT*CDIM/2)

__device__ float g_buf[BUF_TOTAL];

__device__ __forceinline__ uint32_t cvt2bf(float lo, float hi) {
    uint32_t r;
    asm("cvt.rn.bf16x2.f32 %0, %1, %2;" : "=r"(r) : "f"(hi), "f"(lo));
    return r;
}

// ---------------------------------------------------------------------------
// inverse column norms of W [C,C] row-major: inv[k] = 1/||W[:,k]||
// ---------------------------------------------------------------------------
__global__ void colnorm_kernel(const float* __restrict__ Wq, const float* __restrict__ Wk,
                               const float* __restrict__ Wv, const float* __restrict__ Wo,
                               float* __restrict__ inv)
{
    int m = blockIdx.y;
    const float* W = (m == 0) ? Wq : (m == 1) ? Wk : (m == 2) ? Wv : Wo;
    int tx = threadIdx.x & 31;
    int ty = threadIdx.x >> 5;
    int col = blockIdx.x * 32 + tx;
    float s = 0.f;
    for (int i = ty; i < CDIM; i += 8) {
        float w = W[i * CDIM + col];
        s += w * w;
    }
    __shared__ float sm[8][32];
    sm[ty][tx] = s;
    __syncthreads();
    if (ty == 0) {
        float tot = 0.f;
        #pragma unroll
        for (int r = 0; r < 8; r++) tot += sm[r][tx];
        inv[m * CDIM + col] = rsqrtf(tot);
    }
}

// ---------------------------------------------------------------------------
// Weight conversion with folded column norms (4 matrices)
// ---------------------------------------------------------------------------
__global__ void wconv4_kernel(const float* __restrict__ Wq, const float* __restrict__ Wk,
                              const float* __restrict__ Wv, const float* __restrict__ Wo,
                              const float* __restrict__ inv, uint32_t* __restrict__ dst)
{
    int m = blockIdx.y;
    const float* W = (m == 0) ? Wq : (m == 1) ? Wk : (m == 2) ? Wv : Wo;
    int idx = blockIdx.x * 256 + threadIdx.x;
    float4 w = ((const float4*)W)[idx];
    float4 s = ((const float4*)(inv + m * CDIM))[idx & 255];
    uint32_t* d = dst + (size_t)m * (CDIM * CDIM / 2) + idx * 2;
    d[0] = cvt2bf(w.x * s.x, w.y * s.y);
    d[1] = cvt2bf(w.z * s.z, w.w * s.w);
}

__global__ void conv_kernel(const float* __restrict__ src, uint32_t* __restrict__ dst)
{
    int idx = blockIdx.x * 256 + threadIdx.x;
    float4 v = ((const float4*)src)[idx];
    dst[idx * 2 + 0] = cvt2bf(v.x, v.y);
    dst[idx * 2 + 1] = cvt2bf(v.z, v.w);
}

// ---------------------------------------------------------------------------
// Wfc conversion with row permutation for fused SwiGLU
// ---------------------------------------------------------------------------
__global__ void wfc_perm_kernel(const float* __restrict__ Wfc, uint32_t* __restrict__ dst)
{
    int idx = blockIdx.x * 256 + threadIdx.x;
    int r = idx >> 8, c4 = idx & 255;
    int b = r >> 4, w = r & 15;
    int src_r = (w < 8) ? (b * 8 + w) : (4096 + b * 8 + (w - 8));
    float4 v = ((const float4*)Wfc)[(size_t)src_r * 256 + c4];
    dst[(size_t)idx * 2 + 0] = cvt2bf(v.x, v.y);
    dst[(size_t)idx * 2 + 1] = cvt2bf(v.z, v.w);
}

// ---------------------------------------------------------------------------
// bf16 mma.sync GEMM NT (R9/R11 winning shape): 128x128x64, 3-stage cp.async,
// 4 warps, warp tile 64x64, 128 threads, 2 CTAs/SM.
// MODE 1: bf16 out. MODE 2: fused qkv + qk per-head norm. MODE 3: fused SwiGLU.
// ---------------------------------------------------------------------------
#define STAGES 3
#define GEMM_SMEM (STAGES * 32768)

template <int MODE>
__global__ void __launch_bounds__(128, 2) gemm_kernel(
    const __nv_bfloat16* __restrict__ A, const __nv_bfloat16* __restrict__ B,
    void* __restrict__ C0, void* __restrict__ C1, void* __restrict__ C2,
    const float* __restrict__ scl,
    int M, int N, int K)
{
    extern __shared__ char smc[];
    const int tid = threadIdx.x, lane = tid & 31, warp = tid >> 5;
    const int wm = warp & 1, wn = warp >> 1;
    const int crow = blockIdx.y * 128, ccol = blockIdx.x * 128;
    const uint32_t sbase = (uint32_t)__cvta_generic_to_shared(smc);

    const __nv_bfloat16* Ag = A + (size_t)crow * K;
    const __nv_bfloat16* Bg = B + (size_t)ccol * K;

    auto issue = [&](int t, int buf) {
        const uint32_t abase = sbase + buf * 32768;
        const uint32_t bbase = abase + 16384;
        const int k0 = t * 64;
        #pragma unroll
        for (int i = 0; i < 8; i++) {
            int idx = tid + i * 128;
            int row = idx >> 3, c = idx & 7;
            uint32_t sw = (uint32_t)(row * 128 + ((c ^ (row & 7)) << 4));
            asm volatile("cp.async.cg.shared.global [%0], [%1], 16;"
                         :: "r"(abase + sw), "l"((const void*)(Ag + (size_t)row * K + k0 + c * 8)));
            asm volatile("cp.async.cg.shared.global [%0], [%1], 16;"
                         :: "r"(bbase + sw), "l"((const void*)(Bg + (size_t)row * K + k0 + c * 8)));
        }
    };

    float acc[4][8][4];
    #pragma unroll
    for (int i = 0; i < 4; i++)
        #pragma unroll
        for (int j = 0; j < 8; j++)
            #pragma unroll
            for (int e = 0; e < 4; e++) acc[i][j][e] = 0.f;

    const int nt = K / 64;

    issue(0, 0); asm volatile("cp.async.commit_group;");
    issue(1, 1); asm volatile("cp.async.commit_group;");

    const int arow0 = wm * 64 + (lane & 15);
    const int akb   = lane >> 4;
    const int asw   = lane & 7;
    const int brow0 = wn * 64 + (lane & 7) + ((lane >> 4) << 3);
    const int bkb   = (lane >> 3) & 1;

    for (int t = 0; t < nt; t++) {
        asm volatile("cp.async.wait_group 1;");
        __syncthreads();

        if (t + 2 < nt) {
            issue(t + 2, (t + 2) % STAGES);
        }
        asm volatile("cp.async.commit_group;");

        const int buf = t % STAGES;
        const uint32_t abase = sbase + buf * 32768;
        const uint32_t bbase = abase + 16384;

        #pragma unroll
        for (int ks = 0; ks < 4; ks++) {
            uint32_t a[4][4], br[4][4];
            const int ach = 2 * ks + akb;
            const int bch = 2 * ks + bkb;
            #pragma unroll
            for (int mi = 0; mi < 4; mi++) {
                uint32_t ad = abase + (uint32_t)(arow0 + mi * 16) * 128 +
                              (uint32_t)((ach ^ asw) << 4);
                asm volatile("ldmatrix.sync.aligned.m8n8.x4.shared.b16 {%0,%1,%2,%3}, [%4];"
                             : "=r"(a[mi][0]), "=r"(a[mi][1]), "=r"(a[mi][2]), "=r"(a[mi][3])
                             : "r"(ad));
            }
            #pragma unroll
            for (int nj2 = 0; nj2 < 4; nj2++) {
                uint32_t bd = bbase + (uint32_t)(brow0 + nj2 * 16) * 128 +
                              (uint32_t)((bch ^ asw) << 4);
                asm volatile("ldmatrix.sync.aligned.m8n8.x4.shared.b16 {%0,%1,%2,%3}, [%4];"
                             : "=r"(br[nj2][0]), "=r"(br[nj2][1]), "=r"(br[nj2][2]), "=r"(br[nj2][3])
                             : "r"(bd));
            }
            #pragma unroll
            for (int mi = 0; mi < 4; mi++)
                #pragma unroll
                for (int nj = 0; nj < 8; nj++) {
                    uint32_t b0 = br[nj >> 1][(nj & 1) * 2];
                    uint32_t b1 = br[nj >> 1][(nj & 1) * 2 + 1];
                    asm volatile(
                        "mma.sync.aligned.m16n8k16.row.col.f32.bf16.bf16.f32 "
                        "{%0,%1,%2,%3}, {%4,%5,%6,%7}, {%8,%9}, {%0,%1,%2,%3};"
                        : "+f"(acc[mi][nj][0]), "+f"(acc[mi][nj][1]),
                          "+f"(acc[mi][nj][2]), "+f"(acc[mi][nj][3])
                        : "r"(a[mi][0]), "r"(a[mi][1]), "r"(a[mi][2]), "r"(a[mi][3]),
                          "r"(b0), "r"(b1));
                }
        }
        __syncthreads();
    }

    // ---- epilogue ----
    if (MODE == 3) {
        const int xc0 = blockIdx.x * 64;
        __nv_bfloat16* Xb = (__nv_bfloat16*)C0;
        #pragma unroll
        for (int p = 0; p < 4; p++) {
            const int cb = xc0 + (wn * 4 + p) * 8 + 2 * (lane & 3);
            const float su0 = scl[cb] * 32.f,        su1 = scl[cb + 1] * 32.f;
            const float sg0 = scl[4096 + cb] * 32.f, sg1 = scl[4096 + cb + 1] * 32.f;
            #pragma unroll
            for (int mi = 0; mi < 4; mi++) {
                const int r0 = crow + wm * 64 + mi * 16 + (lane >> 2);
                float g, x0, x1;
                g = acc[mi][2 * p + 1][0] * sg0; x0 = (acc[mi][2 * p][0] * su0) * g / (1.f + __expf(-g));
                g = acc[mi][2 * p + 1][1] * sg1; x1 = (acc[mi][2 * p][1] * su1) * g / (1.f + __expf(-g));
                *(uint32_t*)&Xb[(size_t)r0 * 4096 + cb] = cvt2bf(x0, x1);
                g = acc[mi][2 * p + 1][2] * sg0; x0 = (acc[mi][2 * p][2] * su0) * g / (1.f + __expf(-g));
                g = acc[mi][2 * p + 1][3] * sg1; x1 = (acc[mi][2 * p][3] * su1) * g / (1.f + __expf(-g));
                *(uint32_t*)&Xb[(size_t)(r0 + 8) * 4096 + cb] = cvt2bf(x0, x1);
            }
        }
    } else if (MODE == 2) {
        const int which = ccol >> 10;        // 0=q,1=k,2=v
        const int cl = ccol & 1023;
        if (which == 2) {
            __nv_bfloat16* Cb = (__nv_bfloat16*)C2;
            #pragma unroll
            for (int mi = 0; mi < 4; mi++) {
                const int r0 = crow + wm * 64 + mi * 16 + (lane >> 2);
                #pragma unroll
                for (int nj = 0; nj < 8; nj++) {
                    const int c0 = cl + wn * 64 + nj * 8 + 2 * (lane & 3);
                    *(uint32_t*)&Cb[(size_t)r0 * 1024 + c0] =
                        cvt2bf(acc[mi][nj][0], acc[mi][nj][1]);
                    *(uint32_t*)&Cb[(size_t)(r0 + 8) * 1024 + c0] =
                        cvt2bf(acc[mi][nj][2], acc[mi][nj][3]);
                }
            }
        } else {
            __nv_bfloat16* Cb = which ? (__nv_bfloat16*)C1 : (__nv_bfloat16*)C0;
            const float extra = which ? 32.f : 256.f;
            float sc0[8], sc1[8];
            #pragma unroll
            for (int nj = 0; nj < 8; nj++) {
                const int c0 = cl + wn * 64 + nj * 8 + 2 * (lane & 3);
                sc0[nj] = scl[c0] * extra;
                sc1[nj] = scl[c0 + 1] * extra;
            }
            #pragma unroll
            for (int mi = 0; mi < 4; mi++) {
                const int r0 = crow + wm * 64 + mi * 16 + (lane >> 2);
                float ss0 = 0.f, ss1 = 0.f;
                #pragma unroll
                for (int nj = 0; nj < 8; nj++) {
                    ss0 += acc[mi][nj][0] * acc[mi][nj][0] + acc[mi][nj][1] * acc[mi][nj][1];
                    ss1 += acc[mi][nj][2] * acc[mi][nj][2] + acc[mi][nj][3] * acc[mi][nj][3];
                }
                ss0 += __shfl_xor_sync(0xffffffffu, ss0, 1);
                ss0 += __shfl_xor_sync(0xffffffffu, ss0, 2);
                ss1 += __shfl_xor_sync(0xffffffffu, ss1, 1);
                ss1 += __shfl_xor_sync(0xffffffffu, ss1, 2);
                const float rn0 = rsqrtf(ss0), rn1 = rsqrtf(ss1);
                #pragma unroll
                for (int nj = 0; nj < 8; nj++) {
                    const int c0 = cl + wn * 64 + nj * 8 + 2 * (lane & 3);
                    *(uint32_t*)&Cb[(size_t)r0 * 1024 + c0] =
                        cvt2bf(acc[mi][nj][0] * rn0 * sc0[nj], acc[mi][nj][1] * rn0 * sc1[nj]);
                    *(uint32_t*)&Cb[(size_t)(r0 + 8) * 1024 + c0] =
                        cvt2bf(acc[mi][nj][2] * rn1 * sc0[nj], acc[mi][nj][3] * rn1 * sc1[nj]);
                }
            }
        }
    } else {
        __nv_bfloat16* Cb = (__nv_bfloat16*)C0;
        #pragma unroll
        for (int mi = 0; mi < 4; mi++) {
            const int r0 = crow + wm * 64 + mi * 16 + (lane >> 2);
            #pragma unroll
            for (int nj = 0; nj < 8; nj++) {
                const int c0 = ccol + wn * 64 + nj * 8 + 2 * (lane & 3);
                *(uint32_t*)&Cb[(size_t)r0 * N + c0] =
                    cvt2bf(acc[mi][nj][0], acc[mi][nj][1]);
                *(uint32_t*)&Cb[(size_t)(r0 + 8) * N + c0] =
                    cvt2bf(acc[mi][nj][2], acc[mi][nj][3]);
            }
        }
    }
}

// ---------------------------------------------------------------------------
// V transpose: vB bf16 [8192][1024] -> Vt bf16 [1024][8192]
// ---------------------------------------------------------------------------
__global__ void vtrans_kernel(const __nv_bfloat16* __restrict__ vB,
                              __nv_bfloat16* __restrict__ Vt)
{
    __shared__ __nv_bfloat16 tile[64][72];
    int tid = threadIdx.x;
    int t0 = blockIdx.x * 64, d0 = blockIdx.y * 64;
    #pragma unroll
    for (int i = 0; i < 2; i++) {
        int idx = tid + i * 256;
        int row = idx >> 3, c = idx & 7;
        uint4 v = *(const uint4*)&vB[(size_t)(t0 + row) * CDIM + d0 + c * 8];
        __nv_bfloat16 tmp[8];
        *(uint4*)tmp = v;
        #pragma unroll
        for (int j = 0; j < 8; j++) tile[c * 8 + j][row] = tmp[j];
    }
    __syncthreads();
    #pragma unroll
    for (int i = 0; i < 2; i++) {
        int idx = tid + i * 256;
        int d = idx >> 3, c = idx & 7;
        *(uint4*)&Vt[(size_t)(d0 + d) * BT + t0 + c * 8] = *(uint4*)&tile[d][c * 8];
    }
}

// ---------------------------------------------------------------------------
// Tensor-core flash attention (non-causal), D=64. (R11 winner, unchanged)
// ---------------------------------------------------------------------------
#define ATT_SMEM (16384 + 3 * 32768)

__global__ void __launch_bounds__(256) attn_tc_kernel(
    const __nv_bfloat16* __restrict__ q, const __nv_bfloat16* __restrict__ k,
    const __nv_bfloat16* __restrict__ vt, __nv_bfloat16* __restrict__ y)
{
    extern __shared__ char smc[];
    const int tid = threadIdx.x, lane = tid & 31, warp = tid >> 5;
    const int bh = blockIdx.y, b = bh >> 4, cb = (bh & 15) * 64;
    const int tq0 = b * 1024 + blockIdx.x * 128;
    const uint32_t sb = (uint32_t)__cvta_generic_to_shared(smc);
    const uint32_t qs = sb;

    #pragma unroll
    for (int i = 0; i < 4; i++) {
        int idx = tid + i * 256;
        int row = idx >> 3, c = idx & 7;
        uint32_t sw = (uint32_t)(row * 128 + ((c ^ (row & 7)) << 4));
        asm volatile("cp.async.cg.shared.global [%0], [%1], 16;"
                     :: "r"(qs + sw), "l"((const void*)(q + (size_t)(tq0 + row) * CDIM + cb + c * 8)));
    }
    asm volatile("cp.async.commit_group;");

    auto issueKV = [&](int kt, int buf) {
        const int tk0 = b * 1024 + kt * 128;
        const uint32_t kb_ = sb + 16384 + buf * 32768;
        const uint32_t vb_ = kb_ + 16384;
        #pragma unroll
        for (int i = 0; i < 4; i++) {
            int idx = tid + i * 256;
            int row = idx >> 3, c = idx & 7;
            uint32_t sw = (uint32_t)(row * 128 + ((c ^ (row & 7)) << 4));
            asm volatile("cp.async.cg.shared.global [%0], [%1], 16;"
                         :: "r"(kb_ + sw), "l"((const void*)(k + (size_t)(tk0 + row) * CDIM + cb + c * 8)));
            asm volatile("cp.async.cg.shared.global [%0], [%1], 16;"
                         :: "r"(vb_ + sw),
                            "l"((const void*)(vt + (size_t)(cb + (row & 63)) * BT + tk0 + (row >> 6) * 64 + c * 8)));
        }
    };

    issueKV(0, 0); asm volatile("cp.async.commit_group;");
    issueKV(1, 1); asm volatile("cp.async.commit_group;");

    asm volatile("cp.async.wait_group 2;");
    __syncthreads();

    const int arow = warp * 16 + (lane & 15);
    const int akb  = lane >> 4;
    const int lsw  = lane & 7;
    uint32_t aq[4][4];
    #pragma unroll
    for (int ks = 0; ks < 4; ks++) {
        uint32_t ad = qs + (uint32_t)arow * 128 + (uint32_t)(((2 * ks + akb) ^ lsw) << 4);
        asm volatile("ldmatrix.sync.aligned.m8n8.x4.shared.b16 {%0,%1,%2,%3}, [%4];"
                     : "=r"(aq[ks][0]), "=r"(aq[ks][1]), "=r"(aq[ks][2]), "=r"(aq[ks][3])
                     : "r"(ad));
    }

    float acc_o[8][4];
    #pragma unroll
    for (int j = 0; j < 8; j++)
        #pragma unroll
        for (int e = 0; e < 4; e++) acc_o[j][e] = 0.f;
    float m0 = -1e30f, m1 = -1e30f, l0 = 0.f, l1 = 0.f;

    const int brow = (lane & 7) + ((lane >> 4) << 3);
    const int bkb  = (lane >> 3) & 1;

    for (int kt = 0; kt < 8; kt++) {
        asm volatile("cp.async.wait_group 1;");
        __syncthreads();

        const uint32_t kb_ = sb + 16384 + (kt % 3) * 32768;
        const uint32_t vb_ = kb_ + 16384;

        float s[16][4];
        #pragma unroll
        for (int j = 0; j < 16; j++)
            #pragma unroll
            for (int e = 0; e < 4; e++) s[j][e] = 0.f;

        #pragma unroll
        for (int ks = 0; ks < 4; ks++) {
            const int bch = 2 * ks + bkb;
            #pragma unroll
            for (int nj2 = 0; nj2 < 8; nj2++) {
                uint32_t bk[4];
                uint32_t bd = kb_ + (uint32_t)(brow + nj2 * 16) * 128 +
                              (uint32_t)((bch ^ lsw) << 4);
                asm volatile("ldmatrix.sync.aligned.m8n8.x4.shared.b16 {%0,%1,%2,%3}, [%4];"
                             : "=r"(bk[0]), "=r"(bk[1]), "=r"(bk[2]), "=r"(bk[3]) : "r"(bd));
                asm volatile(
                    "mma.sync.aligned.m16n8k16.row.col.f32.bf16.bf16.f32 "
                    "{%0,%1,%2,%3}, {%4,%5,%6,%7}, {%8,%9}, {%0,%1,%2,%3};"
                    : "+f"(s[2 * nj2][0]), "+f"(s[2 * nj2][1]), "+f"(s[2 * nj2][2]), "+f"(s[2 * nj2][3])
                    : "r"(aq[ks][0]), "r"(aq[ks][1]), "r"(aq[ks][2]), "r"(aq[ks][3]),
                      "r"(bk[0]), "r"(bk[1]));
                asm volatile(
                    "mma.sync.aligned.m16n8k16.row.col.f32.bf16.bf16.f32 "
                    "{%0,%1,%2,%3}, {%4,%5,%6,%7}, {%8,%9}, {%0,%1,%2,%3};"
                    : "+f"(s[2 * nj2 + 1][0]), "+f"(s[2 * nj2 + 1][1]), "+f"(s[2 * nj2 + 1][2]), "+f"(s[2 * nj2 + 1][3])
                    : "r"(aq[ks][0]), "r"(aq[ks][1]), "r"(aq[ks][2]), "r"(aq[ks][3]),
                      "r"(bk[2]), "r"(bk[3]));
            }
        }

        float rm0 = -1e30f, rm1 = -1e30f;
        #pragma unroll
        for (int j = 0; j < 16; j++) {
            rm0 = fmaxf(rm0, fmaxf(s[j][0], s[j][1]));
            rm1 = fmaxf(rm1, fmaxf(s[j][2], s[j][3]));
        }
        rm0 = fmaxf(rm0, __shfl_xor_sync(0xffffffffu, rm0, 1));
        rm0 = fmaxf(rm0, __shfl_xor_sync(0xffffffffu, rm0, 2));
        rm1 = fmaxf(rm1, __shfl_xor_sync(0xffffffffu, rm1, 1));
        rm1 = fmaxf(rm1, __shfl_xor_sync(0xffffffffu, rm1, 2));
        float nm0 = fmaxf(m0, rm0), nm1 = fmaxf(m1, rm1);
        float co0 = __expf(m0 - nm0), co1 = __expf(m1 - nm1);
        float ls0 = 0.f, ls1 = 0.f;
        #pragma unroll
        for (int j = 0; j < 16; j++) {
            s[j][0] = __expf(s[j][0] - nm0); ls0 += s[j][0];
            s[j][1] = __expf(s[j][1] - nm0); ls0 += s[j][1];
            s[j][2] = __expf(s[j][2] - nm1); ls1 += s[j][2];
            s[j][3] = __expf(s[j][3] - nm1); ls1 += s[j][3];
        }
        ls0 += __shfl_xor_sync(0xffffffffu, ls0, 1);
        ls0 += __shfl_xor_sync(0xffffffffu, ls0, 2);
        ls1 += __shfl_xor_sync(0xffffffffu, ls1, 1);
        ls1 += __shfl_xor_sync(0xffffffffu, ls1, 2);
        l0 = l0 * co0 + ls0; l1 = l1 * co1 + ls1;
        m0 = nm0; m1 = nm1;
        #pragma unroll
        for (int j = 0; j < 8; j++) {
            acc_o[j][0] *= co0; acc_o[j][1] *= co0;
            acc_o[j][2] *= co1; acc_o[j][3] *= co1;
        }

        #pragma unroll
        for (int kp = 0; kp < 8; kp++) {
            uint32_t ap[4];
            ap[0] = cvt2bf(s[2 * kp][0],     s[2 * kp][1]);
            ap[1] = cvt2bf(s[2 * kp][2],     s[2 * kp][3]);
            ap[2] = cvt2bf(s[2 * kp + 1][0], s[2 * kp + 1][1]);
            ap[3] = cvt2bf(s[2 * kp + 1][2], s[2 * kp + 1][3]);
            const uint32_t vbase = vb_ + (uint32_t)((kp >> 2) * 8192);
            const int ach = 2 * (kp & 3) + bkb;
            #pragma unroll
            for (int dj2 = 0; dj2 < 4; dj2++) {
                uint32_t bv[4];
                uint32_t bd = vbase + (uint32_t)(brow + dj2 * 16) * 128 +
                              (uint32_t)((ach ^ lsw) << 4);
                asm volatile("ldmatrix.sync.aligned.m8n8.x4.shared.b16 {%0,%1,%2,%3}, [%4];"
                             : "=r"(bv[0]), "=r"(bv[1]), "=r"(bv[2]), "=r"(bv[3]) : "r"(bd));
                asm volatile(
                    "mma.sync.aligned.m16n8k16.row.col.f32.bf16.bf16.f32 "
                    "{%0,%1,%2,%3}, {%4,%5,%6,%7}, {%8,%9}, {%0,%1,%2,%3};"
                    : "+f"(acc_o[2 * dj2][0]), "+f"(acc_o[2 * dj2][1]), "+f"(acc_o[2 * dj2][2]), "+f"(acc_o[2 * dj2][3])
                    : "r"(ap[0]), "r"(ap[1]), "r"(ap[2]), "r"(ap[3]), "r"(bv[0]), "r"(bv[1]));
                asm volatile(
                    "mma.sync.aligned.m16n8k16.row.col.f32.bf16.bf16.f32 "
                    "{%0,%1,%2,%3}, {%4,%5,%6,%7}, {%8,%9}, {%0,%1,%2,%3};"
                    : "+f"(acc_o[2 * dj2 + 1][0]), "+f"(acc_o[2 * dj2 + 1][1]), "+f"(acc_o[2 * dj2 + 1][2]), "+f"(acc_o[2 * dj2 + 1][3])
                    : "r"(ap[0]), "r"(ap[1]), "r"(ap[2]), "r"(ap[3]), "r"(bv[2]), "r"(bv[3]));
            }
        }

        if (kt + 2 < 8) issueKV(kt + 2, (kt + 2) % 3);
        asm volatile("cp.async.commit_group;");
    }

    const float li0 = 1.f / l0, li1 = 1.f / l1;
    const int r0 = tq0 + warp * 16 + (lane >> 2);
    #pragma unroll
    for (int dj = 0; dj < 8; dj++) {
        const int c0 = cb + dj * 8 + 2 * (lane & 3);
        *(uint32_t*)&y[(size_t)r0 * CDIM + c0] =
            cvt2bf(acc_o[dj][0] * li0, acc_o[dj][1] * li0);
        *(uint32_t*)&y[(size_t)(r0 + 8) * CDIM + c0] =
            cvt2bf(acc_o[dj][2] * li1, acc_o[dj][3] * li1);
    }
}

// ---------------------------------------------------------------------------
// out = justnorm( justnorm(h) + |alpha*1.6| * (justnorm(hb) - justnorm(h)) )
// hb is bf16 (lr-damped branch).
// ---------------------------------------------------------------------------
__global__ void residual_kernel(const float* __restrict__ hin,
                                const __nv_bfloat162* __restrict__ hb,
                                const float* __restrict__ alpha, float* __restrict__ out,
                                uint32_t* __restrict__ outb)
{
    int t = blockIdx.x, tid = threadIdx.x;
    float4 a = ((const float4*)hin)[(size_t)t * 256 + tid];
    __nv_bfloat162 b0 = hb[((size_t)t * 256 + tid) * 2];
    __nv_bfloat162 b1 = hb[((size_t)t * 256 + tid) * 2 + 1];
    float4 b = make_float4(__bfloat162float(b0.x), __bfloat162float(b0.y),
                           __bfloat162float(b1.x), __bfloat162float(b1.y));
    float s1 = a.x * a.x + a.y * a.y + a.z * a.z + a.w * a.w;
    float s2 = b.x * b.x + b.y * b.y + b.z * b.z + b.w * b.w;
    #pragma unroll
    for (int off = 16; off >= 1; off >>= 1) {
        s1 += __shfl_xor_sync(0xffffffffu, s1, off);
        s2 += __shfl_xor_sync(0xffffffffu, s2, off);
    }
    __shared__ float red1[8], red2[8];
    int w = tid >> 5, lane = tid & 31;
    if (lane == 0) { red1[w] = s1; red2[w] = s2; }
    __syncthreads();
    float t1 = 0.f, t2 = 0.f;
    #pragma unroll
    for (int i = 0; i < 8; i++) { t1 += red1[i]; t2 += red2[i]; }
    float r1 = rsqrtf(t1), r2 = rsqrtf(t2);

    float4 al = ((const float4*)alpha)[tid];
    float4 u;
    u.x = a.x * r1 + fabsf(al.x * 1.6f) * (b.x * r2 - a.x * r1);
    u.y = a.y * r1 + fabsf(al.y * 1.6f) * (b.y * r2 - a.y * r1);
    u.z = a.z * r1 + fabsf(al.z * 1.6f) * (b.z * r2 - a.z * r1);
    u.w = a.w * r1 + fabsf(al.w * 1.6f) * (b.w * r2 - a.w * r1);

    float s3 = u.x * u.x + u.y * u.y + u.z * u.z + u.w * u.w;
    #pragma unroll
    for (int off = 16; off >= 1; off >>= 1) s3 += __shfl_xor_sync(0xffffffffu, s3, off);
    __syncthreads();
    if (lane == 0) red1[w] = s3;
    __syncthreads();
    float t3 = 0.f;
    #pragma unroll
    for (int i = 0; i < 8; i++) t3 += red1[i];
    float r3 = rsqrtf(t3);
    float4 o = make_float4(u.x * r3, u.y * r3, u.z * r3, u.w * r3);
    ((float4*)out)[(size_t)t * 256 + tid] = o;
    if (outb) {
        outb[((size_t)t * 256 + tid) * 2 + 0] = cvt2bf(o.x, o.y);
        outb[((size_t)t * 256 + tid) * 2 + 1] = cvt2bf(o.z, o.w);
    }
}

// ---------------------------------------------------------------------------
extern "C" void kernel_launch(void* const* d_in, const int* in_sizes, int n_in,
                              void* d_out, int out_size)
{
    (void)in_sizes; (void)n_in; (void)out_size;
    const float* h     = (const float*)d_in[0];
    const float* Wq    = (const float*)d_in[1];
    const float* Wk    = (const float*)d_in[2];
    const float* Wv    = (const float*)d_in[3];
    const float* Wo    = (const float*)d_in[4];
    const float* Wfc   = (const float*)d_in[5];
    const float* Wproj = (const float*)d_in[6];
    const float* sqk   = (const float*)d_in[7];
    const float* suv   = (const float*)d_in[8];
    const float* a_att = (const float*)d_in[9];
    const float* a_mlp = (const float*)d_in[10];
    float* out = (float*)d_out;

    float* buf = nullptr;
    cudaGetSymbolAddress((void**)&buf, g_buf);
    float* inv = buf + OFF_INV;
    float* h2  = buf + OFF_H2;
    __nv_bfloat16* vBf  = (__nv_bfloat16*)(buf + OFF_V);
    __nv_bfloat16* t1B  = (__nv_bfloat16*)(buf + OFF_T1);
    __nv_bfloat16* hB   = (__nv_bfloat16*)(buf + OFF_HB);
    __nv_bfloat16* yB   = (__nv_bfloat16*)(buf + OFF_YB);
    __nv_bfloat16* h2B  = (__nv_bfloat16*)(buf + OFF_H2B);
    __nv_bfloat16* xB   = (__nv_bfloat16*)(buf + OFF_XB);
    __nv_bfloat16* WqB  = (__nv_bfloat16*)(buf + OFF_WQB);   // q,k,v contiguous
    __nv_bfloat16* WoB  = WqB + 3 * CDIM * CDIM;
    __nv_bfloat16* WfcP = (__nv_bfloat16*)(buf + OFF_WFCB);  // permuted
    __nv_bfloat16* WpjB = (__nv_bfloat16*)(buf + OFF_WPJB);
    __nv_bfloat16* qBf  = (__nv_bfloat16*)(buf + OFF_QBF);
    __nv_bfloat16* kBf  = (__nv_bfloat16*)(buf + OFF_KBF);
    __nv_bfloat16* VtG  = (__nv_bfloat16*)(buf + OFF_VT);

    cudaFuncSetAttribute(attn_tc_kernel, cudaFuncAttributeMaxDynamicSharedMemorySize, ATT_SMEM);
    cudaFuncSetAttribute(gemm_kernel<1>, cudaFuncAttributeMaxDynamicSharedMemorySize, GEMM_SMEM);
    cudaFuncSetAttribute(gemm_kernel<2>, cudaFuncAttributeMaxDynamicSharedMemorySize, GEMM_SMEM);
    cudaFuncSetAttribute(gemm_kernel<3>, cudaFuncAttributeMaxDynamicSharedMemorySize, GEMM_SMEM);

    // lazily-created side stream + fork/join events (host resources only;
    // identical captured work on every call)
    static cudaStream_t s2 = nullptr;
    static cudaEvent_t evF = nullptr, evJ = nullptr;
    if (!s2) {
        cudaStreamCreateWithFlags(&s2, cudaStreamNonBlocking);
        cudaEventCreateWithFlags(&evF, cudaEventDisableTiming);
        cudaEventCreateWithFlags(&evJ, cudaEventDisableTiming);
    }

    // ---- fork: MLP weight prep runs concurrently with the attention chain ----
    cudaEventRecord(evF, 0);
    cudaStreamWaitEvent(s2, evF, 0);
    wfc_perm_kernel<<<8 * CDIM * CDIM / 1024, 256, 0, s2>>>(Wfc, (uint32_t*)WfcP);
    conv_kernel<<<4 * CDIM * CDIM / 1024, 256, 0, s2>>>(Wproj, (uint32_t*)WpjB);
    cudaEventRecord(evJ, s2);

    // ---- main chain ----
    colnorm_kernel<<<dim3(32, 4), 256>>>(Wq, Wk, Wv, Wo, inv);
    wconv4_kernel<<<dim3(1024, 4), 256>>>(Wq, Wk, Wv, Wo, inv, (uint32_t*)WqB);
    conv_kernel<<<BT * CDIM / 1024, 256>>>(h, (uint32_t*)hB);

    // fused qkv projection + qk per-head norm: all bf16 outputs
    gemm_kernel<2><<<dim3(24, BT / 128), 128, GEMM_SMEM>>>(hB, WqB, qBf, kBf, vBf, sqk, BT, 3 * CDIM, CDIM);

    vtrans_kernel<<<dim3(BT / 64, CDIM / 64), 256>>>(vBf, VtG);

    attn_tc_kernel<<<dim3(8, 128), 256, ATT_SMEM>>>(qBf, kBf, VtG, yB);

    // o projection -> bf16 t1B
    gemm_kernel<1><<<dim3(8, BT / 128), 128, GEMM_SMEM>>>(yB, WoB, t1B, nullptr, nullptr, nullptr, BT, CDIM, CDIM);

    residual_kernel<<<BT, 256>>>(h, (const __nv_bfloat162*)t1B, a_att, h2, (uint32_t*)h2B);

    // join before fc (needs WfcP; proj needs WpjB)
    cudaStreamWaitEvent(0, evJ, 0);

    // MLP: fc + SwiGLU fused -> x bf16; proj -> bf16 t1B
    gemm_kernel<3><<<dim3(64, BT / 128), 128, GEMM_SMEM>>>(h2B, WfcP, xB, nullptr, nullptr, suv, BT, 8 * CDIM, CDIM);
    gemm_kernel<1><<<dim3(8, BT / 128), 128, GEMM_SMEM>>>(xB, WpjB, t1B, nullptr, nullptr, nullptr, BT, CDIM, 4 * CDIM);

    residual_kernel<<<BT, 256>>>(h2, (const __nv_bfloat162*)t1B, a_mlp, out, nullptr);
}

// round 14
// speedup vs baseline: 1.0301x; 1.0129x over previous
#include <cuda_runtime.h>
#include <cuda_bf16.h>
#include <math.h>
#include <stdint.h>

// nGPT block: B=8, T=1024, C=1024, H=16, D=64
#define BT   8192
#define CDIM 1024

// ---- scratch carve (float units) ----
#define OFF_INV  0
#define OFF_T1   4096                         // bf16 t1 [token][dim]
#define OFF_H2   (OFF_T1  + BT*CDIM)
#define OFF_HB   (OFF_H2  + BT*CDIM)
#define OFF_YB   (OFF_HB  + BT*CDIM/2)
#define OFF_H2B  (OFF_YB  + BT*CDIM/2)
#define OFF_XB   (OFF_H2B + BT*CDIM/2)        // 8192x4096 bf16
#define OFF_WQB  (OFF_XB  + BT*4*CDIM/2)      // Wq,Wk,Wv,Wo bf16 contiguous
#define OFF_WFCB (OFF_WQB + 4*CDIM*CDIM/2)    // permuted Wfc bf16
#define OFF_WPJB (OFF_WFCB + 8*CDIM*CDIM/2)
#define OFF_QBF  (OFF_WPJB + 4*CDIM*CDIM/2)   // bf16 q [token][dim]
#define OFF_KBF  (OFF_QBF + BT*CDIM/2)        // bf16 k
#define OFF_VT   (OFF_KBF + BT*CDIM/2)        // bf16 V^T [dim][token]
#define BUF_TOTAL (OFF_VT + BT*CDIM/2)

__device__ float g_buf[BUF_TOTAL];

__device__ __forceinline__ uint32_t cvt2bf(float lo, float hi) {
    uint32_t r;
    asm("cvt.rn.bf16x2.f32 %0, %1, %2;" : "=r"(r) : "f"(hi), "f"(lo));
    return r;
}

// ---------------------------------------------------------------------------
// inverse column norms of W [C,C] row-major: inv[k] = 1/||W[:,k]||
// ---------------------------------------------------------------------------
__global__ void colnorm_kernel(const float* __restrict__ Wq, const float* __restrict__ Wk,
                               const float* __restrict__ Wv, const float* __restrict__ Wo,
                               float* __restrict__ inv)
{
    int m = blockIdx.y;
    const float* W = (m == 0) ? Wq : (m == 1) ? Wk : (m == 2) ? Wv : Wo;
    int tx = threadIdx.x & 31;
    int ty = threadIdx.x >> 5;
    int col = blockIdx.x * 32 + tx;
    float s = 0.f;
    for (int i = ty; i < CDIM; i += 8) {
        float w = W[i * CDIM + col];
        s += w * w;
    }
    __shared__ float sm[8][32];
    sm[ty][tx] = s;
    __syncthreads();
    if (ty == 0) {
        float tot = 0.f;
        #pragma unroll
        for (int r = 0; r < 8; r++) tot += sm[r][tx];
        inv[m * CDIM + col] = rsqrtf(tot);
    }
}

// ---------------------------------------------------------------------------
// Weight conversion with folded column norms (4 matrices)
// ---------------------------------------------------------------------------
__global__ void wconv4_kernel(const float* __restrict__ Wq, const float* __restrict__ Wk,
                              const float* __restrict__ Wv, const float* __restrict__ Wo,
                              const float* __restrict__ inv, uint32_t* __restrict__ dst)
{
    int m = blockIdx.y;
    const float* W = (m == 0) ? Wq : (m == 1) ? Wk : (m == 2) ? Wv : Wo;
    int idx = blockIdx.x * 256 + threadIdx.x;
    float4 w = ((const float4*)W)[idx];
    float4 s = ((const float4*)(inv + m * CDIM))[idx & 255];
    uint32_t* d = dst + (size_t)m * (CDIM * CDIM / 2) + idx * 2;
    d[0] = cvt2bf(w.x * s.x, w.y * s.y);
    d[1] = cvt2bf(w.z * s.z, w.w * s.w);
}

__global__ void conv_kernel(const float* __restrict__ src, uint32_t* __restrict__ dst)
{
    int idx = blockIdx.x * 256 + threadIdx.x;
    float4 v = ((const float4*)src)[idx];
    dst[idx * 2 + 0] = cvt2bf(v.x, v.y);
    dst[idx * 2 + 1] = cvt2bf(v.z, v.w);
}

// ---------------------------------------------------------------------------
// Wfc conversion with row permutation for fused SwiGLU
// ---------------------------------------------------------------------------
__global__ void wfc_perm_kernel(const float* __restrict__ Wfc, uint32_t* __restrict__ dst)
{
    int idx = blockIdx.x * 256 + threadIdx.x;
    int r = idx >> 8, c4 = idx & 255;
    int b = r >> 4, w = r & 15;
    int src_r = (w < 8) ? (b * 8 + w) : (4096 + b * 8 + (w - 8));
    float4 v = ((const float4*)Wfc)[(size_t)src_r * 256 + c4];
    dst[(size_t)idx * 2 + 0] = cvt2bf(v.x, v.y);
    dst[(size_t)idx * 2 + 1] = cvt2bf(v.z, v.w);
}

// ---------------------------------------------------------------------------
// bf16 mma.sync GEMM NT (R9/R11 winning shape): 128x128x64, 3-stage cp.async,
// 4 warps, warp tile 64x64, 128 threads, 2 CTAs/SM.
// MODE 1: bf16 out.
// MODE 2: fused qkv: q,k -> per-head normalized bf16; v -> TRANSPOSED bf16
//         written directly into Vt [dim][token] via smem staging.
// MODE 3: fused SwiGLU (permuted Wfc) -> x bf16 [M,4096].
// ---------------------------------------------------------------------------
#define STAGES 3
#define GEMM_SMEM (STAGES * 32768)

template <int MODE>
__global__ void __launch_bounds__(128, 2) gemm_kernel(
    const __nv_bfloat16* __restrict__ A, const __nv_bfloat16* __restrict__ B,
    void* __restrict__ C0, void* __restrict__ C1, void* __restrict__ C2,
    const float* __restrict__ scl,
    int M, int N, int K)
{
    extern __shared__ char smc[];
    const int tid = threadIdx.x, lane = tid & 31, warp = tid >> 5;
    const int wm = warp & 1, wn = warp >> 1;
    const int crow = blockIdx.y * 128, ccol = blockIdx.x * 128;
    const uint32_t sbase = (uint32_t)__cvta_generic_to_shared(smc);

    const __nv_bfloat16* Ag = A + (size_t)crow * K;
    const __nv_bfloat16* Bg = B + (size_t)ccol * K;

    auto issue = [&](int t, int buf) {
        const uint32_t abase = sbase + buf * 32768;
        const uint32_t bbase = abase + 16384;
        const int k0 = t * 64;
        #pragma unroll
        for (int i = 0; i < 8; i++) {
            int idx = tid + i * 128;
            int row = idx >> 3, c = idx & 7;
            uint32_t sw = (uint32_t)(row * 128 + ((c ^ (row & 7)) << 4));
            asm volatile("cp.async.cg.shared.global [%0], [%1], 16;"
                         :: "r"(abase + sw), "l"((const void*)(Ag + (size_t)row * K + k0 + c * 8)));
            asm volatile("cp.async.cg.shared.global [%0], [%1], 16;"
                         :: "r"(bbase + sw), "l"((const void*)(Bg + (size_t)row * K + k0 + c * 8)));
        }
    };

    float acc[4][8][4];
    #pragma unroll
    for (int i = 0; i < 4; i++)
        #pragma unroll
        for (int j = 0; j < 8; j++)
            #pragma unroll
            for (int e = 0; e < 4; e++) acc[i][j][e] = 0.f;

    const int nt = K / 64;

    issue(0, 0); asm volatile("cp.async.commit_group;");
    issue(1, 1); asm volatile("cp.async.commit_group;");

    const int arow0 = wm * 64 + (lane & 15);
    const int akb   = lane >> 4;
    const int asw   = lane & 7;
    const int brow0 = wn * 64 + (lane & 7) + ((lane >> 4) << 3);
    const int bkb   = (lane >> 3) & 1;

    for (int t = 0; t < nt; t++) {
        asm volatile("cp.async.wait_group 1;");
        __syncthreads();

        if (t + 2 < nt) {
            issue(t + 2, (t + 2) % STAGES);
        }
        asm volatile("cp.async.commit_group;");

        const int buf = t % STAGES;
        const uint32_t abase = sbase + buf * 32768;
        const uint32_t bbase = abase + 16384;

        #pragma unroll
        for (int ks = 0; ks < 4; ks++) {
            uint32_t a[4][4], br[4][4];
            const int ach = 2 * ks + akb;
            const int bch = 2 * ks + bkb;
            #pragma unroll
            for (int mi = 0; mi < 4; mi++) {
                uint32_t ad = abase + (uint32_t)(arow0 + mi * 16) * 128 +
                              (uint32_t)((ach ^ asw) << 4);
                asm volatile("ldmatrix.sync.aligned.m8n8.x4.shared.b16 {%0,%1,%2,%3}, [%4];"
                             : "=r"(a[mi][0]), "=r"(a[mi][1]), "=r"(a[mi][2]), "=r"(a[mi][3])
                             : "r"(ad));
            }
            #pragma unroll
            for (int nj2 = 0; nj2 < 4; nj2++) {
                uint32_t bd = bbase + (uint32_t)(brow0 + nj2 * 16) * 128 +
                              (uint32_t)((bch ^ asw) << 4);
                asm volatile("ldmatrix.sync.aligned.m8n8.x4.shared.b16 {%0,%1,%2,%3}, [%4];"
                             : "=r"(br[nj2][0]), "=r"(br[nj2][1]), "=r"(br[nj2][2]), "=r"(br[nj2][3])
                             : "r"(bd));
            }
            #pragma unroll
            for (int mi = 0; mi < 4; mi++)
                #pragma unroll
                for (int nj = 0; nj < 8; nj++) {
                    uint32_t b0 = br[nj >> 1][(nj & 1) * 2];
                    uint32_t b1 = br[nj >> 1][(nj & 1) * 2 + 1];
                    asm volatile(
                        "mma.sync.aligned.m16n8k16.row.col.f32.bf16.bf16.f32 "
                        "{%0,%1,%2,%3}, {%4,%5,%6,%7}, {%8,%9}, {%0,%1,%2,%3};"
                        : "+f"(acc[mi][nj][0]), "+f"(acc[mi][nj][1]),
                          "+f"(acc[mi][nj][2]), "+f"(acc[mi][nj][3])
                        : "r"(a[mi][0]), "r"(a[mi][1]), "r"(a[mi][2]), "r"(a[mi][3]),
                          "r"(b0), "r"(b1));
                }
        }
        __syncthreads();
    }

    // ---- epilogue ----
    if (MODE == 3) {
        const int xc0 = blockIdx.x * 64;
        __nv_bfloat16* Xb = (__nv_bfloat16*)C0;
        #pragma unroll
        for (int p = 0; p < 4; p++) {
            const int cb = xc0 + (wn * 4 + p) * 8 + 2 * (lane & 3);
            const float su0 = scl[cb] * 32.f,        su1 = scl[cb + 1] * 32.f;
            const float sg0 = scl[4096 + cb] * 32.f, sg1 = scl[4096 + cb + 1] * 32.f;
            #pragma unroll
            for (int mi = 0; mi < 4; mi++) {
                const int r0 = crow + wm * 64 + mi * 16 + (lane >> 2);
                float g, x0, x1;
                g = acc[mi][2 * p + 1][0] * sg0; x0 = (acc[mi][2 * p][0] * su0) * g / (1.f + __expf(-g));
                g = acc[mi][2 * p + 1][1] * sg1; x1 = (acc[mi][2 * p][1] * su1) * g / (1.f + __expf(-g));
                *(uint32_t*)&Xb[(size_t)r0 * 4096 + cb] = cvt2bf(x0, x1);
                g = acc[mi][2 * p + 1][2] * sg0; x0 = (acc[mi][2 * p][2] * su0) * g / (1.f + __expf(-g));
                g = acc[mi][2 * p + 1][3] * sg1; x1 = (acc[mi][2 * p][3] * su1) * g / (1.f + __expf(-g));
                *(uint32_t*)&Xb[(size_t)(r0 + 8) * 4096 + cb] = cvt2bf(x0, x1);
            }
        }
    } else if (MODE == 2) {
        const int which = ccol >> 10;        // 0=q,1=k,2=v
        const int cl = ccol & 1023;
        if (which == 2) {
            // v: stage dim-major in smem, then write transposed rows to Vt.
            __nv_bfloat16* Vt = (__nv_bfloat16*)C2;
            __nv_bfloat16* st = (__nv_bfloat16*)smc;   // 128 dims x (128+8) tokens
            const int RSV = 136;
            #pragma unroll
            for (int mi = 0; mi < 4; mi++) {
                const int rl = wm * 64 + mi * 16 + (lane >> 2);
                #pragma unroll
                for (int nj = 0; nj < 8; nj++) {
                    const int c2 = wn * 64 + nj * 8 + 2 * (lane & 3);
                    st[(c2 + 0) * RSV + rl    ] = __float2bfloat16(acc[mi][nj][0]);
                    st[(c2 + 1) * RSV + rl    ] = __float2bfloat16(acc[mi][nj][1]);
                    st[(c2 + 0) * RSV + rl + 8] = __float2bfloat16(acc[mi][nj][2]);
                    st[(c2 + 1) * RSV + rl + 8] = __float2bfloat16(acc[mi][nj][3]);
                }
            }
            __syncthreads();
            const int d = tid;  // 0..127 local dim
            #pragma unroll
            for (int t8 = 0; t8 < 16; t8++) {
                *(uint4*)&Vt[(size_t)(cl + d) * BT + crow + t8 * 8] =
                    *(uint4*)&st[d * RSV + t8 * 8];
            }
        } else {
            __nv_bfloat16* Cb = which ? (__nv_bfloat16*)C1 : (__nv_bfloat16*)C0;
            const float extra = which ? 32.f : 256.f;
            float sc0[8], sc1[8];
            #pragma unroll
            for (int nj = 0; nj < 8; nj++) {
                const int c0 = cl + wn * 64 + nj * 8 + 2 * (lane & 3);
                sc0[nj] = scl[c0] * extra;
                sc1[nj] = scl[c0 + 1] * extra;
            }
            #pragma unroll
            for (int mi = 0; mi < 4; mi++) {
                const int r0 = crow + wm * 64 + mi * 16 + (lane >> 2);
                float ss0 = 0.f, ss1 = 0.f;
                #pragma unroll
                for (int nj = 0; nj < 8; nj++) {
                    ss0 += acc[mi][nj][0] * acc[mi][nj][0] + acc[mi][nj][1] * acc[mi][nj][1];
                    ss1 += acc[mi][nj][2] * acc[mi][nj][2] + acc[mi][nj][3] * acc[mi][nj][3];
                }
                ss0 += __shfl_xor_sync(0xffffffffu, ss0, 1);
                ss0 += __shfl_xor_sync(0xffffffffu, ss0, 2);
                ss1 += __shfl_xor_sync(0xffffffffu, ss1, 1);
                ss1 += __shfl_xor_sync(0xffffffffu, ss1, 2);
                const float rn0 = rsqrtf(ss0), rn1 = rsqrtf(ss1);
                #pragma unroll
                for (int nj = 0; nj < 8; nj++) {
                    const int c0 = cl + wn * 64 + nj * 8 + 2 * (lane & 3);
                    *(uint32_t*)&Cb[(size_t)r0 * 1024 + c0] =
                        cvt2bf(acc[mi][nj][0] * rn0 * sc0[nj], acc[mi][nj][1] * rn0 * sc1[nj]);
                    *(uint32_t*)&Cb[(size_t)(r0 + 8) * 1024 + c0] =
                        cvt2bf(acc[mi][nj][2] * rn1 * sc0[nj], acc[mi][nj][3] * rn1 * sc1[nj]);
                }
            }
        }
    } else {
        __nv_bfloat16* Cb = (__nv_bfloat16*)C0;
        #pragma unroll
        for (int mi = 0; mi < 4; mi++) {
            const int r0 = crow + wm * 64 + mi * 16 + (lane >> 2);
            #pragma unroll
            for (int nj = 0; nj < 8; nj++) {
                const int c0 = ccol + wn * 64 + nj * 8 + 2 * (lane & 3);
                *(uint32_t*)&Cb[(size_t)r0 * N + c0] =
                    cvt2bf(acc[mi][nj][0], acc[mi][nj][1]);
                *(uint32_t*)&Cb[(size_t)(r0 + 8) * N + c0] =
                    cvt2bf(acc[mi][nj][2], acc[mi][nj][3]);
            }
        }
    }
}

// ---------------------------------------------------------------------------
// Tensor-core flash attention (non-causal), D=64. (R11 winner, unchanged)
// ---------------------------------------------------------------------------
#define ATT_SMEM (16384 + 3 * 32768)

__global__ void __launch_bounds__(256) attn_tc_kernel(
    const __nv_bfloat16* __restrict__ q, const __nv_bfloat16* __restrict__ k,
    const __nv_bfloat16* __restrict__ vt, __nv_bfloat16* __restrict__ y)
{
    extern __shared__ char smc[];
    const int tid = threadIdx.x, lane = tid & 31, warp = tid >> 5;
    const int bh = blockIdx.y, b = bh >> 4, cb = (bh & 15) * 64;
    const int tq0 = b * 1024 + blockIdx.x * 128;
    const uint32_t sb = (uint32_t)__cvta_generic_to_shared(smc);
    const uint32_t qs = sb;

    #pragma unroll
    for (int i = 0; i < 4; i++) {
        int idx = tid + i * 256;
        int row = idx >> 3, c = idx & 7;
        uint32_t sw = (uint32_t)(row * 128 + ((c ^ (row & 7)) << 4));
        asm volatile("cp.async.cg.shared.global [%0], [%1], 16;"
                     :: "r"(qs + sw), "l"((const void*)(q + (size_t)(tq0 + row) * CDIM + cb + c * 8)));
    }
    asm volatile("cp.async.commit_group;");

    auto issueKV = [&](int kt, int buf) {
        const int tk0 = b * 1024 + kt * 128;
        const uint32_t kb_ = sb + 16384 + buf * 32768;
        const uint32_t vb_ = kb_ + 16384;
        #pragma unroll
        for (int i = 0; i < 4; i++) {
            int idx = tid + i * 256;
            int row = idx >> 3, c = idx & 7;
            uint32_t sw = (uint32_t)(row * 128 + ((c ^ (row & 7)) << 4));
            asm volatile("cp.async.cg.shared.global [%0], [%1], 16;"
                         :: "r"(kb_ + sw), "l"((const void*)(k + (size_t)(tk0 + row) * CDIM + cb + c * 8)));
            asm volatile("cp.async.cg.shared.global [%0], [%1], 16;"
                         :: "r"(vb_ + sw),
                            "l"((const void*)(vt + (size_t)(cb + (row & 63)) * BT + tk0 + (row >> 6) * 64 + c * 8)));
        }
    };

    issueKV(0, 0); asm volatile("cp.async.commit_group;");
    issueKV(1, 1); asm volatile("cp.async.commit_group;");

    asm volatile("cp.async.wait_group 2;");
    __syncthreads();

    const int arow = warp * 16 + (lane & 15);
    const int akb  = lane >> 4;
    const int lsw  = lane & 7;
    uint32_t aq[4][4];
    #pragma unroll
    for (int ks = 0; ks < 4; ks++) {
        uint32_t ad = qs + (uint32_t)arow * 128 + (uint32_t)(((2 * ks + akb) ^ lsw) << 4);
        asm volatile("ldmatrix.sync.aligned.m8n8.x4.shared.b16 {%0,%1,%2,%3}, [%4];"
                     : "=r"(aq[ks][0]), "=r"(aq[ks][1]), "=r"(aq[ks][2]), "=r"(aq[ks][3])
                     : "r"(ad));
    }

    float acc_o[8][4];
    #pragma unroll
    for (int j = 0; j < 8; j++)
        #pragma unroll
        for (int e = 0; e < 4; e++) acc_o[j][e] = 0.f;
    float m0 = -1e30f, m1 = -1e30f, l0 = 0.f, l1 = 0.f;

    const int brow = (lane & 7) + ((lane >> 4) << 3);
    const int bkb  = (lane >> 3) & 1;

    for (int kt = 0; kt < 8; kt++) {
        asm volatile("cp.async.wait_group 1;");
        __syncthreads();

        const uint32_t kb_ = sb + 16384 + (kt % 3) * 32768;
        const uint32_t vb_ = kb_ + 16384;

        float s[16][4];
        #pragma unroll
        for (int j = 0; j < 16; j++)
            #pragma unroll
            for (int e = 0; e < 4; e++) s[j][e] = 0.f;

        #pragma unroll
        for (int ks = 0; ks < 4; ks++) {
            const int bch = 2 * ks + bkb;
            #pragma unroll
            for (int nj2 = 0; nj2 < 8; nj2++) {
                uint32_t bk[4];
                uint32_t bd = kb_ + (uint32_t)(brow + nj2 * 16) * 128 +
                              (uint32_t)((bch ^ lsw) << 4);
                asm volatile("ldmatrix.sync.aligned.m8n8.x4.shared.b16 {%0,%1,%2,%3}, [%4];"
                             : "=r"(bk[0]), "=r"(bk[1]), "=r"(bk[2]), "=r"(bk[3]) : "r"(bd));
                asm volatile(
                    "mma.sync.aligned.m16n8k16.row.col.f32.bf16.bf16.f32 "
                    "{%0,%1,%2,%3}, {%4,%5,%6,%7}, {%8,%9}, {%0,%1,%2,%3};"
                    : "+f"(s[2 * nj2][0]), "+f"(s[2 * nj2][1]), "+f"(s[2 * nj2][2]), "+f"(s[2 * nj2][3])
                    : "r"(aq[ks][0]), "r"(aq[ks][1]), "r"(aq[ks][2]), "r"(aq[ks][3]),
                      "r"(bk[0]), "r"(bk[1]));
                asm volatile(
                    "mma.sync.aligned.m16n8k16.row.col.f32.bf16.bf16.f32 "
                    "{%0,%1,%2,%3}, {%4,%5,%6,%7}, {%8,%9}, {%0,%1,%2,%3};"
                    : "+f"(s[2 * nj2 + 1][0]), "+f"(s[2 * nj2 + 1][1]), "+f"(s[2 * nj2 + 1][2]), "+f"(s[2 * nj2 + 1][3])
                    : "r"(aq[ks][0]), "r"(aq[ks][1]), "r"(aq[ks][2]), "r"(aq[ks][3]),
                      "r"(bk[2]), "r"(bk[3]));
            }
        }

        float rm0 = -1e30f, rm1 = -1e30f;
        #pragma unroll
        for (int j = 0; j < 16; j++) {
            rm0 = fmaxf(rm0, fmaxf(s[j][0], s[j][1]));
            rm1 = fmaxf(rm1, fmaxf(s[j][2], s[j][3]));
        }
        rm0 = fmaxf(rm0, __shfl_xor_sync(0xffffffffu, rm0, 1));
        rm0 = fmaxf(rm0, __shfl_xor_sync(0xffffffffu, rm0, 2));
        rm1 = fmaxf(rm1, __shfl_xor_sync(0xffffffffu, rm1, 1));
        rm1 = fmaxf(rm1, __shfl_xor_sync(0xffffffffu, rm1, 2));
        float nm0 = fmaxf(m0, rm0), nm1 = fmaxf(m1, rm1);
        float co0 = __expf(m0 - nm0), co1 = __expf(m1 - nm1);
        float ls0 = 0.f, ls1 = 0.f;
        #pragma unroll
        for (int j = 0; j < 16; j++) {
            s[j][0] = __expf(s[j][0] - nm0); ls0 += s[j][0];
            s[j][1] = __expf(s[j][1] - nm0); ls0 += s[j][1];
            s[j][2] = __expf(s[j][2] - nm1); ls1 += s[j][2];
            s[j][3] = __expf(s[j][3] - nm1); ls1 += s[j][3];
        }
        ls0 += __shfl_xor_sync(0xffffffffu, ls0, 1);
        ls0 += __shfl_xor_sync(0xffffffffu, ls0, 2);
        ls1 += __shfl_xor_sync(0xffffffffu, ls1, 1);
        ls1 += __shfl_xor_sync(0xffffffffu, ls1, 2);
        l0 = l0 * co0 + ls0; l1 = l1 * co1 + ls1;
        m0 = nm0; m1 = nm1;
        #pragma unroll
        for (int j = 0; j < 8; j++) {
            acc_o[j][0] *= co0; acc_o[j][1] *= co0;
            acc_o[j][2] *= co1; acc_o[j][3] *= co1;
        }

        #pragma unroll
        for (int kp = 0; kp < 8; kp++) {
            uint32_t ap[4];
            ap[0] = cvt2bf(s[2 * kp][0],     s[2 * kp][1]);
            ap[1] = cvt2bf(s[2 * kp][2],     s[2 * kp][3]);
            ap[2] = cvt2bf(s[2 * kp + 1][0], s[2 * kp + 1][1]);
            ap[3] = cvt2bf(s[2 * kp + 1][2], s[2 * kp + 1][3]);
            const uint32_t vbase = vb_ + (uint32_t)((kp >> 2) * 8192);
            const int ach = 2 * (kp & 3) + bkb;
            #pragma unroll
            for (int dj2 = 0; dj2 < 4; dj2++) {
                uint32_t bv[4];
                uint32_t bd = vbase + (uint32_t)(brow + dj2 * 16) * 128 +
                              (uint32_t)((ach ^ lsw) << 4);
                asm volatile("ldmatrix.sync.aligned.m8n8.x4.shared.b16 {%0,%1,%2,%3}, [%4];"
                             : "=r"(bv[0]), "=r"(bv[1]), "=r"(bv[2]), "=r"(bv[3]) : "r"(bd));
                asm volatile(
                    "mma.sync.aligned.m16n8k16.row.col.f32.bf16.bf16.f32 "
                    "{%0,%1,%2,%3}, {%4,%5,%6,%7}, {%8,%9}, {%0,%1,%2,%3};"
                    : "+f"(acc_o[2 * dj2][0]), "+f"(acc_o[2 * dj2][1]), "+f"(acc_o[2 * dj2][2]), "+f"(acc_o[2 * dj2][3])
                    : "r"(ap[0]), "r"(ap[1]), "r"(ap[2]), "r"(ap[3]), "r"(bv[0]), "r"(bv[1]));
                asm volatile(
                    "mma.sync.aligned.m16n8k16.row.col.f32.bf16.bf16.f32 "
                    "{%0,%1,%2,%3}, {%4,%5,%6,%7}, {%8,%9}, {%0,%1,%2,%3};"
                    : "+f"(acc_o[2 * dj2 + 1][0]), "+f"(acc_o[2 * dj2 + 1][1]), "+f"(acc_o[2 * dj2 + 1][2]), "+f"(acc_o[2 * dj2 + 1][3])
                    : "r"(ap[0]), "r"(ap[1]), "r"(ap[2]), "r"(ap[3]), "r"(bv[2]), "r"(bv[3]));
            }
        }

        if (kt + 2 < 8) issueKV(kt + 2, (kt + 2) % 3);
        asm volatile("cp.async.commit_group;");
    }

    const float li0 = 1.f / l0, li1 = 1.f / l1;
    const int r0 = tq0 + warp * 16 + (lane >> 2);
    #pragma unroll
    for (int dj = 0; dj < 8; dj++) {
        const int c0 = cb + dj * 8 + 2 * (lane & 3);
        *(uint32_t*)&y[(size_t)r0 * CDIM + c0] =
            cvt2bf(acc_o[dj][0] * li0, acc_o[dj][1] * li0);
        *(uint32_t*)&y[(size_t)(r0 + 8) * CDIM + c0] =
            cvt2bf(acc_o[dj][2] * li1, acc_o[dj][3] * li1);
    }
}

// ---------------------------------------------------------------------------
// out = justnorm( justnorm(h) + |alpha*1.6| * (justnorm(hb) - justnorm(h)) )
// hb is bf16 (lr-damped branch).
// ---------------------------------------------------------------------------
__global__ void residual_kernel(const float* __restrict__ hin,
                                const __nv_bfloat162* __restrict__ hb,
                                const float* __restrict__ alpha, float* __restrict__ out,
                                uint32_t* __restrict__ outb)
{
    int t = blockIdx.x, tid = threadIdx.x;
    float4 a = ((const float4*)hin)[(size_t)t * 256 + tid];
    __nv_bfloat162 b0 = hb[((size_t)t * 256 + tid) * 2];
    __nv_bfloat162 b1 = hb[((size_t)t * 256 + tid) * 2 + 1];
    float4 b = make_float4(__bfloat162float(b0.x), __bfloat162float(b0.y),
                           __bfloat162float(b1.x), __bfloat162float(b1.y));
    float s1 = a.x * a.x + a.y * a.y + a.z * a.z + a.w * a.w;
    float s2 = b.x * b.x + b.y * b.y + b.z * b.z + b.w * b.w;
    #pragma unroll
    for (int off = 16; off >= 1; off >>= 1) {
        s1 += __shfl_xor_sync(0xffffffffu, s1, off);
        s2 += __shfl_xor_sync(0xffffffffu, s2, off);
    }
    __shared__ float red1[8], red2[8];
    int w = tid >> 5, lane = tid & 31;
    if (lane == 0) { red1[w] = s1; red2[w] = s2; }
    __syncthreads();
    float t1 = 0.f, t2 = 0.f;
    #pragma unroll
    for (int i = 0; i < 8; i++) { t1 += red1[i]; t2 += red2[i]; }
    float r1 = rsqrtf(t1), r2 = rsqrtf(t2);

    float4 al = ((const float4*)alpha)[tid];
    float4 u;
    u.x = a.x * r1 + fabsf(al.x * 1.6f) * (b.x * r2 - a.x * r1);
    u.y = a.y * r1 + fabsf(al.y * 1.6f) * (b.y * r2 - a.y * r1);
    u.z = a.z * r1 + fabsf(al.z * 1.6f) * (b.z * r2 - a.z * r1);
    u.w = a.w * r1 + fabsf(al.w * 1.6f) * (b.w * r2 - a.w * r1);

    float s3 = u.x * u.x + u.y * u.y + u.z * u.z + u.w * u.w;
    #pragma unroll
    for (int off = 16; off >= 1; off >>= 1) s3 += __shfl_xor_sync(0xffffffffu, s3, off);
    __syncthreads();
    if (lane == 0) red1[w] = s3;
    __syncthreads();
    float t3 = 0.f;
    #pragma unroll
    for (int i = 0; i < 8; i++) t3 += red1[i];
    float r3 = rsqrtf(t3);
    float4 o = make_float4(u.x * r3, u.y * r3, u.z * r3, u.w * r3);
    ((float4*)out)[(size_t)t * 256 + tid] = o;
    if (outb) {
        outb[((size_t)t * 256 + tid) * 2 + 0] = cvt2bf(o.x, o.y);
        outb[((size_t)t * 256 + tid) * 2 + 1] = cvt2bf(o.z, o.w);
    }
}

// ---------------------------------------------------------------------------
extern "C" void kernel_launch(void* const* d_in, const int* in_sizes, int n_in,
                              void* d_out, int out_size)
{
    (void)in_sizes; (void)n_in; (void)out_size;
    const float* h     = (const float*)d_in[0];
    const float* Wq    = (const float*)d_in[1];
    const float* Wk    = (const float*)d_in[2];
    const float* Wv    = (const float*)d_in[3];
    const float* Wo    = (const float*)d_in[4];
    const float* Wfc   = (const float*)d_in[5];
    const float* Wproj = (const float*)d_in[6];
    const float* sqk   = (const float*)d_in[7];
    const float* suv   = (const float*)d_in[8];
    const float* a_att = (const float*)d_in[9];
    const float* a_mlp = (const float*)d_in[10];
    float* out = (float*)d_out;

    float* buf = nullptr;
    cudaGetSymbolAddress((void**)&buf, g_buf);
    float* inv = buf + OFF_INV;
    float* h2  = buf + OFF_H2;
    __nv_bfloat16* t1B  = (__nv_bfloat16*)(buf + OFF_T1);
    __nv_bfloat16* hB   = (__nv_bfloat16*)(buf + OFF_HB);
    __nv_bfloat16* yB   = (__nv_bfloat16*)(buf + OFF_YB);
    __nv_bfloat16* h2B  = (__nv_bfloat16*)(buf + OFF_H2B);
    __nv_bfloat16* xB   = (__nv_bfloat16*)(buf + OFF_XB);
    __nv_bfloat16* WqB  = (__nv_bfloat16*)(buf + OFF_WQB);   // q,k,v contiguous
    __nv_bfloat16* WoB  = WqB + 3 * CDIM * CDIM;
    __nv_bfloat16* WfcP = (__nv_bfloat16*)(buf + OFF_WFCB);  // permuted
    __nv_bfloat16* WpjB = (__nv_bfloat16*)(buf + OFF_WPJB);
    __nv_bfloat16* qBf  = (__nv_bfloat16*)(buf + OFF_QBF);
    __nv_bfloat16* kBf  = (__nv_bfloat16*)(buf + OFF_KBF);
    __nv_bfloat16* VtG  = (__nv_bfloat16*)(buf + OFF_VT);

    cudaFuncSetAttribute(attn_tc_kernel, cudaFuncAttributeMaxDynamicSharedMemorySize, ATT_SMEM);
    cudaFuncSetAttribute(gemm_kernel<1>, cudaFuncAttributeMaxDynamicSharedMemorySize, GEMM_SMEM);
    cudaFuncSetAttribute(gemm_kernel<2>, cudaFuncAttributeMaxDynamicSharedMemorySize, GEMM_SMEM);
    cudaFuncSetAttribute(gemm_kernel<3>, cudaFuncAttributeMaxDynamicSharedMemorySize, GEMM_SMEM);

    // lazily-created side stream + fork/join events (host resources only;
    // identical captured work on every call)
    static cudaStream_t s2 = nullptr;
    static cudaEvent_t evF = nullptr, evJ = nullptr;
    if (!s2) {
        cudaStreamCreateWithFlags(&s2, cudaStreamNonBlocking);
        cudaEventCreateWithFlags(&evF, cudaEventDisableTiming);
        cudaEventCreateWithFlags(&evJ, cudaEventDisableTiming);
    }

    // ---- fork: MLP weight prep runs concurrently with the attention chain ----
    cudaEventRecord(evF, 0);
    cudaStreamWaitEvent(s2, evF, 0);
    wfc_perm_kernel<<<8 * CDIM * CDIM / 1024, 256, 0, s2>>>(Wfc, (uint32_t*)WfcP);
    conv_kernel<<<4 * CDIM * CDIM / 1024, 256, 0, s2>>>(Wproj, (uint32_t*)WpjB);
    cudaEventRecord(evJ, s2);

    // ---- main chain ----
    colnorm_kernel<<<dim3(32, 4), 256>>>(Wq, Wk, Wv, Wo, inv);
    wconv4_kernel<<<dim3(1024, 4), 256>>>(Wq, Wk, Wv, Wo, inv, (uint32_t*)WqB);
    conv_kernel<<<BT * CDIM / 1024, 256>>>(h, (uint32_t*)hB);

    // fused qkv projection + qk per-head norm + v transpose: all bf16 outputs
    gemm_kernel<2><<<dim3(24, BT / 128), 128, GEMM_SMEM>>>(hB, WqB, qBf, kBf, VtG, sqk, BT, 3 * CDIM, CDIM);

    attn_tc_kernel<<<dim3(8, 128), 256, ATT_SMEM>>>(qBf, kBf, VtG, yB);

    // o projection -> bf16 t1B
    gemm_kernel<1><<<dim3(8, BT / 128), 128, GEMM_SMEM>>>(yB, WoB, t1B, nullptr, nullptr, nullptr, BT, CDIM, CDIM);

    residual_kernel<<<BT, 256>>>(h, (const __nv_bfloat162*)t1B, a_att, h2, (uint32_t*)h2B);

    // join before fc (needs WfcP; proj needs WpjB)
    cudaStreamWaitEvent(0, evJ, 0);

    // MLP: fc + SwiGLU fused -> x bf16; proj -> bf16 t1B
    gemm_kernel<3><<<dim3(64, BT / 128), 128, GEMM_SMEM>>>(h2B, WfcP, xB, nullptr, nullptr, suv, BT, 8 * CDIM, CDIM);
    gemm_kernel<1><<<dim3(8, BT / 128), 128, GEMM_SMEM>>>(xB, WpjB, t1B, nullptr, nullptr, nullptr, BT, CDIM, 4 * CDIM);

    residual_kernel<<<BT, 256>>>(h2, (const __nv_bfloat162*)t1B, a_mlp, out, nullptr);
}

// round 15
// speedup vs baseline: 1.0426x; 1.0122x over previous
#include <cuda_runtime.h>
#include <cuda_bf16.h>
#include <math.h>
#include <stdint.h>

// nGPT block: B=8, T=1024, C=1024, H=16, D=64
#define BT   8192
#define CDIM 1024

// ---- scratch carve (float units) ----
#define OFF_INV  0
#define OFF_T1   4096                         // bf16 t1 [token][dim]
#define OFF_H2   (OFF_T1  + BT*CDIM)
#define OFF_HB   (OFF_H2  + BT*CDIM)
#define OFF_YB   (OFF_HB  + BT*CDIM/2)
#define OFF_H2B  (OFF_YB  + BT*CDIM/2)
#define OFF_XB   (OFF_H2B + BT*CDIM/2)        // 8192x4096 bf16
#define OFF_WQB  (OFF_XB  + BT*4*CDIM/2)      // Wq,Wk,Wv,Wo bf16 contiguous
#define OFF_WFCB (OFF_WQB + 4*CDIM*CDIM/2)    // permuted Wfc bf16
#define OFF_WPJB (OFF_WFCB + 8*CDIM*CDIM/2)
#define OFF_QBF  (OFF_WPJB + 4*CDIM*CDIM/2)   // bf16 q [token][dim]
#define OFF_KBF  (OFF_QBF + BT*CDIM/2)        // bf16 k
#define OFF_VT   (OFF_KBF + BT*CDIM/2)        // bf16 V^T [dim][token]
#define BUF_TOTAL (OFF_VT + BT*CDIM/2)

__device__ float g_buf[BUF_TOTAL];

__device__ __forceinline__ uint32_t cvt2bf(float lo, float hi) {
    uint32_t r;
    asm("cvt.rn.bf16x2.f32 %0, %1, %2;" : "=r"(r) : "f"(hi), "f"(lo));
    return r;
}

// ---------------------------------------------------------------------------
// inverse column norms of W [C,C] row-major: inv[k] = 1/||W[:,k]||
// ---------------------------------------------------------------------------
__global__ void colnorm_kernel(const float* __restrict__ Wq, const float* __restrict__ Wk,
                               const float* __restrict__ Wv, const float* __restrict__ Wo,
                               float* __restrict__ inv)
{
    int m = blockIdx.y;
    const float* W = (m == 0) ? Wq : (m == 1) ? Wk : (m == 2) ? Wv : Wo;
    int tx = threadIdx.x & 31;
    int ty = threadIdx.x >> 5;
    int col = blockIdx.x * 32 + tx;
    float s = 0.f;
    for (int i = ty; i < CDIM; i += 8) {
        float w = W[i * CDIM + col];
        s += w * w;
    }
    __shared__ float sm[8][32];
    sm[ty][tx] = s;
    __syncthreads();
    if (ty == 0) {
        float tot = 0.f;
        #pragma unroll
        for (int r = 0; r < 8; r++) tot += sm[r][tx];
        inv[m * CDIM + col] = rsqrtf(tot);
    }
}

// ---------------------------------------------------------------------------
// Weight conversion with folded column norms (4 matrices)
// ---------------------------------------------------------------------------
__global__ void wconv4_kernel(const float* __restrict__ Wq, const float* __restrict__ Wk,
                              const float* __restrict__ Wv, const float* __restrict__ Wo,
                              const float* __restrict__ inv, uint32_t* __restrict__ dst)
{
    int m = blockIdx.y;
    const float* W = (m == 0) ? Wq : (m == 1) ? Wk : (m == 2) ? Wv : Wo;
    int idx = blockIdx.x * 256 + threadIdx.x;
    float4 w = ((const float4*)W)[idx];
    float4 s = ((const float4*)(inv + m * CDIM))[idx & 255];
    uint32_t* d = dst + (size_t)m * (CDIM * CDIM / 2) + idx * 2;
    d[0] = cvt2bf(w.x * s.x, w.y * s.y);
    d[1] = cvt2bf(w.z * s.z, w.w * s.w);
}

__global__ void conv_kernel(const float* __restrict__ src, uint32_t* __restrict__ dst)
{
    int idx = blockIdx.x * 256 + threadIdx.x;
    float4 v = ((const float4*)src)[idx];
    dst[idx * 2 + 0] = cvt2bf(v.x, v.y);
    dst[idx * 2 + 1] = cvt2bf(v.z, v.w);
}

// ---------------------------------------------------------------------------
// Wfc conversion with row permutation for fused SwiGLU
// ---------------------------------------------------------------------------
__global__ void wfc_perm_kernel(const float* __restrict__ Wfc, uint32_t* __restrict__ dst)
{
    int idx = blockIdx.x * 256 + threadIdx.x;
    int r = idx >> 8, c4 = idx & 255;
    int b = r >> 4, w = r & 15;
    int src_r = (w < 8) ? (b * 8 + w) : (4096 + b * 8 + (w - 8));
    float4 v = ((const float4*)Wfc)[(size_t)src_r * 256 + c4];
    dst[(size_t)idx * 2 + 0] = cvt2bf(v.x, v.y);
    dst[(size_t)idx * 2 + 1] = cvt2bf(v.z, v.w);
}

// ---------------------------------------------------------------------------
// bf16 mma.sync GEMM NT (R9/R11 winning shape): 128x128x64, 3-stage cp.async,
// 4 warps, warp tile 64x64, 128 threads, 2 CTAs/SM.
// MODE 1: bf16 out.
// MODE 2: fused qkv: q,k -> per-head normalized bf16; v -> TRANSPOSED bf16
//         written directly into Vt [dim][token] via smem staging.
// MODE 3: fused SwiGLU (permuted Wfc) -> x bf16 [M,4096].
// ---------------------------------------------------------------------------
#define STAGES 3
#define GEMM_SMEM (STAGES * 32768)

template <int MODE>
__global__ void __launch_bounds__(128, 2) gemm_kernel(
    const __nv_bfloat16* __restrict__ A, const __nv_bfloat16* __restrict__ B,
    void* __restrict__ C0, void* __restrict__ C1, void* __restrict__ C2,
    const float* __restrict__ scl,
    int M, int N, int K)
{
    extern __shared__ char smc[];
    const int tid = threadIdx.x, lane = tid & 31, warp = tid >> 5;
    const int wm = warp & 1, wn = warp >> 1;
    const int crow = blockIdx.y * 128, ccol = blockIdx.x * 128;
    const uint32_t sbase = (uint32_t)__cvta_generic_to_shared(smc);

    const __nv_bfloat16* Ag = A + (size_t)crow * K;
    const __nv_bfloat16* Bg = B + (size_t)ccol * K;

    auto issue = [&](int t, int buf) {
        const uint32_t abase = sbase + buf * 32768;
        const uint32_t bbase = abase + 16384;
        const int k0 = t * 64;
        #pragma unroll
        for (int i = 0; i < 8; i++) {
            int idx = tid + i * 128;
            int row = idx >> 3, c = idx & 7;
            uint32_t sw = (uint32_t)(row * 128 + ((c ^ (row & 7)) << 4));
            asm volatile("cp.async.cg.shared.global [%0], [%1], 16;"
                         :: "r"(abase + sw), "l"((const void*)(Ag + (size_t)row * K + k0 + c * 8)));
            asm volatile("cp.async.cg.shared.global [%0], [%1], 16;"
                         :: "r"(bbase + sw), "l"((const void*)(Bg + (size_t)row * K + k0 + c * 8)));
        }
    };

    float acc[4][8][4];
    #pragma unroll
    for (int i = 0; i < 4; i++)
        #pragma unroll
        for (int j = 0; j < 8; j++)
            #pragma unroll
            for (int e = 0; e < 4; e++) acc[i][j][e] = 0.f;

    const int nt = K / 64;

    issue(0, 0); asm volatile("cp.async.commit_group;");
    issue(1, 1); asm volatile("cp.async.commit_group;");

    const int arow0 = wm * 64 + (lane & 15);
    const int akb   = lane >> 4;
    const int asw   = lane & 7;
    const int brow0 = wn * 64 + (lane & 7) + ((lane >> 4) << 3);
    const int bkb   = (lane >> 3) & 1;

    for (int t = 0; t < nt; t++) {
        asm volatile("cp.async.wait_group 1;");
        __syncthreads();
        // NOTE: this top-of-loop barrier also orders the previous iteration's
        // compute (reads of buffer (t-1)%3) before the issue below overwrites
        // it — the former trailing barrier was redundant and is removed.

        if (t + 2 < nt) {
            issue(t + 2, (t + 2) % STAGES);
        }
        asm volatile("cp.async.commit_group;");

        const int buf = t % STAGES;
        const uint32_t abase = sbase + buf * 32768;
        const uint32_t bbase = abase + 16384;

        #pragma unroll
        for (int ks = 0; ks < 4; ks++) {
            uint32_t a[4][4], br[4][4];
            const int ach = 2 * ks + akb;
            const int bch = 2 * ks + bkb;
            #pragma unroll
            for (int mi = 0; mi < 4; mi++) {
                uint32_t ad = abase + (uint32_t)(arow0 + mi * 16) * 128 +
                              (uint32_t)((ach ^ asw) << 4);
                asm volatile("ldmatrix.sync.aligned.m8n8.x4.shared.b16 {%0,%1,%2,%3}, [%4];"
                             : "=r"(a[mi][0]), "=r"(a[mi][1]), "=r"(a[mi][2]), "=r"(a[mi][3])
                             : "r"(ad));
            }
            #pragma unroll
            for (int nj2 = 0; nj2 < 4; nj2++) {
                uint32_t bd = bbase + (uint32_t)(brow0 + nj2 * 16) * 128 +
                              (uint32_t)((bch ^ asw) << 4);
                asm volatile("ldmatrix.sync.aligned.m8n8.x4.shared.b16 {%0,%1,%2,%3}, [%4];"
                             : "=r"(br[nj2][0]), "=r"(br[nj2][1]), "=r"(br[nj2][2]), "=r"(br[nj2][3])
                             : "r"(bd));
            }
            #pragma unroll
            for (int mi = 0; mi < 4; mi++)
                #pragma unroll
                for (int nj = 0; nj < 8; nj++) {
                    uint32_t b0 = br[nj >> 1][(nj & 1) * 2];
                    uint32_t b1 = br[nj >> 1][(nj & 1) * 2 + 1];
                    asm volatile(
                        "mma.sync.aligned.m16n8k16.row.col.f32.bf16.bf16.f32 "
                        "{%0,%1,%2,%3}, {%4,%5,%6,%7}, {%8,%9}, {%0,%1,%2,%3};"
                        : "+f"(acc[mi][nj][0]), "+f"(acc[mi][nj][1]),
                          "+f"(acc[mi][nj][2]), "+f"(acc[mi][nj][3])
                        : "r"(a[mi][0]), "r"(a[mi][1]), "r"(a[mi][2]), "r"(a[mi][3]),
                          "r"(b0), "r"(b1));
                }
        }
    }
    __syncthreads();   // mainloop done; smem free for epilogue staging

    // ---- epilogue ----
    if (MODE == 3) {
        const int xc0 = blockIdx.x * 64;
        __nv_bfloat16* Xb = (__nv_bfloat16*)C0;
        #pragma unroll
        for (int p = 0; p < 4; p++) {
            const int cb = xc0 + (wn * 4 + p) * 8 + 2 * (lane & 3);
            const float su0 = scl[cb] * 32.f,        su1 = scl[cb + 1] * 32.f;
            const float sg0 = scl[4096 + cb] * 32.f, sg1 = scl[4096 + cb + 1] * 32.f;
            #pragma unroll
            for (int mi = 0; mi < 4; mi++) {
                const int r0 = crow + wm * 64 + mi * 16 + (lane >> 2);
                float g, x0, x1;
                g = acc[mi][2 * p + 1][0] * sg0; x0 = (acc[mi][2 * p][0] * su0) * g / (1.f + __expf(-g));
                g = acc[mi][2 * p + 1][1] * sg1; x1 = (acc[mi][2 * p][1] * su1) * g / (1.f + __expf(-g));
                *(uint32_t*)&Xb[(size_t)r0 * 4096 + cb] = cvt2bf(x0, x1);
                g = acc[mi][2 * p + 1][2] * sg0; x0 = (acc[mi][2 * p][2] * su0) * g / (1.f + __expf(-g));
                g = acc[mi][2 * p + 1][3] * sg1; x1 = (acc[mi][2 * p][3] * su1) * g / (1.f + __expf(-g));
                *(uint32_t*)&Xb[(size_t)(r0 + 8) * 4096 + cb] = cvt2bf(x0, x1);
            }
        }
    } else if (MODE == 2) {
        const int which = ccol >> 10;        // 0=q,1=k,2=v
        const int cl = ccol & 1023;
        if (which == 2) {
            // v: stage dim-major in smem, then write transposed rows to Vt.
            __nv_bfloat16* Vt = (__nv_bfloat16*)C2;
            __nv_bfloat16* st = (__nv_bfloat16*)smc;   // 128 dims x (128+8) tokens
            const int RSV = 136;
            #pragma unroll
            for (int mi = 0; mi < 4; mi++) {
                const int rl = wm * 64 + mi * 16 + (lane >> 2);
                #pragma unroll
                for (int nj = 0; nj < 8; nj++) {
                    const int c2 = wn * 64 + nj * 8 + 2 * (lane & 3);
                    st[(c2 + 0) * RSV + rl    ] = __float2bfloat16(acc[mi][nj][0]);
                    st[(c2 + 1) * RSV + rl    ] = __float2bfloat16(acc[mi][nj][1]);
                    st[(c2 + 0) * RSV + rl + 8] = __float2bfloat16(acc[mi][nj][2]);
                    st[(c2 + 1) * RSV + rl + 8] = __float2bfloat16(acc[mi][nj][3]);
                }
            }
            __syncthreads();
            const int d = tid;  // 0..127 local dim
            #pragma unroll
            for (int t8 = 0; t8 < 16; t8++) {
                *(uint4*)&Vt[(size_t)(cl + d) * BT + crow + t8 * 8] =
                    *(uint4*)&st[d * RSV + t8 * 8];
            }
        } else {
            __nv_bfloat16* Cb = which ? (__nv_bfloat16*)C1 : (__nv_bfloat16*)C0;
            const float extra = which ? 32.f : 256.f;
            float sc0[8], sc1[8];
            #pragma unroll
            for (int nj = 0; nj < 8; nj++) {
                const int c0 = cl + wn * 64 + nj * 8 + 2 * (lane & 3);
                sc0[nj] = scl[c0] * extra;
                sc1[nj] = scl[c0 + 1] * extra;
            }
            #pragma unroll
            for (int mi = 0; mi < 4; mi++) {
                const int r0 = crow + wm * 64 + mi * 16 + (lane >> 2);
                float ss0 = 0.f, ss1 = 0.f;
                #pragma unroll
                for (int nj = 0; nj < 8; nj++) {
                    ss0 += acc[mi][nj][0] * acc[mi][nj][0] + acc[mi][nj][1] * acc[mi][nj][1];
                    ss1 += acc[mi][nj][2] * acc[mi][nj][2] + acc[mi][nj][3] * acc[mi][nj][3];
                }
                ss0 += __shfl_xor_sync(0xffffffffu, ss0, 1);
                ss0 += __shfl_xor_sync(0xffffffffu, ss0, 2);
                ss1 += __shfl_xor_sync(0xffffffffu, ss1, 1);
                ss1 += __shfl_xor_sync(0xffffffffu, ss1, 2);
                const float rn0 = rsqrtf(ss0), rn1 = rsqrtf(ss1);
                #pragma unroll
                for (int nj = 0; nj < 8; nj++) {
                    const int c0 = cl + wn * 64 + nj * 8 + 2 * (lane & 3);
                    *(uint32_t*)&Cb[(size_t)r0 * 1024 + c0] =
                        cvt2bf(acc[mi][nj][0] * rn0 * sc0[nj], acc[mi][nj][1] * rn0 * sc1[nj]);
                    *(uint32_t*)&Cb[(size_t)(r0 + 8) * 1024 + c0] =
                        cvt2bf(acc[mi][nj][2] * rn1 * sc0[nj], acc[mi][nj][3] * rn1 * sc1[nj]);
                }
            }
        }
    } else {
        __nv_bfloat16* Cb = (__nv_bfloat16*)C0;
        #pragma unroll
        for (int mi = 0; mi < 4; mi++) {
            const int r0 = crow + wm * 64 + mi * 16 + (lane >> 2);
            #pragma unroll
            for (int nj = 0; nj < 8; nj++) {
                const int c0 = ccol + wn * 64 + nj * 8 + 2 * (lane & 3);
                *(uint32_t*)&Cb[(size_t)r0 * N + c0] =
                    cvt2bf(acc[mi][nj][0], acc[mi][nj][1]);
                *(uint32_t*)&Cb[(size_t)(r0 + 8) * N + c0] =
                    cvt2bf(acc[mi][nj][2], acc[mi][nj][3]);
            }
        }
    }
}

// ---------------------------------------------------------------------------
// Tensor-core flash attention (non-causal), D=64. (R11 winner, unchanged)
// ---------------------------------------------------------------------------
#define ATT_SMEM (16384 + 3 * 32768)

__global__ void __launch_bounds__(256) attn_tc_kernel(
    const __nv_bfloat16* __restrict__ q, const __nv_bfloat16* __restrict__ k,
    const __nv_bfloat16* __restrict__ vt, __nv_bfloat16* __restrict__ y)
{
    extern __shared__ char smc[];
    const int tid = threadIdx.x, lane = tid & 31, warp = tid >> 5;
    const int bh = blockIdx.y, b = bh >> 4, cb = (bh & 15) * 64;
    const int tq0 = b * 1024 + blockIdx.x * 128;
    const uint32_t sb = (uint32_t)__cvta_generic_to_shared(smc);
    const uint32_t qs = sb;

    #pragma unroll
    for (int i = 0; i < 4; i++) {
        int idx = tid + i * 256;
        int row = idx >> 3, c = idx & 7;
        uint32_t sw = (uint32_t)(row * 128 + ((c ^ (row & 7)) << 4));
        asm volatile("cp.async.cg.shared.global [%0], [%1], 16;"
                     :: "r"(qs + sw), "l"((const void*)(q + (size_t)(tq0 + row) * CDIM + cb + c * 8)));
    }
    asm volatile("cp.async.commit_group;");

    auto issueKV = [&](int kt, int buf) {
        const int tk0 = b * 1024 + kt * 128;
        const uint32_t kb_ = sb + 16384 + buf * 32768;
        const uint32_t vb_ = kb_ + 16384;
        #pragma unroll
        for (int i = 0; i < 4; i++) {
            int idx = tid + i * 256;
            int row = idx >> 3, c = idx & 7;
            uint32_t sw = (uint32_t)(row * 128 + ((c ^ (row & 7)) << 4));
            asm volatile("cp.async.cg.shared.global [%0], [%1], 16;"
                         :: "r"(kb_ + sw), "l"((const void*)(k + (size_t)(tk0 + row) * CDIM + cb + c * 8)));
            asm volatile("cp.async.cg.shared.global [%0], [%1], 16;"
                         :: "r"(vb_ + sw),
                            "l"((const void*)(vt + (size_t)(cb + (row & 63)) * BT + tk0 + (row >> 6) * 64 + c * 8)));
        }
    };

    issueKV(0, 0); asm volatile("cp.async.commit_group;");
    issueKV(1, 1); asm volatile("cp.async.commit_group;");

    asm volatile("cp.async.wait_group 2;");
    __syncthreads();

    const int arow = warp * 16 + (lane & 15);
    const int akb  = lane >> 4;
    const int lsw  = lane & 7;
    uint32_t aq[4][4];
    #pragma unroll
    for (int ks = 0; ks < 4; ks++) {
        uint32_t ad = qs + (uint32_t)arow * 128 + (uint32_t)(((2 * ks + akb) ^ lsw) << 4);
        asm volatile("ldmatrix.sync.aligned.m8n8.x4.shared.b16 {%0,%1,%2,%3}, [%4];"
                     : "=r"(aq[ks][0]), "=r"(aq[ks][1]), "=r"(aq[ks][2]), "=r"(aq[ks][3])
                     : "r"(ad));
    }

    float acc_o[8][4];
    #pragma unroll
    for (int j = 0; j < 8; j++)
        #pragma unroll
        for (int e = 0; e < 4; e++) acc_o[j][e] = 0.f;
    float m0 = -1e30f, m1 = -1e30f, l0 = 0.f, l1 = 0.f;

    const int brow = (lane & 7) + ((lane >> 4) << 3);
    const int bkb  = (lane >> 3) & 1;

    for (int kt = 0; kt < 8; kt++) {
        asm volatile("cp.async.wait_group 1;");
        __syncthreads();

        const uint32_t kb_ = sb + 16384 + (kt % 3) * 32768;
        const uint32_t vb_ = kb_ + 16384;

        float s[16][4];
        #pragma unroll
        for (int j = 0; j < 16; j++)
            #pragma unroll
            for (int e = 0; e < 4; e++) s[j][e] = 0.f;

        #pragma unroll
        for (int ks = 0; ks < 4; ks++) {
            const int bch = 2 * ks + bkb;
            #pragma unroll
            for (int nj2 = 0; nj2 < 8; nj2++) {
                uint32_t bk[4];
                uint32_t bd = kb_ + (uint32_t)(brow + nj2 * 16) * 128 +
                              (uint32_t)((bch ^ lsw) << 4);
                asm volatile("ldmatrix.sync.aligned.m8n8.x4.shared.b16 {%0,%1,%2,%3}, [%4];"
                             : "=r"(bk[0]), "=r"(bk[1]), "=r"(bk[2]), "=r"(bk[3]) : "r"(bd));
                asm volatile(
                    "mma.sync.aligned.m16n8k16.row.col.f32.bf16.bf16.f32 "
                    "{%0,%1,%2,%3}, {%4,%5,%6,%7}, {%8,%9}, {%0,%1,%2,%3};"
                    : "+f"(s[2 * nj2][0]), "+f"(s[2 * nj2][1]), "+f"(s[2 * nj2][2]), "+f"(s[2 * nj2][3])
                    : "r"(aq[ks][0]), "r"(aq[ks][1]), "r"(aq[ks][2]), "r"(aq[ks][3]),
                      "r"(bk[0]), "r"(bk[1]));
                asm volatile(
                    "mma.sync.aligned.m16n8k16.row.col.f32.bf16.bf16.f32 "
                    "{%0,%1,%2,%3}, {%4,%5,%6,%7}, {%8,%9}, {%0,%1,%2,%3};"
                    : "+f"(s[2 * nj2 + 1][0]), "+f"(s[2 * nj2 + 1][1]), "+f"(s[2 * nj2 + 1][2]), "+f"(s[2 * nj2 + 1][3])
                    : "r"(aq[ks][0]), "r"(aq[ks][1]), "r"(aq[ks][2]), "r"(aq[ks][3]),
                      "r"(bk[2]), "r"(bk[3]));
            }
        }

        float rm0 = -1e30f, rm1 = -1e30f;
        #pragma unroll
        for (int j = 0; j < 16; j++) {
            rm0 = fmaxf(rm0, fmaxf(s[j][0], s[j][1]));
            rm1 = fmaxf(rm1, fmaxf(s[j][2], s[j][3]));
        }
        rm0 = fmaxf(rm0, __shfl_xor_sync(0xffffffffu, rm0, 1));
        rm0 = fmaxf(rm0, __shfl_xor_sync(0xffffffffu, rm0, 2));
        rm1 = fmaxf(rm1, __shfl_xor_sync(0xffffffffu, rm1, 1));
        rm1 = fmaxf(rm1, __shfl_xor_sync(0xffffffffu, rm1, 2));
        float nm0 = fmaxf(m0, rm0), nm1 = fmaxf(m1, rm1);
        float co0 = __expf(m0 - nm0), co1 = __expf(m1 - nm1);
        float ls0 = 0.f, ls1 = 0.f;
        #pragma unroll
        for (int j = 0; j < 16; j++) {
            s[j][0] = __expf(s[j][0] - nm0); ls0 += s[j][0];
            s[j][1] = __expf(s[j][1] - nm0); ls0 += s[j][1];
            s[j][2] = __expf(s[j][2] - nm1); ls1 += s[j][2];
            s[j][3] = __expf(s[j][3] - nm1); ls1 += s[j][3];
        }
        ls0 += __shfl_xor_sync(0xffffffffu, ls0, 1);
        ls0 += __shfl_xor_sync(0xffffffffu, ls0, 2);
        ls1 += __shfl_xor_sync(0xffffffffu, ls1, 1);
        ls1 += __shfl_xor_sync(0xffffffffu, ls1, 2);
        l0 = l0 * co0 + ls0; l1 = l1 * co1 + ls1;
        m0 = nm0; m1 = nm1;
        #pragma unroll
        for (int j = 0; j < 8; j++) {
            acc_o[j][0] *= co0; acc_o[j][1] *= co0;
            acc_o[j][2] *= co1; acc_o[j][3] *= co1;
        }

        #pragma unroll
        for (int kp = 0; kp < 8; kp++) {
            uint32_t ap[4];
            ap[0] = cvt2bf(s[2 * kp][0],     s[2 * kp][1]);
            ap[1] = cvt2bf(s[2 * kp][2],     s[2 * kp][3]);
            ap[2] = cvt2bf(s[2 * kp + 1][0], s[2 * kp + 1][1]);
            ap[3] = cvt2bf(s[2 * kp + 1][2], s[2 * kp + 1][3]);
            const uint32_t vbase = vb_ + (uint32_t)((kp >> 2) * 8192);
            const int ach = 2 * (kp & 3) + bkb;
            #pragma unroll
            for (int dj2 = 0; dj2 < 4; dj2++) {
                uint32_t bv[4];
                uint32_t bd = vbase + (uint32_t)(brow + dj2 * 16) * 128 +
                              (uint32_t)((ach ^ lsw) << 4);
                asm volatile("ldmatrix.sync.aligned.m8n8.x4.shared.b16 {%0,%1,%2,%3}, [%4];"
                             : "=r"(bv[0]), "=r"(bv[1]), "=r"(bv[2]), "=r"(bv[3]) : "r"(bd));
                asm volatile(
                    "mma.sync.aligned.m16n8k16.row.col.f32.bf16.bf16.f32 "
                    "{%0,%1,%2,%3}, {%4,%5,%6,%7}, {%8,%9}, {%0,%1,%2,%3};"
                    : "+f"(acc_o[2 * dj2][0]), "+f"(acc_o[2 * dj2][1]), "+f"(acc_o[2 * dj2][2]), "+f"(acc_o[2 * dj2][3])
                    : "r"(ap[0]), "r"(ap[1]), "r"(ap[2]), "r"(ap[3]), "r"(bv[0]), "r"(bv[1]));
                asm volatile(
                    "mma.sync.aligned.m16n8k16.row.col.f32.bf16.bf16.f32 "
                    "{%0,%1,%2,%3}, {%4,%5,%6,%7}, {%8,%9}, {%0,%1,%2,%3};"
                    : "+f"(acc_o[2 * dj2 + 1][0]), "+f"(acc_o[2 * dj2 + 1][1]), "+f"(acc_o[2 * dj2 + 1][2]), "+f"(acc_o[2 * dj2 + 1][3])
                    : "r"(ap[0]), "r"(ap[1]), "r"(ap[2]), "r"(ap[3]), "r"(bv[2]), "r"(bv[3]));
            }
        }

        if (kt + 2 < 8) issueKV(kt + 2, (kt + 2) % 3);
        asm volatile("cp.async.commit_group;");
    }

    const float li0 = 1.f / l0, li1 = 1.f / l1;
    const int r0 = tq0 + warp * 16 + (lane >> 2);
    #pragma unroll
    for (int dj = 0; dj < 8; dj++) {
        const int c0 = cb + dj * 8 + 2 * (lane & 3);
        *(uint32_t*)&y[(size_t)r0 * CDIM + c0] =
            cvt2bf(acc_o[dj][0] * li0, acc_o[dj][1] * li0);
        *(uint32_t*)&y[(size_t)(r0 + 8) * CDIM + c0] =
            cvt2bf(acc_o[dj][2] * li1, acc_o[dj][3] * li1);
    }
}

// ---------------------------------------------------------------------------
// out = justnorm( justnorm(h) + |alpha*1.6| * (justnorm(hb) - justnorm(h)) )
// hb is bf16 (lr-damped branch).
// ---------------------------------------------------------------------------
__global__ void residual_kernel(const float* __restrict__ hin,
                                const __nv_bfloat162* __restrict__ hb,
                                const float* __restrict__ alpha, float* __restrict__ out,
                                uint32_t* __restrict__ outb)
{
    int t = blockIdx.x, tid = threadIdx.x;
    float4 a = ((const float4*)hin)[(size_t)t * 256 + tid];
    __nv_bfloat162 b0 = hb[((size_t)t * 256 + tid) * 2];
    __nv_bfloat162 b1 = hb[((size_t)t * 256 + tid) * 2 + 1];
    float4 b = make_float4(__bfloat162float(b0.x), __bfloat162float(b0.y),
                           __bfloat162float(b1.x), __bfloat162float(b1.y));
    float s1 = a.x * a.x + a.y * a.y + a.z * a.z + a.w * a.w;
    float s2 = b.x * b.x + b.y * b.y + b.z * b.z + b.w * b.w;
    #pragma unroll
    for (int off = 16; off >= 1; off >>= 1) {
        s1 += __shfl_xor_sync(0xffffffffu, s1, off);
        s2 += __shfl_xor_sync(0xffffffffu, s2, off);
    }
    __shared__ float red1[8], red2[8];
    int w = tid >> 5, lane = tid & 31;
    if (lane == 0) { red1[w] = s1; red2[w] = s2; }
    __syncthreads();
    float t1 = 0.f, t2 = 0.f;
    #pragma unroll
    for (int i = 0; i < 8; i++) { t1 += red1[i]; t2 += red2[i]; }
    float r1 = rsqrtf(t1), r2 = rsqrtf(t2);

    float4 al = ((const float4*)alpha)[tid];
    float4 u;
    u.x = a.x * r1 + fabsf(al.x * 1.6f) * (b.x * r2 - a.x * r1);
    u.y = a.y * r1 + fabsf(al.y * 1.6f) * (b.y * r2 - a.y * r1);
    u.z = a.z * r1 + fabsf(al.z * 1.6f) * (b.z * r2 - a.z * r1);
    u.w = a.w * r1 + fabsf(al.w * 1.6f) * (b.w * r2 - a.w * r1);

    float s3 = u.x * u.x + u.y * u.y + u.z * u.z + u.w * u.w;
    #pragma unroll
    for (int off = 16; off >= 1; off >>= 1) s3 += __shfl_xor_sync(0xffffffffu, s3, off);
    __syncthreads();
    if (lane == 0) red1[w] = s3;
    __syncthreads();
    float t3 = 0.f;
    #pragma unroll
    for (int i = 0; i < 8; i++) t3 += red1[i];
    float r3 = rsqrtf(t3);
    float4 o = make_float4(u.x * r3, u.y * r3, u.z * r3, u.w * r3);
    ((float4*)out)[(size_t)t * 256 + tid] = o;
    if (outb) {
        outb[((size_t)t * 256 + tid) * 2 + 0] = cvt2bf(o.x, o.y);
        outb[((size_t)t * 256 + tid) * 2 + 1] = cvt2bf(o.z, o.w);
    }
}

// ---------------------------------------------------------------------------
extern "C" void kernel_launch(void* const* d_in, const int* in_sizes, int n_in,
                              void* d_out, int out_size)
{
    (void)in_sizes; (void)n_in; (void)out_size;
    const float* h     = (const float*)d_in[0];
    const float* Wq    = (const float*)d_in[1];
    const float* Wk    = (const float*)d_in[2];
    const float* Wv    = (const float*)d_in[3];
    const float* Wo    = (const float*)d_in[4];
    const float* Wfc   = (const float*)d_in[5];
    const float* Wproj = (const float*)d_in[6];
    const float* sqk   = (const float*)d_in[7];
    const float* suv   = (const float*)d_in[8];
    const float* a_att = (const float*)d_in[9];
    const float* a_mlp = (const float*)d_in[10];
    float* out = (float*)d_out;

    float* buf = nullptr;
    cudaGetSymbolAddress((void**)&buf, g_buf);
    float* inv = buf + OFF_INV;
    float* h2  = buf + OFF_H2;
    __nv_bfloat16* t1B  = (__nv_bfloat16*)(buf + OFF_T1);
    __nv_bfloat16* hB   = (__nv_bfloat16*)(buf + OFF_HB);
    __nv_bfloat16* yB   = (__nv_bfloat16*)(buf + OFF_YB);
    __nv_bfloat16* h2B  = (__nv_bfloat16*)(buf + OFF_H2B);
    __nv_bfloat16* xB   = (__nv_bfloat16*)(buf + OFF_XB);
    __nv_bfloat16* WqB  = (__nv_bfloat16*)(buf + OFF_WQB);   // q,k,v contiguous
    __nv_bfloat16* WoB  = WqB + 3 * CDIM * CDIM;
    __nv_bfloat16* WfcP = (__nv_bfloat16*)(buf + OFF_WFCB);  // permuted
    __nv_bfloat16* WpjB = (__nv_bfloat16*)(buf + OFF_WPJB);
    __nv_bfloat16* qBf  = (__nv_bfloat16*)(buf + OFF_QBF);
    __nv_bfloat16* kBf  = (__nv_bfloat16*)(buf + OFF_KBF);
    __nv_bfloat16* VtG  = (__nv_bfloat16*)(buf + OFF_VT);

    cudaFuncSetAttribute(attn_tc_kernel, cudaFuncAttributeMaxDynamicSharedMemorySize, ATT_SMEM);
    cudaFuncSetAttribute(gemm_kernel<1>, cudaFuncAttributeMaxDynamicSharedMemorySize, GEMM_SMEM);
    cudaFuncSetAttribute(gemm_kernel<2>, cudaFuncAttributeMaxDynamicSharedMemorySize, GEMM_SMEM);
    cudaFuncSetAttribute(gemm_kernel<3>, cudaFuncAttributeMaxDynamicSharedMemorySize, GEMM_SMEM);

    // lazily-created side stream + fork/join events (host resources only;
    // identical captured work on every call)
    static cudaStream_t s2 = nullptr;
    static cudaEvent_t evF = nullptr, evH = nullptr, evJ = nullptr;
    if (!s2) {
        cudaStreamCreateWithFlags(&s2, cudaStreamNonBlocking);
        cudaEventCreateWithFlags(&evF, cudaEventDisableTiming);
        cudaEventCreateWithFlags(&evH, cudaEventDisableTiming);
        cudaEventCreateWithFlags(&evJ, cudaEventDisableTiming);
    }

    // ---- fork: h conversion + MLP weight prep overlap the (underfilled)
    //      colnorm/wconv4 head and the attention chain ----
    cudaEventRecord(evF, 0);
    cudaStreamWaitEvent(s2, evF, 0);
    conv_kernel<<<BT * CDIM / 1024, 256, 0, s2>>>(h, (uint32_t*)hB);
    cudaEventRecord(evH, s2);                      // hB ready
    wfc_perm_kernel<<<8 * CDIM * CDIM / 1024, 256, 0, s2>>>(Wfc, (uint32_t*)WfcP);
    conv_kernel<<<4 * CDIM * CDIM / 1024, 256, 0, s2>>>(Wproj, (uint32_t*)WpjB);
    cudaEventRecord(evJ, s2);                      // WfcP + WpjB ready

    // ---- main chain ----
    colnorm_kernel<<<dim3(32, 4), 256>>>(Wq, Wk, Wv, Wo, inv);
    wconv4_kernel<<<dim3(1024, 4), 256>>>(Wq, Wk, Wv, Wo, inv, (uint32_t*)WqB);

    cudaStreamWaitEvent(0, evH, 0);   // need hB

    // fused qkv projection + qk per-head norm + v transpose: all bf16 outputs
    gemm_kernel<2><<<dim3(24, BT / 128), 128, GEMM_SMEM>>>(hB, WqB, qBf, kBf, VtG, sqk, BT, 3 * CDIM, CDIM);

    attn_tc_kernel<<<dim3(8, 128), 256, ATT_SMEM>>>(qBf, kBf, VtG, yB);

    // o projection -> bf16 t1B
    gemm_kernel<1><<<dim3(8, BT / 128), 128, GEMM_SMEM>>>(yB, WoB, t1B, nullptr, nullptr, nullptr, BT, CDIM, CDIM);

    residual_kernel<<<BT, 256>>>(h, (const __nv_bfloat162*)t1B, a_att, h2, (uint32_t*)h2B);

    // join before fc (needs WfcP; proj needs WpjB)
    cudaStreamWaitEvent(0, evJ, 0);

    // MLP: fc + SwiGLU fused -> x bf16; proj -> bf16 t1B
    gemm_kernel<3><<<dim3(64, BT / 128), 128, GEMM_SMEM>>>(h2B, WfcP, xB, nullptr, nullptr, suv, BT, 8 * CDIM, CDIM);
    gemm_kernel<1><<<dim3(8, BT / 128), 128, GEMM_SMEM>>>(xB, WpjB, t1B, nullptr, nullptr, nullptr, BT, CDIM, 4 * CDIM);

    residual_kernel<<<BT, 256>>>(h2, (const __nv_bfloat162*)t1B, a_mlp, out, nullptr);
}

// round 16
// speedup vs baseline: 1.0478x; 1.0050x over previous
#include <cuda_runtime.h>
#include <cuda_bf16.h>
#include <math.h>
#include <stdint.h>

// nGPT block: B=8, T=1024, C=1024, H=16, D=64
#define BT   8192
#define CDIM 1024

// ---- scratch carve (float units) ----
#define OFF_INV  0
#define OFF_T1   4096                         // bf16 t1 [token][dim]
#define OFF_H2   (OFF_T1  + BT*CDIM)
#define OFF_HB   (OFF_H2  + BT*CDIM)
#define OFF_YB   (OFF_HB  + BT*CDIM/2)
#define OFF_H2B  (OFF_YB  + BT*CDIM/2)
#define OFF_XB   (OFF_H2B + BT*CDIM/2)        // 8192x4096 bf16
#define OFF_WQB  (OFF_XB  + BT*4*CDIM/2)      // Wq,Wk,Wv,Wo bf16 contiguous
#define OFF_WFCB (OFF_WQB + 4*CDIM*CDIM/2)    // permuted Wfc bf16
#define OFF_WPJB (OFF_WFCB + 8*CDIM*CDIM/2)
#define OFF_QBF  (OFF_WPJB + 4*CDIM*CDIM/2)   // bf16 q [token][dim]
#define OFF_KBF  (OFF_QBF + BT*CDIM/2)        // bf16 k
#define OFF_VT   (OFF_KBF + BT*CDIM/2)        // bf16 V^T [dim][token]
#define BUF_TOTAL (OFF_VT + BT*CDIM/2)

__device__ float g_buf[BUF_TOTAL];

__device__ __forceinline__ uint32_t cvt2bf(float lo, float hi) {
    uint32_t r;
    asm("cvt.rn.bf16x2.f32 %0, %1, %2;" : "=r"(r) : "f"(hi), "f"(lo));
    return r;
}

// ---------------------------------------------------------------------------
// inverse column norms of W [C,C] row-major: inv[j] = 1/||W[:,j]||
// grid (32, 4), 1024 threads (32 cols x 32 row-groups) for high MLP.
// ---------------------------------------------------------------------------
__global__ void __launch_bounds__(1024) colnorm_kernel(
    const float* __restrict__ Wq, const float* __restrict__ Wk,
    const float* __restrict__ Wv, const float* __restrict__ Wo,
    float* __restrict__ inv)
{
    int m = blockIdx.y;
    const float* W = (m == 0) ? Wq : (m == 1) ? Wk : (m == 2) ? Wv : Wo;
    int tx = threadIdx.x & 31;
    int ty = threadIdx.x >> 5;
    int col = blockIdx.x * 32 + tx;
    float s = 0.f;
    #pragma unroll 8
    for (int i = ty; i < CDIM; i += 32) {
        float w = W[(size_t)i * CDIM + col];
        s += w * w;
    }
    __shared__ float sm[32][33];
    sm[ty][tx] = s;
    __syncthreads();
    if (ty == 0) {
        float tot = 0.f;
        #pragma unroll
        for (int r = 0; r < 32; r++) tot += sm[r][tx];
        inv[m * CDIM + col] = rsqrtf(tot);
    }
}

// ---------------------------------------------------------------------------
// Weight conversion with folded column norms (4 matrices)
// ---------------------------------------------------------------------------
__global__ void wconv4_kernel(const float* __restrict__ Wq, const float* __restrict__ Wk,
                              const float* __restrict__ Wv, const float* __restrict__ Wo,
                              const float* __restrict__ inv, uint32_t* __restrict__ dst)
{
    int m = blockIdx.y;
    const float* W = (m == 0) ? Wq : (m == 1) ? Wk : (m == 2) ? Wv : Wo;
    int idx = blockIdx.x * 256 + threadIdx.x;
    float4 w = ((const float4*)W)[idx];
    float4 s = ((const float4*)(inv + m * CDIM))[idx & 255];
    uint32_t* d = dst + (size_t)m * (CDIM * CDIM / 2) + idx * 2;
    d[0] = cvt2bf(w.x * s.x, w.y * s.y);
    d[1] = cvt2bf(w.z * s.z, w.w * s.w);
}

__global__ void conv_kernel(const float* __restrict__ src, uint32_t* __restrict__ dst)
{
    int idx = blockIdx.x * 256 + threadIdx.x;
    float4 v = ((const float4*)src)[idx];
    dst[idx * 2 + 0] = cvt2bf(v.x, v.y);
    dst[idx * 2 + 1] = cvt2bf(v.z, v.w);
}

// ---------------------------------------------------------------------------
// Wfc conversion with row permutation for fused SwiGLU
// ---------------------------------------------------------------------------
__global__ void wfc_perm_kernel(const float* __restrict__ Wfc, uint32_t* __restrict__ dst)
{
    int idx = blockIdx.x * 256 + threadIdx.x;
    int r = idx >> 8, c4 = idx & 255;
    int b = r >> 4, w = r & 15;
    int src_r = (w < 8) ? (b * 8 + w) : (4096 + b * 8 + (w - 8));
    float4 v = ((const float4*)Wfc)[(size_t)src_r * 256 + c4];
    dst[(size_t)idx * 2 + 0] = cvt2bf(v.x, v.y);
    dst[(size_t)idx * 2 + 1] = cvt2bf(v.z, v.w);
}

// ---------------------------------------------------------------------------
// bf16 mma.sync GEMM NT (R9/R11 winning shape): 128x128x64, 3-stage cp.async,
// 4 warps, warp tile 64x64, 128 threads, 2 CTAs/SM.
// MODE 1: bf16 out.
// MODE 2: fused qkv: q,k -> per-head normalized bf16; v -> TRANSPOSED bf16
//         written directly into Vt [dim][token] via smem staging.
// MODE 3: fused SwiGLU (permuted Wfc) -> x bf16 [M,4096].
// ---------------------------------------------------------------------------
#define STAGES 3
#define GEMM_SMEM (STAGES * 32768)

template <int MODE>
__global__ void __launch_bounds__(128, 2) gemm_kernel(
    const __nv_bfloat16* __restrict__ A, const __nv_bfloat16* __restrict__ B,
    void* __restrict__ C0, void* __restrict__ C1, void* __restrict__ C2,
    const float* __restrict__ scl,
    int M, int N, int K)
{
    extern __shared__ char smc[];
    const int tid = threadIdx.x, lane = tid & 31, warp = tid >> 5;
    const int wm = warp & 1, wn = warp >> 1;
    const int crow = blockIdx.y * 128, ccol = blockIdx.x * 128;
    const uint32_t sbase = (uint32_t)__cvta_generic_to_shared(smc);

    const __nv_bfloat16* Ag = A + (size_t)crow * K;
    const __nv_bfloat16* Bg = B + (size_t)ccol * K;

    auto issue = [&](int t, int buf) {
        const uint32_t abase = sbase + buf * 32768;
        const uint32_t bbase = abase + 16384;
        const int k0 = t * 64;
        #pragma unroll
        for (int i = 0; i < 8; i++) {
            int idx = tid + i * 128;
            int row = idx >> 3, c = idx & 7;
            uint32_t sw = (uint32_t)(row * 128 + ((c ^ (row & 7)) << 4));
            asm volatile("cp.async.cg.shared.global [%0], [%1], 16;"
                         :: "r"(abase + sw), "l"((const void*)(Ag + (size_t)row * K + k0 + c * 8)));
            asm volatile("cp.async.cg.shared.global [%0], [%1], 16;"
                         :: "r"(bbase + sw), "l"((const void*)(Bg + (size_t)row * K + k0 + c * 8)));
        }
    };

    float acc[4][8][4];
    #pragma unroll
    for (int i = 0; i < 4; i++)
        #pragma unroll
        for (int j = 0; j < 8; j++)
            #pragma unroll
            for (int e = 0; e < 4; e++) acc[i][j][e] = 0.f;

    const int nt = K / 64;

    issue(0, 0); asm volatile("cp.async.commit_group;");
    issue(1, 1); asm volatile("cp.async.commit_group;");

    const int arow0 = wm * 64 + (lane & 15);
    const int akb   = lane >> 4;
    const int asw   = lane & 7;
    const int brow0 = wn * 64 + (lane & 7) + ((lane >> 4) << 3);
    const int bkb   = (lane >> 3) & 1;

    for (int t = 0; t < nt; t++) {
        asm volatile("cp.async.wait_group 1;");
        __syncthreads();

        if (t + 2 < nt) {
            issue(t + 2, (t + 2) % STAGES);
        }
        asm volatile("cp.async.commit_group;");

        const int buf = t % STAGES;
        const uint32_t abase = sbase + buf * 32768;
        const uint32_t bbase = abase + 16384;

        #pragma unroll
        for (int ks = 0; ks < 4; ks++) {
            uint32_t a[4][4], br[4][4];
            const int ach = 2 * ks + akb;
            const int bch = 2 * ks + bkb;
            #pragma unroll
            for (int mi = 0; mi < 4; mi++) {
                uint32_t ad = abase + (uint32_t)(arow0 + mi * 16) * 128 +
                              (uint32_t)((ach ^ asw) << 4);
                asm volatile("ldmatrix.sync.aligned.m8n8.x4.shared.b16 {%0,%1,%2,%3}, [%4];"
                             : "=r"(a[mi][0]), "=r"(a[mi][1]), "=r"(a[mi][2]), "=r"(a[mi][3])
                             : "r"(ad));
            }
            #pragma unroll
            for (int nj2 = 0; nj2 < 4; nj2++) {
                uint32_t bd = bbase + (uint32_t)(brow0 + nj2 * 16) * 128 +
                              (uint32_t)((bch ^ asw) << 4);
                asm volatile("ldmatrix.sync.aligned.m8n8.x4.shared.b16 {%0,%1,%2,%3}, [%4];"
                             : "=r"(br[nj2][0]), "=r"(br[nj2][1]), "=r"(br[nj2][2]), "=r"(br[nj2][3])
                             : "r"(bd));
            }
            #pragma unroll
            for (int mi = 0; mi < 4; mi++)
                #pragma unroll
                for (int nj = 0; nj < 8; nj++) {
                    uint32_t b0 = br[nj >> 1][(nj & 1) * 2];
                    uint32_t b1 = br[nj >> 1][(nj & 1) * 2 + 1];
                    asm volatile(
                        "mma.sync.aligned.m16n8k16.row.col.f32.bf16.bf16.f32 "
                        "{%0,%1,%2,%3}, {%4,%5,%6,%7}, {%8,%9}, {%0,%1,%2,%3};"
                        : "+f"(acc[mi][nj][0]), "+f"(acc[mi][nj][1]),
                          "+f"(acc[mi][nj][2]), "+f"(acc[mi][nj][3])
                        : "r"(a[mi][0]), "r"(a[mi][1]), "r"(a[mi][2]), "r"(a[mi][3]),
                          "r"(b0), "r"(b1));
                }
        }
    }
    __syncthreads();   // mainloop done; smem free for epilogue staging

    // ---- epilogue ----
    if (MODE == 3) {
        const int xc0 = blockIdx.x * 64;
        __nv_bfloat16* Xb = (__nv_bfloat16*)C0;
        #pragma unroll
        for (int p = 0; p < 4; p++) {
            const int cb = xc0 + (wn * 4 + p) * 8 + 2 * (lane & 3);
            const float su0 = scl[cb] * 32.f,        su1 = scl[cb + 1] * 32.f;
            const float sg0 = scl[4096 + cb] * 32.f, sg1 = scl[4096 + cb + 1] * 32.f;
            #pragma unroll
            for (int mi = 0; mi < 4; mi++) {
                const int r0 = crow + wm * 64 + mi * 16 + (lane >> 2);
                float g, x0, x1;
                g = acc[mi][2 * p + 1][0] * sg0; x0 = (acc[mi][2 * p][0] * su0) * g / (1.f + __expf(-g));
                g = acc[mi][2 * p + 1][1] * sg1; x1 = (acc[mi][2 * p][1] * su1) * g / (1.f + __expf(-g));
                *(uint32_t*)&Xb[(size_t)r0 * 4096 + cb] = cvt2bf(x0, x1);
                g = acc[mi][2 * p + 1][2] * sg0; x0 = (acc[mi][2 * p][2] * su0) * g / (1.f + __expf(-g));
                g = acc[mi][2 * p + 1][3] * sg1; x1 = (acc[mi][2 * p][3] * su1) * g / (1.f + __expf(-g));
                *(uint32_t*)&Xb[(size_t)(r0 + 8) * 4096 + cb] = cvt2bf(x0, x1);
            }
        }
    } else if (MODE == 2) {
        const int which = ccol >> 10;        // 0=q,1=k,2=v
        const int cl = ccol & 1023;
        if (which == 2) {
            // v: stage dim-major in smem, then write transposed rows to Vt.
            __nv_bfloat16* Vt = (__nv_bfloat16*)C2;
            __nv_bfloat16* st = (__nv_bfloat16*)smc;   // 128 dims x (128+8) tokens
            const int RSV = 136;
            #pragma unroll
            for (int mi = 0; mi < 4; mi++) {
                const int rl = wm * 64 + mi * 16 + (lane >> 2);
                #pragma unroll
                for (int nj = 0; nj < 8; nj++) {
                    const int c2 = wn * 64 + nj * 8 + 2 * (lane & 3);
                    st[(c2 + 0) * RSV + rl    ] = __float2bfloat16(acc[mi][nj][0]);
                    st[(c2 + 1) * RSV + rl    ] = __float2bfloat16(acc[mi][nj][1]);
                    st[(c2 + 0) * RSV + rl + 8] = __float2bfloat16(acc[mi][nj][2]);
                    st[(c2 + 1) * RSV + rl + 8] = __float2bfloat16(acc[mi][nj][3]);
                }
            }
            __syncthreads();
            const int d = tid;  // 0..127 local dim
            #pragma unroll
            for (int t8 = 0; t8 < 16; t8++) {
                *(uint4*)&Vt[(size_t)(cl + d) * BT + crow + t8 * 8] =
                    *(uint4*)&st[d * RSV + t8 * 8];
            }
        } else {
            __nv_bfloat16* Cb = which ? (__nv_bfloat16*)C1 : (__nv_bfloat16*)C0;
            const float extra = which ? 32.f : 256.f;
            float sc0[8], sc1[8];
            #pragma unroll
            for (int nj = 0; nj < 8; nj++) {
                const int c0 = cl + wn * 64 + nj * 8 + 2 * (lane & 3);
                sc0[nj] = scl[c0] * extra;
                sc1[nj] = scl[c0 + 1] * extra;
            }
            #pragma unroll
            for (int mi = 0; mi < 4; mi++) {
                const int r0 = crow + wm * 64 + mi * 16 + (lane >> 2);
                float ss0 = 0.f, ss1 = 0.f;
                #pragma unroll
                for (int nj = 0; nj < 8; nj++) {
                    ss0 += acc[mi][nj][0] * acc[mi][nj][0] + acc[mi][nj][1] * acc[mi][nj][1];
                    ss1 += acc[mi][nj][2] * acc[mi][nj][2] + acc[mi][nj][3] * acc[mi][nj][3];
                }
                ss0 += __shfl_xor_sync(0xffffffffu, ss0, 1);
                ss0 += __shfl_xor_sync(0xffffffffu, ss0, 2);
                ss1 += __shfl_xor_sync(0xffffffffu, ss1, 1);
                ss1 += __shfl_xor_sync(0xffffffffu, ss1, 2);
                const float rn0 = rsqrtf(ss0), rn1 = rsqrtf(ss1);
                #pragma unroll
                for (int nj = 0; nj < 8; nj++) {
                    const int c0 = cl + wn * 64 + nj * 8 + 2 * (lane & 3);
                    *(uint32_t*)&Cb[(size_t)r0 * 1024 + c0] =
                        cvt2bf(acc[mi][nj][0] * rn0 * sc0[nj], acc[mi][nj][1] * rn0 * sc1[nj]);
                    *(uint32_t*)&Cb[(size_t)(r0 + 8) * 1024 + c0] =
                        cvt2bf(acc[mi][nj][2] * rn1 * sc0[nj], acc[mi][nj][3] * rn1 * sc1[nj]);
                }
            }
        }
    } else {
        __nv_bfloat16* Cb = (__nv_bfloat16*)C0;
        #pragma unroll
        for (int mi = 0; mi < 4; mi++) {
            const int r0 = crow + wm * 64 + mi * 16 + (lane >> 2);
            #pragma unroll
            for (int nj = 0; nj < 8; nj++) {
                const int c0 = ccol + wn * 64 + nj * 8 + 2 * (lane & 3);
                *(uint32_t*)&Cb[(size_t)r0 * N + c0] =
                    cvt2bf(acc[mi][nj][0], acc[mi][nj][1]);
                *(uint32_t*)&Cb[(size_t)(r0 + 8) * N + c0] =
                    cvt2bf(acc[mi][nj][2], acc[mi][nj][3]);
            }
        }
    }
}

// ---------------------------------------------------------------------------
// Tensor-core flash attention (non-causal), D=64. (R11 winner, unchanged)
// ---------------------------------------------------------------------------
#define ATT_SMEM (16384 + 3 * 32768)

__global__ void __launch_bounds__(256) attn_tc_kernel(
    const __nv_bfloat16* __restrict__ q, const __nv_bfloat16* __restrict__ k,
    const __nv_bfloat16* __restrict__ vt, __nv_bfloat16* __restrict__ y)
{
    extern __shared__ char smc[];
    const int tid = threadIdx.x, lane = tid & 31, warp = tid >> 5;
    const int bh = blockIdx.y, b = bh >> 4, cb = (bh & 15) * 64;
    const int tq0 = b * 1024 + blockIdx.x * 128;
    const uint32_t sb = (uint32_t)__cvta_generic_to_shared(smc);
    const uint32_t qs = sb;

    #pragma unroll
    for (int i = 0; i < 4; i++) {
        int idx = tid + i * 256;
        int row = idx >> 3, c = idx & 7;
        uint32_t sw = (uint32_t)(row * 128 + ((c ^ (row & 7)) << 4));
        asm volatile("cp.async.cg.shared.global [%0], [%1], 16;"
                     :: "r"(qs + sw), "l"((const void*)(q + (size_t)(tq0 + row) * CDIM + cb + c * 8)));
    }
    asm volatile("cp.async.commit_group;");

    auto issueKV = [&](int kt, int buf) {
        const int tk0 = b * 1024 + kt * 128;
        const uint32_t kb_ = sb + 16384 + buf * 32768;
        const uint32_t vb_ = kb_ + 16384;
        #pragma unroll
        for (int i = 0; i < 4; i++) {
            int idx = tid + i * 256;
            int row = idx >> 3, c = idx & 7;
            uint32_t sw = (uint32_t)(row * 128 + ((c ^ (row & 7)) << 4));
            asm volatile("cp.async.cg.shared.global [%0], [%1], 16;"
                         :: "r"(kb_ + sw), "l"((const void*)(k + (size_t)(tk0 + row) * CDIM + cb + c * 8)));
            asm volatile("cp.async.cg.shared.global [%0], [%1], 16;"
                         :: "r"(vb_ + sw),
                            "l"((const void*)(vt + (size_t)(cb + (row & 63)) * BT + tk0 + (row >> 6) * 64 + c * 8)));
        }
    };

    issueKV(0, 0); asm volatile("cp.async.commit_group;");
    issueKV(1, 1); asm volatile("cp.async.commit_group;");

    asm volatile("cp.async.wait_group 2;");
    __syncthreads();

    const int arow = warp * 16 + (lane & 15);
    const int akb  = lane >> 4;
    const int lsw  = lane & 7;
    uint32_t aq[4][4];
    #pragma unroll
    for (int ks = 0; ks < 4; ks++) {
        uint32_t ad = qs + (uint32_t)arow * 128 + (uint32_t)(((2 * ks + akb) ^ lsw) << 4);
        asm volatile("ldmatrix.sync.aligned.m8n8.x4.shared.b16 {%0,%1,%2,%3}, [%4];"
                     : "=r"(aq[ks][0]), "=r"(aq[ks][1]), "=r"(aq[ks][2]), "=r"(aq[ks][3])
                     : "r"(ad));
    }

    float acc_o[8][4];
    #pragma unroll
    for (int j = 0; j < 8; j++)
        #pragma unroll
        for (int e = 0; e < 4; e++) acc_o[j][e] = 0.f;
    float m0 = -1e30f, m1 = -1e30f, l0 = 0.f, l1 = 0.f;

    const int brow = (lane & 7) + ((lane >> 4) << 3);
    const int bkb  = (lane >> 3) & 1;

    for (int kt = 0; kt < 8; kt++) {
        asm volatile("cp.async.wait_group 1;");
        __syncthreads();

        const uint32_t kb_ = sb + 16384 + (kt % 3) * 32768;
        const uint32_t vb_ = kb_ + 16384;

        float s[16][4];
        #pragma unroll
        for (int j = 0; j < 16; j++)
            #pragma unroll
            for (int e = 0; e < 4; e++) s[j][e] = 0.f;

        #pragma unroll
        for (int ks = 0; ks < 4; ks++) {
            const int bch = 2 * ks + bkb;
            #pragma unroll
            for (int nj2 = 0; nj2 < 8; nj2++) {
                uint32_t bk[4];
                uint32_t bd = kb_ + (uint32_t)(brow + nj2 * 16) * 128 +
                              (uint32_t)((bch ^ lsw) << 4);
                asm volatile("ldmatrix.sync.aligned.m8n8.x4.shared.b16 {%0,%1,%2,%3}, [%4];"
                             : "=r"(bk[0]), "=r"(bk[1]), "=r"(bk[2]), "=r"(bk[3]) : "r"(bd));
                asm volatile(
                    "mma.sync.aligned.m16n8k16.row.col.f32.bf16.bf16.f32 "
                    "{%0,%1,%2,%3}, {%4,%5,%6,%7}, {%8,%9}, {%0,%1,%2,%3};"
                    : "+f"(s[2 * nj2][0]), "+f"(s[2 * nj2][1]), "+f"(s[2 * nj2][2]), "+f"(s[2 * nj2][3])
                    : "r"(aq[ks][0]), "r"(aq[ks][1]), "r"(aq[ks][2]), "r"(aq[ks][3]),
                      "r"(bk[0]), "r"(bk[1]));
                asm volatile(
                    "mma.sync.aligned.m16n8k16.row.col.f32.bf16.bf16.f32 "
                    "{%0,%1,%2,%3}, {%4,%5,%6,%7}, {%8,%9}, {%0,%1,%2,%3};"
                    : "+f"(s[2 * nj2 + 1][0]), "+f"(s[2 * nj2 + 1][1]), "+f"(s[2 * nj2 + 1][2]), "+f"(s[2 * nj2 + 1][3])
                    : "r"(aq[ks][0]), "r"(aq[ks][1]), "r"(aq[ks][2]), "r"(aq[ks][3]),
                      "r"(bk[2]), "r"(bk[3]));
            }
        }

        float rm0 = -1e30f, rm1 = -1e30f;
        #pragma unroll
        for (int j = 0; j < 16; j++) {
            rm0 = fmaxf(rm0, fmaxf(s[j][0], s[j][1]));
            rm1 = fmaxf(rm1, fmaxf(s[j][2], s[j][3]));
        }
        rm0 = fmaxf(rm0, __shfl_xor_sync(0xffffffffu, rm0, 1));
        rm0 = fmaxf(rm0, __shfl_xor_sync(0xffffffffu, rm0, 2));
        rm1 = fmaxf(rm1, __shfl_xor_sync(0xffffffffu, rm1, 1));
        rm1 = fmaxf(rm1, __shfl_xor_sync(0xffffffffu, rm1, 2));
        float nm0 = fmaxf(m0, rm0), nm1 = fmaxf(m1, rm1);
        float co0 = __expf(m0 - nm0), co1 = __expf(m1 - nm1);
        float ls0 = 0.f, ls1 = 0.f;
        #pragma unroll
        for (int j = 0; j < 16; j++) {
            s[j][0] = __expf(s[j][0] - nm0); ls0 += s[j][0];
            s[j][1] = __expf(s[j][1] - nm0); ls0 += s[j][1];
            s[j][2] = __expf(s[j][2] - nm1); ls1 += s[j][2];
            s[j][3] = __expf(s[j][3] - nm1); ls1 += s[j][3];
        }
        ls0 += __shfl_xor_sync(0xffffffffu, ls0, 1);
        ls0 += __shfl_xor_sync(0xffffffffu, ls0, 2);
        ls1 += __shfl_xor_sync(0xffffffffu, ls1, 1);
        ls1 += __shfl_xor_sync(0xffffffffu, ls1, 2);
        l0 = l0 * co0 + ls0; l1 = l1 * co1 + ls1;
        m0 = nm0; m1 = nm1;
        #pragma unroll
        for (int j = 0; j < 8; j++) {
            acc_o[j][0] *= co0; acc_o[j][1] *= co0;
            acc_o[j][2] *= co1; acc_o[j][3] *= co1;
        }

        #pragma unroll
        for (int kp = 0; kp < 8; kp++) {
            uint32_t ap[4];
            ap[0] = cvt2bf(s[2 * kp][0],     s[2 * kp][1]);
            ap[1] = cvt2bf(s[2 * kp][2],     s[2 * kp][3]);
            ap[2] = cvt2bf(s[2 * kp + 1][0], s[2 * kp + 1][1]);
            ap[3] = cvt2bf(s[2 * kp + 1][2], s[2 * kp + 1][3]);
            const uint32_t vbase = vb_ + (uint32_t)((kp >> 2) * 8192);
            const int ach = 2 * (kp & 3) + bkb;
            #pragma unroll
            for (int dj2 = 0; dj2 < 4; dj2++) {
                uint32_t bv[4];
                uint32_t bd = vbase + (uint32_t)(brow + dj2 * 16) * 128 +
                              (uint32_t)((ach ^ lsw) << 4);
                asm volatile("ldmatrix.sync.aligned.m8n8.x4.shared.b16 {%0,%1,%2,%3}, [%4];"
                             : "=r"(bv[0]), "=r"(bv[1]), "=r"(bv[2]), "=r"(bv[3]) : "r"(bd));
                asm volatile(
                    "mma.sync.aligned.m16n8k16.row.col.f32.bf16.bf16.f32 "
                    "{%0,%1,%2,%3}, {%4,%5,%6,%7}, {%8,%9}, {%0,%1,%2,%3};"
                    : "+f"(acc_o[2 * dj2][0]), "+f"(acc_o[2 * dj2][1]), "+f"(acc_o[2 * dj2][2]), "+f"(acc_o[2 * dj2][3])
                    : "r"(ap[0]), "r"(ap[1]), "r"(ap[2]), "r"(ap[3]), "r"(bv[0]), "r"(bv[1]));
                asm volatile(
                    "mma.sync.aligned.m16n8k16.row.col.f32.bf16.bf16.f32 "
                    "{%0,%1,%2,%3}, {%4,%5,%6,%7}, {%8,%9}, {%0,%1,%2,%3};"
                    : "+f"(acc_o[2 * dj2 + 1][0]), "+f"(acc_o[2 * dj2 + 1][1]), "+f"(acc_o[2 * dj2 + 1][2]), "+f"(acc_o[2 * dj2 + 1][3])
                    : "r"(ap[0]), "r"(ap[1]), "r"(ap[2]), "r"(ap[3]), "r"(bv[2]), "r"(bv[3]));
            }
        }

        if (kt + 2 < 8) issueKV(kt + 2, (kt + 2) % 3);
        asm volatile("cp.async.commit_group;");
    }

    const float li0 = 1.f / l0, li1 = 1.f / l1;
    const int r0 = tq0 + warp * 16 + (lane >> 2);
    #pragma unroll
    for (int dj = 0; dj < 8; dj++) {
        const int c0 = cb + dj * 8 + 2 * (lane & 3);
        *(uint32_t*)&y[(size_t)r0 * CDIM + c0] =
            cvt2bf(acc_o[dj][0] * li0, acc_o[dj][1] * li0);
        *(uint32_t*)&y[(size_t)(r0 + 8) * CDIM + c0] =
            cvt2bf(acc_o[dj][2] * li1, acc_o[dj][3] * li1);
    }
}

// ---------------------------------------------------------------------------
// out = justnorm( justnorm(h) + |alpha*1.6| * (justnorm(hb) - justnorm(h)) )
// hb is bf16 (lr-damped branch).
// ---------------------------------------------------------------------------
__global__ void residual_kernel(const float* __restrict__ hin,
                                const __nv_bfloat162* __restrict__ hb,
                                const float* __restrict__ alpha, float* __restrict__ out,
                                uint32_t* __restrict__ outb)
{
    int t = blockIdx.x, tid = threadIdx.x;
    float4 a = ((const float4*)hin)[(size_t)t * 256 + tid];
    __nv_bfloat162 b0 = hb[((size_t)t * 256 + tid) * 2];
    __nv_bfloat162 b1 = hb[((size_t)t * 256 + tid) * 2 + 1];
    float4 b = make_float4(__bfloat162float(b0.x), __bfloat162float(b0.y),
                           __bfloat162float(b1.x), __bfloat162float(b1.y));
    float s1 = a.x * a.x + a.y * a.y + a.z * a.z + a.w * a.w;
    float s2 = b.x * b.x + b.y * b.y + b.z * b.z + b.w * b.w;
    #pragma unroll
    for (int off = 16; off >= 1; off >>= 1) {
        s1 += __shfl_xor_sync(0xffffffffu, s1, off);
        s2 += __shfl_xor_sync(0xffffffffu, s2, off);
    }
    __shared__ float red1[8], red2[8];
    int w = tid >> 5, lane = tid & 31;
    if (lane == 0) { red1[w] = s1; red2[w] = s2; }
    __syncthreads();
    float t1 = 0.f, t2 = 0.f;
    #pragma unroll
    for (int i = 0; i < 8; i++) { t1 += red1[i]; t2 += red2[i]; }
    float r1 = rsqrtf(t1), r2 = rsqrtf(t2);

    float4 al = ((const float4*)alpha)[tid];
    float4 u;
    u.x = a.x * r1 + fabsf(al.x * 1.6f) * (b.x * r2 - a.x * r1);
    u.y = a.y * r1 + fabsf(al.y * 1.6f) * (b.y * r2 - a.y * r1);
    u.z = a.z * r1 + fabsf(al.z * 1.6f) * (b.z * r2 - a.z * r1);
    u.w = a.w * r1 + fabsf(al.w * 1.6f) * (b.w * r2 - a.w * r1);

    float s3 = u.x * u.x + u.y * u.y + u.z * u.z + u.w * u.w;
    #pragma unroll
    for (int off = 16; off >= 1; off >>= 1) s3 += __shfl_xor_sync(0xffffffffu, s3, off);
    __syncthreads();
    if (lane == 0) red1[w] = s3;
    __syncthreads();
    float t3 = 0.f;
    #pragma unroll
    for (int i = 0; i < 8; i++) t3 += red1[i];
    float r3 = rsqrtf(t3);
    float4 o = make_float4(u.x * r3, u.y * r3, u.z * r3, u.w * r3);
    ((float4*)out)[(size_t)t * 256 + tid] = o;
    if (outb) {
        outb[((size_t)t * 256 + tid) * 2 + 0] = cvt2bf(o.x, o.y);
        outb[((size_t)t * 256 + tid) * 2 + 1] = cvt2bf(o.z, o.w);
    }
}

// ---------------------------------------------------------------------------
extern "C" void kernel_launch(void* const* d_in, const int* in_sizes, int n_in,
                              void* d_out, int out_size)
{
    (void)in_sizes; (void)n_in; (void)out_size;
    const float* h     = (const float*)d_in[0];
    const float* Wq    = (const float*)d_in[1];
    const float* Wk    = (const float*)d_in[2];
    const float* Wv    = (const float*)d_in[3];
    const float* Wo    = (const float*)d_in[4];
    const float* Wfc   = (const float*)d_in[5];
    const float* Wproj = (const float*)d_in[6];
    const float* sqk   = (const float*)d_in[7];
    const float* suv   = (const float*)d_in[8];
    const float* a_att = (const float*)d_in[9];
    const float* a_mlp = (const float*)d_in[10];
    float* out = (float*)d_out;

    float* buf = nullptr;
    cudaGetSymbolAddress((void**)&buf, g_buf);
    float* inv = buf + OFF_INV;
    float* h2  = buf + OFF_H2;
    __nv_bfloat16* t1B  = (__nv_bfloat16*)(buf + OFF_T1);
    __nv_bfloat16* hB   = (__nv_bfloat16*)(buf + OFF_HB);
    __nv_bfloat16* yB   = (__nv_bfloat16*)(buf + OFF_YB);
    __nv_bfloat16* h2B  = (__nv_bfloat16*)(buf + OFF_H2B);
    __nv_bfloat16* xB   = (__nv_bfloat16*)(buf + OFF_XB);
    __nv_bfloat16* WqB  = (__nv_bfloat16*)(buf + OFF_WQB);   // q,k,v contiguous
    __nv_bfloat16* WoB  = WqB + 3 * CDIM * CDIM;
    __nv_bfloat16* WfcP = (__nv_bfloat16*)(buf + OFF_WFCB);  // permuted
    __nv_bfloat16* WpjB = (__nv_bfloat16*)(buf + OFF_WPJB);
    __nv_bfloat16* qBf  = (__nv_bfloat16*)(buf + OFF_QBF);
    __nv_bfloat16* kBf  = (__nv_bfloat16*)(buf + OFF_KBF);
    __nv_bfloat16* VtG  = (__nv_bfloat16*)(buf + OFF_VT);

    cudaFuncSetAttribute(attn_tc_kernel, cudaFuncAttributeMaxDynamicSharedMemorySize, ATT_SMEM);
    cudaFuncSetAttribute(gemm_kernel<1>, cudaFuncAttributeMaxDynamicSharedMemorySize, GEMM_SMEM);
    cudaFuncSetAttribute(gemm_kernel<2>, cudaFuncAttributeMaxDynamicSharedMemorySize, GEMM_SMEM);
    cudaFuncSetAttribute(gemm_kernel<3>, cudaFuncAttributeMaxDynamicSharedMemorySize, GEMM_SMEM);

    // lazily-created side stream + fork/join events (host resources only;
    // identical captured work on every call)
    static cudaStream_t s2 = nullptr;
    static cudaEvent_t evF = nullptr, evH = nullptr, evJ = nullptr;
    if (!s2) {
        cudaStreamCreateWithFlags(&s2, cudaStreamNonBlocking);
        cudaEventCreateWithFlags(&evF, cudaEventDisableTiming);
        cudaEventCreateWithFlags(&evH, cudaEventDisableTiming);
        cudaEventCreateWithFlags(&evJ, cudaEventDisableTiming);
    }

    // ---- fork: h conversion + MLP weight prep overlap the (underfilled)
    //      colnorm/wconv4 head and the attention chain ----
    cudaEventRecord(evF, 0);
    cudaStreamWaitEvent(s2, evF, 0);
    conv_kernel<<<BT * CDIM / 1024, 256, 0, s2>>>(h, (uint32_t*)hB);
    cudaEventRecord(evH, s2);                      // hB ready
    wfc_perm_kernel<<<8 * CDIM * CDIM / 1024, 256, 0, s2>>>(Wfc, (uint32_t*)WfcP);
    conv_kernel<<<4 * CDIM * CDIM / 1024, 256, 0, s2>>>(Wproj, (uint32_t*)WpjB);
    cudaEventRecord(evJ, s2);                      // WfcP + WpjB ready

    // ---- main chain ----
    colnorm_kernel<<<dim3(32, 4), 1024>>>(Wq, Wk, Wv, Wo, inv);
    wconv4_kernel<<<dim3(1024, 4), 256>>>(Wq, Wk, Wv, Wo, inv, (uint32_t*)WqB);

    cudaStreamWaitEvent(0, evH, 0);   // need hB

    // fused qkv projection + qk per-head norm + v transpose: all bf16 outputs
    gemm_kernel<2><<<dim3(24, BT / 128), 128, GEMM_SMEM>>>(hB, WqB, qBf, kBf, VtG, sqk, BT, 3 * CDIM, CDIM);

    attn_tc_kernel<<<dim3(8, 128), 256, ATT_SMEM>>>(qBf, kBf, VtG, yB);

    // o projection -> bf16 t1B
    gemm_kernel<1><<<dim3(8, BT / 128), 128, GEMM_SMEM>>>(yB, WoB, t1B, nullptr, nullptr, nullptr, BT, CDIM, CDIM);

    residual_kernel<<<BT, 256>>>(h, (const __nv_bfloat162*)t1B, a_att, h2, (uint32_t*)h2B);

    // join before fc (needs WfcP; proj needs WpjB)
    cudaStreamWaitEvent(0, evJ, 0);

    // MLP: fc + SwiGLU fused -> x bf16; proj -> bf16 t1B
    gemm_kernel<3><<<dim3(64, BT / 128), 128, GEMM_SMEM>>>(h2B, WfcP, xB, nullptr, nullptr, suv, BT, 8 * CDIM, CDIM);
    gemm_kernel<1><<<dim3(8, BT / 128), 128, GEMM_SMEM>>>(xB, WpjB, t1B, nullptr, nullptr, nullptr, BT, CDIM, 4 * CDIM);

    residual_kernel<<<BT, 256>>>(h2, (const __nv_bfloat162*)t1B, a_mlp, out, nullptr);
}

// round 17
// speedup vs baseline: 1.0529x; 1.0049x over previous
#include <cuda_runtime.h>
#include <cuda_bf16.h>
#include <math.h>
#include <stdint.h>

// nGPT block: B=8, T=1024, C=1024, H=16, D=64
#define BT   8192
#define CDIM 1024

// ---- scratch carve (float units) ----
#define OFF_INV  0
#define OFF_T1   4096                         // bf16 t1 [token][dim]
#define OFF_H2   (OFF_T1  + BT*CDIM)
#define OFF_HB   (OFF_H2  + BT*CDIM)
#define OFF_YB   (OFF_HB  + BT*CDIM/2)
#define OFF_H2B  (OFF_YB  + BT*CDIM/2)
#define OFF_XB   (OFF_H2B + BT*CDIM/2)        // 8192x4096 bf16
#define OFF_WQB  (OFF_XB  + BT*4*CDIM/2)      // Wq,Wk,Wv,Wo bf16 contiguous
#define OFF_WFCB (OFF_WQB + 4*CDIM*CDIM/2)    // permuted Wfc bf16
#define OFF_WPJB (OFF_WFCB + 8*CDIM*CDIM/2)
#define OFF_QBF  (OFF_WPJB + 4*CDIM*CDIM/2)   // bf16 q [token][dim]
#define OFF_KBF  (OFF_QBF + BT*CDIM/2)        // bf16 k
#define OFF_VT   (OFF_KBF + BT*CDIM/2)        // bf16 V^T [dim][token]
#define BUF_TOTAL (OFF_VT + BT*CDIM/2)

__device__ float g_buf[BUF_TOTAL];

__device__ __forceinline__ uint32_t cvt2bf(float lo, float hi) {
    uint32_t r;
    asm("cvt.rn.bf16x2.f32 %0, %1, %2;" : "=r"(r) : "f"(hi), "f"(lo));
    return r;
}

// ---------------------------------------------------------------------------
// Fused column-norm + bf16 weight conversion (4 matrices).
// grid (32, 4), 1024 threads (32 cols x 32 row-groups).
// Pass 1: per-column sum of squares (identical reduction/rounding to R16).
// Pass 2: re-read own 128KB slice (L2-hot), scale by rsqrt, write bf16.
// ---------------------------------------------------------------------------
__global__ void __launch_bounds__(1024) wnormconv_kernel(
    const float* __restrict__ Wq, const float* __restrict__ Wk,
    const float* __restrict__ Wv, const float* __restrict__ Wo,
    __nv_bfloat16* __restrict__ dst)
{
    int m = blockIdx.y;
    const float* W = (m == 0) ? Wq : (m == 1) ? Wk : (m == 2) ? Wv : Wo;
    int tx = threadIdx.x & 31;
    int ty = threadIdx.x >> 5;
    int col = blockIdx.x * 32 + tx;
    float s = 0.f;
    #pragma unroll 8
    for (int i = ty; i < CDIM; i += 32) {
        float w = W[(size_t)i * CDIM + col];
        s += w * w;
    }
    __shared__ float sm[32][33];
    __shared__ float invs[32];
    sm[ty][tx] = s;
    __syncthreads();
    if (ty == 0) {
        float tot = 0.f;
        #pragma unroll
        for (int r = 0; r < 32; r++) tot += sm[r][tx];
        invs[tx] = rsqrtf(tot);
    }
    __syncthreads();
    const float iv = invs[tx];
    __nv_bfloat16* d = dst + (size_t)m * CDIM * CDIM;
    #pragma unroll 8
    for (int i = ty; i < CDIM; i += 32) {
        d[(size_t)i * CDIM + col] = __float2bfloat16(W[(size_t)i * CDIM + col] * iv);
    }
}

__global__ void conv_kernel(const float* __restrict__ src, uint32_t* __restrict__ dst)
{
    int idx = blockIdx.x * 256 + threadIdx.x;
    float4 v = ((const float4*)src)[idx];
    dst[idx * 2 + 0] = cvt2bf(v.x, v.y);
    dst[idx * 2 + 1] = cvt2bf(v.z, v.w);
}

// ---------------------------------------------------------------------------
// Wfc conversion with row permutation for fused SwiGLU
// ---------------------------------------------------------------------------
__global__ void wfc_perm_kernel(const float* __restrict__ Wfc, uint32_t* __restrict__ dst)
{
    int idx = blockIdx.x * 256 + threadIdx.x;
    int r = idx >> 8, c4 = idx & 255;
    int b = r >> 4, w = r & 15;
    int src_r = (w < 8) ? (b * 8 + w) : (4096 + b * 8 + (w - 8));
    float4 v = ((const float4*)Wfc)[(size_t)src_r * 256 + c4];
    dst[(size_t)idx * 2 + 0] = cvt2bf(v.x, v.y);
    dst[(size_t)idx * 2 + 1] = cvt2bf(v.z, v.w);
}

// ---------------------------------------------------------------------------
// bf16 mma.sync GEMM NT (R9/R11 winning shape): 128x128x64, 3-stage cp.async,
// 4 warps, warp tile 64x64, 128 threads, 2 CTAs/SM.
// MODE 1: bf16 out.
// MODE 2: fused qkv: q,k -> per-head normalized bf16; v -> TRANSPOSED bf16
//         written directly into Vt [dim][token] via smem staging.
// MODE 3: fused SwiGLU (permuted Wfc) -> x bf16 [M,4096].
// ---------------------------------------------------------------------------
#define STAGES 3
#define GEMM_SMEM (STAGES * 32768)

template <int MODE>
__global__ void __launch_bounds__(128, 2) gemm_kernel(
    const __nv_bfloat16* __restrict__ A, const __nv_bfloat16* __restrict__ B,
    void* __restrict__ C0, void* __restrict__ C1, void* __restrict__ C2,
    const float* __restrict__ scl,
    int M, int N, int K)
{
    extern __shared__ char smc[];
    const int tid = threadIdx.x, lane = tid & 31, warp = tid >> 5;
    const int wm = warp & 1, wn = warp >> 1;
    const int crow = blockIdx.y * 128, ccol = blockIdx.x * 128;
    const uint32_t sbase = (uint32_t)__cvta_generic_to_shared(smc);

    const __nv_bfloat16* Ag = A + (size_t)crow * K;
    const __nv_bfloat16* Bg = B + (size_t)ccol * K;

    auto issue = [&](int t, int buf) {
        const uint32_t abase = sbase + buf * 32768;
        const uint32_t bbase = abase + 16384;
        const int k0 = t * 64;
        #pragma unroll
        for (int i = 0; i < 8; i++) {
            int idx = tid + i * 128;
            int row = idx >> 3, c = idx & 7;
            uint32_t sw = (uint32_t)(row * 128 + ((c ^ (row & 7)) << 4));
            asm volatile("cp.async.cg.shared.global [%0], [%1], 16;"
                         :: "r"(abase + sw), "l"((const void*)(Ag + (size_t)row * K + k0 + c * 8)));
            asm volatile("cp.async.cg.shared.global [%0], [%1], 16;"
                         :: "r"(bbase + sw), "l"((const void*)(Bg + (size_t)row * K + k0 + c * 8)));
        }
    };

    float acc[4][8][4];
    #pragma unroll
    for (int i = 0; i < 4; i++)
        #pragma unroll
        for (int j = 0; j < 8; j++)
            #pragma unroll
            for (int e = 0; e < 4; e++) acc[i][j][e] = 0.f;

    const int nt = K / 64;

    issue(0, 0); asm volatile("cp.async.commit_group;");
    issue(1, 1); asm volatile("cp.async.commit_group;");

    const int arow0 = wm * 64 + (lane & 15);
    const int akb   = lane >> 4;
    const int asw   = lane & 7;
    const int brow0 = wn * 64 + (lane & 7) + ((lane >> 4) << 3);
    const int bkb   = (lane >> 3) & 1;

    for (int t = 0; t < nt; t++) {
        asm volatile("cp.async.wait_group 1;");
        __syncthreads();

        if (t + 2 < nt) {
            issue(t + 2, (t + 2) % STAGES);
        }
        asm volatile("cp.async.commit_group;");

        const int buf = t % STAGES;
        const uint32_t abase = sbase + buf * 32768;
        const uint32_t bbase = abase + 16384;

        #pragma unroll
        for (int ks = 0; ks < 4; ks++) {
            uint32_t a[4][4], br[4][4];
            const int ach = 2 * ks + akb;
            const int bch = 2 * ks + bkb;
            #pragma unroll
            for (int mi = 0; mi < 4; mi++) {
                uint32_t ad = abase + (uint32_t)(arow0 + mi * 16) * 128 +
                              (uint32_t)((ach ^ asw) << 4);
                asm volatile("ldmatrix.sync.aligned.m8n8.x4.shared.b16 {%0,%1,%2,%3}, [%4];"
                             : "=r"(a[mi][0]), "=r"(a[mi][1]), "=r"(a[mi][2]), "=r"(a[mi][3])
                             : "r"(ad));
            }
            #pragma unroll
            for (int nj2 = 0; nj2 < 4; nj2++) {
                uint32_t bd = bbase + (uint32_t)(brow0 + nj2 * 16) * 128 +
                              (uint32_t)((bch ^ asw) << 4);
                asm volatile("ldmatrix.sync.aligned.m8n8.x4.shared.b16 {%0,%1,%2,%3}, [%4];"
                             : "=r"(br[nj2][0]), "=r"(br[nj2][1]), "=r"(br[nj2][2]), "=r"(br[nj2][3])
                             : "r"(bd));
            }
            #pragma unroll
            for (int mi = 0; mi < 4; mi++)
                #pragma unroll
                for (int nj = 0; nj < 8; nj++) {
                    uint32_t b0 = br[nj >> 1][(nj & 1) * 2];
                    uint32_t b1 = br[nj >> 1][(nj & 1) * 2 + 1];
                    asm volatile(
                        "mma.sync.aligned.m16n8k16.row.col.f32.bf16.bf16.f32 "
                        "{%0,%1,%2,%3}, {%4,%5,%6,%7}, {%8,%9}, {%0,%1,%2,%3};"
                        : "+f"(acc[mi][nj][0]), "+f"(acc[mi][nj][1]),
                          "+f"(acc[mi][nj][2]), "+f"(acc[mi][nj][3])
                        : "r"(a[mi][0]), "r"(a[mi][1]), "r"(a[mi][2]), "r"(a[mi][3]),
                          "r"(b0), "r"(b1));
                }
        }
    }
    __syncthreads();   // mainloop done; smem free for epilogue staging

    // ---- epilogue ----
    if (MODE == 3) {
        const int xc0 = blockIdx.x * 64;
        __nv_bfloat16* Xb = (__nv_bfloat16*)C0;
        #pragma unroll
        for (int p = 0; p < 4; p++) {
            const int cb = xc0 + (wn * 4 + p) * 8 + 2 * (lane & 3);
            const float su0 = scl[cb] * 32.f,        su1 = scl[cb + 1] * 32.f;
            const float sg0 = scl[4096 + cb] * 32.f, sg1 = scl[4096 + cb + 1] * 32.f;
            #pragma unroll
            for (int mi = 0; mi < 4; mi++) {
                const int r0 = crow + wm * 64 + mi * 16 + (lane >> 2);
                float g, x0, x1;
                g = acc[mi][2 * p + 1][0] * sg0; x0 = (acc[mi][2 * p][0] * su0) * g / (1.f + __expf(-g));
                g = acc[mi][2 * p + 1][1] * sg1; x1 = (acc[mi][2 * p][1] * su1) * g / (1.f + __expf(-g));
                *(uint32_t*)&Xb[(size_t)r0 * 4096 + cb] = cvt2bf(x0, x1);
                g = acc[mi][2 * p + 1][2] * sg0; x0 = (acc[mi][2 * p][2] * su0) * g / (1.f + __expf(-g));
                g = acc[mi][2 * p + 1][3] * sg1; x1 = (acc[mi][2 * p][3] * su1) * g / (1.f + __expf(-g));
                *(uint32_t*)&Xb[(size_t)(r0 + 8) * 4096 + cb] = cvt2bf(x0, x1);
            }
        }
    } else if (MODE == 2) {
        const int which = ccol >> 10;        // 0=q,1=k,2=v
        const int cl = ccol & 1023;
        if (which == 2) {
            // v: stage dim-major in smem, then write transposed rows to Vt.
            __nv_bfloat16* Vt = (__nv_bfloat16*)C2;
            __nv_bfloat16* st = (__nv_bfloat16*)smc;   // 128 dims x (128+8) tokens
            const int RSV = 136;
            #pragma unroll
            for (int mi = 0; mi < 4; mi++) {
                const int rl = wm * 64 + mi * 16 + (lane >> 2);
                #pragma unroll
                for (int nj = 0; nj < 8; nj++) {
                    const int c2 = wn * 64 + nj * 8 + 2 * (lane & 3);
                    st[(c2 + 0) * RSV + rl    ] = __float2bfloat16(acc[mi][nj][0]);
                    st[(c2 + 1) * RSV + rl    ] = __float2bfloat16(acc[mi][nj][1]);
                    st[(c2 + 0) * RSV + rl + 8] = __float2bfloat16(acc[mi][nj][2]);
                    st[(c2 + 1) * RSV + rl + 8] = __float2bfloat16(acc[mi][nj][3]);
                }
            }
            __syncthreads();
            const int d = tid;  // 0..127 local dim
            #pragma unroll
            for (int t8 = 0; t8 < 16; t8++) {
                *(uint4*)&Vt[(size_t)(cl + d) * BT + crow + t8 * 8] =
                    *(uint4*)&st[d * RSV + t8 * 8];
            }
        } else {
            __nv_bfloat16* Cb = which ? (__nv_bfloat16*)C1 : (__nv_bfloat16*)C0;
            const float extra = which ? 32.f : 256.f;
            float sc0[8], sc1[8];
            #pragma unroll
            for (int nj = 0; nj < 8; nj++) {
                const int c0 = cl + wn * 64 + nj * 8 + 2 * (lane & 3);
                sc0[nj] = scl[c0] * extra;
                sc1[nj] = scl[c0 + 1] * extra;
            }
            #pragma unroll
            for (int mi = 0; mi < 4; mi++) {
                const int r0 = crow + wm * 64 + mi * 16 + (lane >> 2);
                float ss0 = 0.f, ss1 = 0.f;
                #pragma unroll
                for (int nj = 0; nj < 8; nj++) {
                    ss0 += acc[mi][nj][0] * acc[mi][nj][0] + acc[mi][nj][1] * acc[mi][nj][1];
                    ss1 += acc[mi][nj][2] * acc[mi][nj][2] + acc[mi][nj][3] * acc[mi][nj][3];
                }
                ss0 += __shfl_xor_sync(0xffffffffu, ss0, 1);
                ss0 += __shfl_xor_sync(0xffffffffu, ss0, 2);
                ss1 += __shfl_xor_sync(0xffffffffu, ss1, 1);
                ss1 += __shfl_xor_sync(0xffffffffu, ss1, 2);
                const float rn0 = rsqrtf(ss0), rn1 = rsqrtf(ss1);
                #pragma unroll
                for (int nj = 0; nj < 8; nj++) {
                    const int c0 = cl + wn * 64 + nj * 8 + 2 * (lane & 3);
                    *(uint32_t*)&Cb[(size_t)r0 * 1024 + c0] =
                        cvt2bf(acc[mi][nj][0] * rn0 * sc0[nj], acc[mi][nj][1] * rn0 * sc1[nj]);
                    *(uint32_t*)&Cb[(size_t)(r0 + 8) * 1024 + c0] =
                        cvt2bf(acc[mi][nj][2] * rn1 * sc0[nj], acc[mi][nj][3] * rn1 * sc1[nj]);
                }
            }
        }
    } else {
        __nv_bfloat16* Cb = (__nv_bfloat16*)C0;
        #pragma unroll
        for (int mi = 0; mi < 4; mi++) {
            const int r0 = crow + wm * 64 + mi * 16 + (lane >> 2);
            #pragma unroll
            for (int nj = 0; nj < 8; nj++) {
                const int c0 = ccol + wn * 64 + nj * 8 + 2 * (lane & 3);
                *(uint32_t*)&Cb[(size_t)r0 * N + c0] =
                    cvt2bf(acc[mi][nj][0], acc[mi][nj][1]);
                *(uint32_t*)&Cb[(size_t)(r0 + 8) * N + c0] =
                    cvt2bf(acc[mi][nj][2], acc[mi][nj][3]);
            }
        }
    }
}

// ---------------------------------------------------------------------------
// Tensor-core flash attention (non-causal), D=64. (R11 winner, unchanged)
// ---------------------------------------------------------------------------
#define ATT_SMEM (16384 + 3 * 32768)

__global__ void __launch_bounds__(256) attn_tc_kernel(
    const __nv_bfloat16* __restrict__ q, const __nv_bfloat16* __restrict__ k,
    const __nv_bfloat16* __restrict__ vt, __nv_bfloat16* __restrict__ y)
{
    extern __shared__ char smc[];
    const int tid = threadIdx.x, lane = tid & 31, warp = tid >> 5;
    const int bh = blockIdx.y, b = bh >> 4, cb = (bh & 15) * 64;
    const int tq0 = b * 1024 + blockIdx.x * 128;
    const uint32_t sb = (uint32_t)__cvta_generic_to_shared(smc);
    const uint32_t qs = sb;

    #pragma unroll
    for (int i = 0; i < 4; i++) {
        int idx = tid + i * 256;
        int row = idx >> 3, c = idx & 7;
        uint32_t sw = (uint32_t)(row * 128 + ((c ^ (row & 7)) << 4));
        asm volatile("cp.async.cg.shared.global [%0], [%1], 16;"
                     :: "r"(qs + sw), "l"((const void*)(q + (size_t)(tq0 + row) * CDIM + cb + c * 8)));
    }
    asm volatile("cp.async.commit_group;");

    auto issueKV = [&](int kt, int buf) {
        const int tk0 = b * 1024 + kt * 128;
        const uint32_t kb_ = sb + 16384 + buf * 32768;
        const uint32_t vb_ = kb_ + 16384;
        #pragma unroll
        for (int i = 0; i < 4; i++) {
            int idx = tid + i * 256;
            int row = idx >> 3, c = idx & 7;
            uint32_t sw = (uint32_t)(row * 128 + ((c ^ (row & 7)) << 4));
            asm volatile("cp.async.cg.shared.global [%0], [%1], 16;"
                         :: "r"(kb_ + sw), "l"((const void*)(k + (size_t)(tk0 + row) * CDIM + cb + c * 8)));
            asm volatile("cp.async.cg.shared.global [%0], [%1], 16;"
                         :: "r"(vb_ + sw),
                            "l"((const void*)(vt + (size_t)(cb + (row & 63)) * BT + tk0 + (row >> 6) * 64 + c * 8)));
        }
    };

    issueKV(0, 0); asm volatile("cp.async.commit_group;");
    issueKV(1, 1); asm volatile("cp.async.commit_group;");

    asm volatile("cp.async.wait_group 2;");
    __syncthreads();

    const int arow = warp * 16 + (lane & 15);
    const int akb  = lane >> 4;
    const int lsw  = lane & 7;
    uint32_t aq[4][4];
    #pragma unroll
    for (int ks = 0; ks < 4; ks++) {
        uint32_t ad = qs + (uint32_t)arow * 128 + (uint32_t)(((2 * ks + akb) ^ lsw) << 4);
        asm volatile("ldmatrix.sync.aligned.m8n8.x4.shared.b16 {%0,%1,%2,%3}, [%4];"
                     : "=r"(aq[ks][0]), "=r"(aq[ks][1]), "=r"(aq[ks][2]), "=r"(aq[ks][3])
                     : "r"(ad));
    }

    float acc_o[8][4];
    #pragma unroll
    for (int j = 0; j < 8; j++)
        #pragma unroll
        for (int e = 0; e < 4; e++) acc_o[j][e] = 0.f;
    float m0 = -1e30f, m1 = -1e30f, l0 = 0.f, l1 = 0.f;

    const int brow = (lane & 7) + ((lane >> 4) << 3);
    const int bkb  = (lane >> 3) & 1;

    for (int kt = 0; kt < 8; kt++) {
        asm volatile("cp.async.wait_group 1;");
        __syncthreads();

        const uint32_t kb_ = sb + 16384 + (kt % 3) * 32768;
        const uint32_t vb_ = kb_ + 16384;

        float s[16][4];
        #pragma unroll
        for (int j = 0; j < 16; j++)
            #pragma unroll
            for (int e = 0; e < 4; e++) s[j][e] = 0.f;

        #pragma unroll
        for (int ks = 0; ks < 4; ks++) {
            const int bch = 2 * ks + bkb;
            #pragma unroll
            for (int nj2 = 0; nj2 < 8; nj2++) {
                uint32_t bk[4];
                uint32_t bd = kb_ + (uint32_t)(brow + nj2 * 16) * 128 +
                              (uint32_t)((bch ^ lsw) << 4);
                asm volatile("ldmatrix.sync.aligned.m8n8.x4.shared.b16 {%0,%1,%2,%3}, [%4];"
                             : "=r"(bk[0]), "=r"(bk[1]), "=r"(bk[2]), "=r"(bk[3]) : "r"(bd));
                asm volatile(
                    "mma.sync.aligned.m16n8k16.row.col.f32.bf16.bf16.f32 "
                    "{%0,%1,%2,%3}, {%4,%5,%6,%7}, {%8,%9}, {%0,%1,%2,%3};"
                    : "+f"(s[2 * nj2][0]), "+f"(s[2 * nj2][1]), "+f"(s[2 * nj2][2]), "+f"(s[2 * nj2][3])
                    : "r"(aq[ks][0]), "r"(aq[ks][1]), "r"(aq[ks][2]), "r"(aq[ks][3]),
                      "r"(bk[0]), "r"(bk[1]));
                asm volatile(
                    "mma.sync.aligned.m16n8k16.row.col.f32.bf16.bf16.f32 "
                    "{%0,%1,%2,%3}, {%4,%5,%6,%7}, {%8,%9}, {%0,%1,%2,%3};"
                    : "+f"(s[2 * nj2 + 1][0]), "+f"(s[2 * nj2 + 1][1]), "+f"(s[2 * nj2 + 1][2]), "+f"(s[2 * nj2 + 1][3])
                    : "r"(aq[ks][0]), "r"(aq[ks][1]), "r"(aq[ks][2]), "r"(aq[ks][3]),
                      "r"(bk[2]), "r"(bk[3]));
            }
        }

        float rm0 = -1e30f, rm1 = -1e30f;
        #pragma unroll
        for (int j = 0; j < 16; j++) {
            rm0 = fmaxf(rm0, fmaxf(s[j][0], s[j][1]));
            rm1 = fmaxf(rm1, fmaxf(s[j][2], s[j][3]));
        }
        rm0 = fmaxf(rm0, __shfl_xor_sync(0xffffffffu, rm0, 1));
        rm0 = fmaxf(rm0, __shfl_xor_sync(0xffffffffu, rm0, 2));
        rm1 = fmaxf(rm1, __shfl_xor_sync(0xffffffffu, rm1, 1));
        rm1 = fmaxf(rm1, __shfl_xor_sync(0xffffffffu, rm1, 2));
        float nm0 = fmaxf(m0, rm0), nm1 = fmaxf(m1, rm1);
        float co0 = __expf(m0 - nm0), co1 = __expf(m1 - nm1);
        float ls0 = 0.f, ls1 = 0.f;
        #pragma unroll
        for (int j = 0; j < 16; j++) {
            s[j][0] = __expf(s[j][0] - nm0); ls0 += s[j][0];
            s[j][1] = __expf(s[j][1] - nm0); ls0 += s[j][1];
            s[j][2] = __expf(s[j][2] - nm1); ls1 += s[j][2];
            s[j][3] = __expf(s[j][3] - nm1); ls1 += s[j][3];
        }
        ls0 += __shfl_xor_sync(0xffffffffu, ls0, 1);
        ls0 += __shfl_xor_sync(0xffffffffu, ls0, 2);
        ls1 += __shfl_xor_sync(0xffffffffu, ls1, 1);
        ls1 += __shfl_xor_sync(0xffffffffu, ls1, 2);
        l0 = l0 * co0 + ls0; l1 = l1 * co1 + ls1;
        m0 = nm0; m1 = nm1;
        #pragma unroll
        for (int j = 0; j < 8; j++) {
            acc_o[j][0] *= co0; acc_o[j][1] *= co0;
            acc_o[j][2] *= co1; acc_o[j][3] *= co1;
        }

        #pragma unroll
        for (int kp = 0; kp < 8; kp++) {
            uint32_t ap[4];
            ap[0] = cvt2bf(s[2 * kp][0],     s[2 * kp][1]);
            ap[1] = cvt2bf(s[2 * kp][2],     s[2 * kp][3]);
            ap[2] = cvt2bf(s[2 * kp + 1][0], s[2 * kp + 1][1]);
            ap[3] = cvt2bf(s[2 * kp + 1][2], s[2 * kp + 1][3]);
            const uint32_t vbase = vb_ + (uint32_t)((kp >> 2) * 8192);
            const int ach = 2 * (kp & 3) + bkb;
            #pragma unroll
            for (int dj2 = 0; dj2 < 4; dj2++) {
                uint32_t bv[4];
                uint32_t bd = vbase + (uint32_t)(brow + dj2 * 16) * 128 +
                              (uint32_t)((ach ^ lsw) << 4);
                asm volatile("ldmatrix.sync.aligned.m8n8.x4.shared.b16 {%0,%1,%2,%3}, [%4];"
                             : "=r"(bv[0]), "=r"(bv[1]), "=r"(bv[2]), "=r"(bv[3]) : "r"(bd));
                asm volatile(
                    "mma.sync.aligned.m16n8k16.row.col.f32.bf16.bf16.f32 "
                    "{%0,%1,%2,%3}, {%4,%5,%6,%7}, {%8,%9}, {%0,%1,%2,%3};"
                    : "+f"(acc_o[2 * dj2][0]), "+f"(acc_o[2 * dj2][1]), "+f"(acc_o[2 * dj2][2]), "+f"(acc_o[2 * dj2][3])
                    : "r"(ap[0]), "r"(ap[1]), "r"(ap[2]), "r"(ap[3]), "r"(bv[0]), "r"(bv[1]));
                asm volatile(
                    "mma.sync.aligned.m16n8k16.row.col.f32.bf16.bf16.f32 "
                    "{%0,%1,%2,%3}, {%4,%5,%6,%7}, {%8,%9}, {%0,%1,%2,%3};"
                    : "+f"(acc_o[2 * dj2 + 1][0]), "+f"(acc_o[2 * dj2 + 1][1]), "+f"(acc_o[2 * dj2 + 1][2]), "+f"(acc_o[2 * dj2 + 1][3])
                    : "r"(ap[0]), "r"(ap[1]), "r"(ap[2]), "r"(ap[3]), "r"(bv[2]), "r"(bv[3]));
            }
        }

        if (kt + 2 < 8) issueKV(kt + 2, (kt + 2) % 3);
        asm volatile("cp.async.commit_group;");
    }

    const float li0 = 1.f / l0, li1 = 1.f / l1;
    const int r0 = tq0 + warp * 16 + (lane >> 2);
    #pragma unroll
    for (int dj = 0; dj < 8; dj++) {
        const int c0 = cb + dj * 8 + 2 * (lane & 3);
        *(uint32_t*)&y[(size_t)r0 * CDIM + c0] =
            cvt2bf(acc_o[dj][0] * li0, acc_o[dj][1] * li0);
        *(uint32_t*)&y[(size_t)(r0 + 8) * CDIM + c0] =
            cvt2bf(acc_o[dj][2] * li1, acc_o[dj][3] * li1);
    }
}

// ---------------------------------------------------------------------------
// out = justnorm( justnorm(h) + |alpha*1.6| * (justnorm(hb) - justnorm(h)) )
// hb is bf16 (lr-damped branch).
// ---------------------------------------------------------------------------
__global__ void residual_kernel(const float* __restrict__ hin,
                                const __nv_bfloat162* __restrict__ hb,
                                const float* __restrict__ alpha, float* __restrict__ out,
                                uint32_t* __restrict__ outb)
{
    int t = blockIdx.x, tid = threadIdx.x;
    float4 a = ((const float4*)hin)[(size_t)t * 256 + tid];
    __nv_bfloat162 b0 = hb[((size_t)t * 256 + tid) * 2];
    __nv_bfloat162 b1 = hb[((size_t)t * 256 + tid) * 2 + 1];
    float4 b = make_float4(__bfloat162float(b0.x), __bfloat162float(b0.y),
                           __bfloat162float(b1.x), __bfloat162float(b1.y));
    float s1 = a.x * a.x + a.y * a.y + a.z * a.z + a.w * a.w;
    float s2 = b.x * b.x + b.y * b.y + b.z * b.z + b.w * b.w;
    #pragma unroll
    for (int off = 16; off >= 1; off >>= 1) {
        s1 += __shfl_xor_sync(0xffffffffu, s1, off);
        s2 += __shfl_xor_sync(0xffffffffu, s2, off);
    }
    __shared__ float red1[8], red2[8];
    int w = tid >> 5, lane = tid & 31;
    if (lane == 0) { red1[w] = s1; red2[w] = s2; }
    __syncthreads();
    float t1 = 0.f, t2 = 0.f;
    #pragma unroll
    for (int i = 0; i < 8; i++) { t1 += red1[i]; t2 += red2[i]; }
    float r1 = rsqrtf(t1), r2 = rsqrtf(t2);

    float4 al = ((const float4*)alpha)[tid];
    float4 u;
    u.x = a.x * r1 + fabsf(al.x * 1.6f) * (b.x * r2 - a.x * r1);
    u.y = a.y * r1 + fabsf(al.y * 1.6f) * (b.y * r2 - a.y * r1);
    u.z = a.z * r1 + fabsf(al.z * 1.6f) * (b.z * r2 - a.z * r1);
    u.w = a.w * r1 + fabsf(al.w * 1.6f) * (b.w * r2 - a.w * r1);

    float s3 = u.x * u.x + u.y * u.y + u.z * u.z + u.w * u.w;
    #pragma unroll
    for (int off = 16; off >= 1; off >>= 1) s3 += __shfl_xor_sync(0xffffffffu, s3, off);
    __syncthreads();
    if (lane == 0) red1[w] = s3;
    __syncthreads();
    float t3 = 0.f;
    #pragma unroll
    for (int i = 0; i < 8; i++) t3 += red1[i];
    float r3 = rsqrtf(t3);
    float4 o = make_float4(u.x * r3, u.y * r3, u.z * r3, u.w * r3);
    ((float4*)out)[(size_t)t * 256 + tid] = o;
    if (outb) {
        outb[((size_t)t * 256 + tid) * 2 + 0] = cvt2bf(o.x, o.y);
        outb[((size_t)t * 256 + tid) * 2 + 1] = cvt2bf(o.z, o.w);
    }
}

// ---------------------------------------------------------------------------
extern "C" void kernel_launch(void* const* d_in, const int* in_sizes, int n_in,
                              void* d_out, int out_size)
{
    (void)in_sizes; (void)n_in; (void)out_size;
    const float* h     = (const float*)d_in[0];
    const float* Wq    = (const float*)d_in[1];
    const float* Wk    = (const float*)d_in[2];
    const float* Wv    = (const float*)d_in[3];
    const float* Wo    = (const float*)d_in[4];
    const float* Wfc   = (const float*)d_in[5];
    const float* Wproj = (const float*)d_in[6];
    const float* sqk   = (const float*)d_in[7];
    const float* suv   = (const float*)d_in[8];
    const float* a_att = (const float*)d_in[9];
    const float* a_mlp = (const float*)d_in[10];
    float* out = (float*)d_out;

    float* buf = nullptr;
    cudaGetSymbolAddress((void**)&buf, g_buf);
    float* h2  = buf + OFF_H2;
    __nv_bfloat16* t1B  = (__nv_bfloat16*)(buf + OFF_T1);
    __nv_bfloat16* hB   = (__nv_bfloat16*)(buf + OFF_HB);
    __nv_bfloat16* yB   = (__nv_bfloat16*)(buf + OFF_YB);
    __nv_bfloat16* h2B  = (__nv_bfloat16*)(buf + OFF_H2B);
    __nv_bfloat16* xB   = (__nv_bfloat16*)(buf + OFF_XB);
    __nv_bfloat16* WqB  = (__nv_bfloat16*)(buf + OFF_WQB);   // q,k,v contiguous
    __nv_bfloat16* WoB  = WqB + 3 * CDIM * CDIM;
    __nv_bfloat16* WfcP = (__nv_bfloat16*)(buf + OFF_WFCB);  // permuted
    __nv_bfloat16* WpjB = (__nv_bfloat16*)(buf + OFF_WPJB);
    __nv_bfloat16* qBf  = (__nv_bfloat16*)(buf + OFF_QBF);
    __nv_bfloat16* kBf  = (__nv_bfloat16*)(buf + OFF_KBF);
    __nv_bfloat16* VtG  = (__nv_bfloat16*)(buf + OFF_VT);

    cudaFuncSetAttribute(attn_tc_kernel, cudaFuncAttributeMaxDynamicSharedMemorySize, ATT_SMEM);
    cudaFuncSetAttribute(gemm_kernel<1>, cudaFuncAttributeMaxDynamicSharedMemorySize, GEMM_SMEM);
    cudaFuncSetAttribute(gemm_kernel<2>, cudaFuncAttributeMaxDynamicSharedMemorySize, GEMM_SMEM);
    cudaFuncSetAttribute(gemm_kernel<3>, cudaFuncAttributeMaxDynamicSharedMemorySize, GEMM_SMEM);

    // lazily-created side stream + fork/join events (host resources only;
    // identical captured work on every call)
    static cudaStream_t s2 = nullptr;
    static cudaEvent_t evF = nullptr, evH = nullptr, evJ = nullptr;
    if (!s2) {
        cudaStreamCreateWithFlags(&s2, cudaStreamNonBlocking);
        cudaEventCreateWithFlags(&evF, cudaEventDisableTiming);
        cudaEventCreateWithFlags(&evH, cudaEventDisableTiming);
        cudaEventCreateWithFlags(&evJ, cudaEventDisableTiming);
    }

    // ---- fork: h conversion + MLP weight prep overlap the weight-norm head
    //      and the attention chain ----
    cudaEventRecord(evF, 0);
    cudaStreamWaitEvent(s2, evF, 0);
    conv_kernel<<<BT * CDIM / 1024, 256, 0, s2>>>(h, (uint32_t*)hB);
    cudaEventRecord(evH, s2);                      // hB ready
    wfc_perm_kernel<<<8 * CDIM * CDIM / 1024, 256, 0, s2>>>(Wfc, (uint32_t*)WfcP);
    conv_kernel<<<4 * CDIM * CDIM / 1024, 256, 0, s2>>>(Wproj, (uint32_t*)WpjB);
    cudaEventRecord(evJ, s2);                      // WfcP + WpjB ready

    // ---- main chain ----
    // fused column-norm + bf16 conversion for Wq/Wk/Wv/Wo (one kernel)
    wnormconv_kernel<<<dim3(32, 4), 1024>>>(Wq, Wk, Wv, Wo, WqB);

    cudaStreamWaitEvent(0, evH, 0);   // need hB

    // fused qkv projection + qk per-head norm + v transpose: all bf16 outputs
    gemm_kernel<2><<<dim3(24, BT / 128), 128, GEMM_SMEM>>>(hB, WqB, qBf, kBf, VtG, sqk, BT, 3 * CDIM, CDIM);

    attn_tc_kernel<<<dim3(8, 128), 256, ATT_SMEM>>>(qBf, kBf, VtG, yB);

    // o projection -> bf16 t1B
    gemm_kernel<1><<<dim3(8, BT / 128), 128, GEMM_SMEM>>>(yB, WoB, t1B, nullptr, nullptr, nullptr, BT, CDIM, CDIM);

    residual_kernel<<<BT, 256>>>(h, (const __nv_bfloat162*)t1B, a_att, h2, (uint32_t*)h2B);

    // join before fc (needs WfcP; proj needs WpjB)
    cudaStreamWaitEvent(0, evJ, 0);

    // MLP: fc + SwiGLU fused -> x bf16; proj -> bf16 t1B
    gemm_kernel<3><<<dim3(64, BT / 128), 128, GEMM_SMEM>>>(h2B, WfcP, xB, nullptr, nullptr, suv, BT, 8 * CDIM, CDIM);
    gemm_kernel<1><<<dim3(8, BT / 128), 128, GEMM_SMEM>>>(xB, WpjB, t1B, nullptr, nullptr, nullptr, BT, CDIM, 4 * CDIM);

    residual_kernel<<<BT, 256>>>(h2, (const __nv_bfloat162*)t1B, a_mlp, out, nullptr);
}